// round 1
// baseline (speedup 1.0000x reference)
#include <cuda_runtime.h>
#include <cuda_bf16.h>
#include <math.h>

// Problem constants
#define BATCH 2
#define SEQ   2048
#define DMODEL 512
#define NHEAD 8
#define DHEAD 64
#define NTOK  (BATCH*SEQ)          // 4096
#define NQK   1024                 // 2*DMODEL for q|k
#define NFEAT 1536                 // 1024 qk + 512 v
#define CHUNK 128
#define NCHUNK (SEQ/CHUNK)         // 16
#define BHEADS (BATCH*NHEAD)       // 16

// Scratch (device globals; no allocation allowed)
__device__ float g_q[BHEADS*SEQ*DHEAD];     // (b,h,s,d)
__device__ float g_k[BHEADS*SEQ*DHEAD];
__device__ float g_v[BHEADS*SEQ*DHEAD];
__device__ float g_ctx[NTOK*DMODEL];        // (b,s, h*64+d)
__device__ float g_kv_loc[BHEADS*NCHUNK*DHEAD*DHEAD];
__device__ float g_kv_pre[BHEADS*NCHUNK*DHEAD*DHEAD];
__device__ float g_z_loc[BHEADS*NCHUNK*DHEAD];
__device__ float g_z_pre[BHEADS*NCHUNK*DHEAD];

// ---------------------------------------------------------------------------
// Kernel 1: fused QKV GEMM  Y[m,n] = x[m,:] . W[n,:] + b[n], n in [0,1536)
//   n <  512 : q features  -> elu+1 -> g_q
//   n < 1024 : k features  -> elu+1 -> g_k
//   else     : v features  ->          g_v
// 128x128x16 tiling, 256 threads, 8x8 per thread.
// ---------------------------------------------------------------------------
#define BM 128
#define BN 128
#define BKK 16

__global__ __launch_bounds__(256) void qkv_gemm_kernel(
    const float* __restrict__ x,
    const float* __restrict__ Wqk, const float* __restrict__ bqk,
    const float* __restrict__ Wv,  const float* __restrict__ bv)
{
    __shared__ float As[BKK][BM+4];
    __shared__ float Bs[BKK][BN+4];
    const int n0 = blockIdx.x * BN;
    const int m0 = blockIdx.y * BM;
    const int tid = threadIdx.x;
    const int tx = tid & 15;
    const int ty = tid >> 4;
    const int lr = tid >> 2;           // 0..63
    const int lc = (tid & 3) * 4;      // k-offset within tile

    float acc[8][8];
#pragma unroll
    for (int i = 0; i < 8; i++)
#pragma unroll
        for (int j = 0; j < 8; j++) acc[i][j] = 0.f;

    for (int k0 = 0; k0 < DMODEL; k0 += BKK) {
#pragma unroll
        for (int half = 0; half < 2; half++) {
            int m = m0 + lr + half*64;
            float4 a = *(const float4*)(x + (size_t)m*DMODEL + k0 + lc);
            As[lc+0][lr+half*64] = a.x;
            As[lc+1][lr+half*64] = a.y;
            As[lc+2][lr+half*64] = a.z;
            As[lc+3][lr+half*64] = a.w;
        }
#pragma unroll
        for (int half = 0; half < 2; half++) {
            int n = n0 + lr + half*64;
            const float* wrow = (n < NQK) ? (Wqk + (size_t)n*DMODEL)
                                          : (Wv + (size_t)(n-NQK)*DMODEL);
            float4 b = *(const float4*)(wrow + k0 + lc);
            Bs[lc+0][lr+half*64] = b.x;
            Bs[lc+1][lr+half*64] = b.y;
            Bs[lc+2][lr+half*64] = b.z;
            Bs[lc+3][lr+half*64] = b.w;
        }
        __syncthreads();
#pragma unroll
        for (int kk = 0; kk < BKK; kk++) {
            float a[8], b[8];
#pragma unroll
            for (int i = 0; i < 8; i++) a[i] = As[kk][ty*8+i];
#pragma unroll
            for (int j = 0; j < 8; j++) b[j] = Bs[kk][tx*8+j];
#pragma unroll
            for (int i = 0; i < 8; i++)
#pragma unroll
                for (int j = 0; j < 8; j++) acc[i][j] += a[i]*b[j];
        }
        __syncthreads();
    }

    // Epilogue: bias, elu+1 for qk, scatter to head-major layouts.
    const int n_base = n0 + tx*8;      // multiple of 8; 8 cols stay in one head
#pragma unroll
    for (int i = 0; i < 8; i++) {
        int m = m0 + ty*8 + i;
        int bb = m / SEQ;
        int ss = m % SEQ;
        float vals[8];
#pragma unroll
        for (int j = 0; j < 8; j++) {
            int n = n_base + j;
            float val = acc[i][j] + ((n < NQK) ? bqk[n] : bv[n-NQK]);
            if (n < NQK) val = (val > 0.f) ? (val + 1.f) : expf(val);
            vals[j] = val;
        }
        float* dst;
        if (n_base < DMODEL) {
            int h = n_base / DHEAD, d = n_base % DHEAD;
            dst = g_q + (((size_t)(bb*NHEAD + h))*SEQ + ss)*DHEAD + d;
        } else if (n_base < NQK) {
            int nn = n_base - DMODEL;
            int h = nn / DHEAD, d = nn % DHEAD;
            dst = g_k + (((size_t)(bb*NHEAD + h))*SEQ + ss)*DHEAD + d;
        } else {
            int nn = n_base - NQK;
            int h = nn / DHEAD, d = nn % DHEAD;
            dst = g_v + (((size_t)(bb*NHEAD + h))*SEQ + ss)*DHEAD + d;
        }
        *(float4*)dst       = make_float4(vals[0], vals[1], vals[2], vals[3]);
        *(float4*)(dst + 4) = make_float4(vals[4], vals[5], vals[6], vals[7]);
    }
}

// ---------------------------------------------------------------------------
// Kernel 2: per-chunk local state  KV[dk][dv] = sum_s k[s][dk]*v[s][dv],
//           z[dk] = sum_s k[s][dk].  grid = BHEADS*NCHUNK, 256 threads.
// ---------------------------------------------------------------------------
__global__ __launch_bounds__(256) void chunk_local_kernel()
{
    const int blk = blockIdx.x;
    const int bh = blk / NCHUNK;
    const int c  = blk % NCHUNK;
    const float* kp = g_k + ((size_t)bh*SEQ + c*CHUNK)*DHEAD;
    const float* vp = g_v + ((size_t)bh*SEQ + c*CHUNK)*DHEAD;
    __shared__ float sk[DHEAD];
    __shared__ float sv[DHEAD];
    const int tid = threadIdx.x;
    const int dk0 = tid >> 2;
    const int dv0 = (tid & 3) * 16;

    float acc[16];
#pragma unroll
    for (int i = 0; i < 16; i++) acc[i] = 0.f;
    float zacc = 0.f;

    for (int s = 0; s < CHUNK; s++) {
        if (tid < 64) sk[tid] = kp[s*DHEAD + tid];
        else if (tid < 128) sv[tid-64] = vp[s*DHEAD + tid - 64];
        __syncthreads();
        float kv = sk[dk0];
#pragma unroll
        for (int i = 0; i < 16; i++) acc[i] += kv * sv[dv0 + i];
        if ((tid & 3) == 0) zacc += kv;
        __syncthreads();
    }
    float* kvout = g_kv_loc + (size_t)blk * (DHEAD*DHEAD);
#pragma unroll
    for (int i = 0; i < 16; i++) kvout[dk0*DHEAD + dv0 + i] = acc[i];
    if ((tid & 3) == 0) g_z_loc[(size_t)blk*DHEAD + dk0] = zacc;
}

// ---------------------------------------------------------------------------
// Kernel 3: exclusive prefix scan of chunk states along chunks. grid=BHEADS.
// ---------------------------------------------------------------------------
__global__ __launch_bounds__(256) void scan_kernel()
{
    const int bh = blockIdx.x;
    for (int e = threadIdx.x; e < DHEAD*DHEAD; e += blockDim.x) {
        float run = 0.f;
        for (int c = 0; c < NCHUNK; c++) {
            size_t idx = ((size_t)(bh*NCHUNK + c))*(DHEAD*DHEAD) + e;
            g_kv_pre[idx] = run;
            run += g_kv_loc[idx];
        }
    }
    if (threadIdx.x < DHEAD) {
        float run = 0.f;
        for (int c = 0; c < NCHUNK; c++) {
            size_t idx = ((size_t)(bh*NCHUNK + c))*DHEAD + threadIdx.x;
            g_z_pre[idx] = run;
            run += g_z_loc[idx];
        }
    }
}

// ---------------------------------------------------------------------------
// Kernel 4: per-chunk readout. 128 threads, one token per thread.
//   ctx_t = q_t @ KV_pre + sum_{s<=t in chunk}(q_t.k_s) v_s
//   nu_t  = q_t . z_pre  + sum_{s<=t in chunk}(q_t.k_s)
// Dynamic smem: sk[128*64] + sv[128*64] + sq[128*65] + skv[64*64] + sz[64]
// ---------------------------------------------------------------------------
#define SMEM4_FLOATS (CHUNK*DHEAD + CHUNK*DHEAD + CHUNK*(DHEAD+1) + DHEAD*DHEAD + DHEAD)
#define SMEM4_BYTES (SMEM4_FLOATS*4)

__global__ __launch_bounds__(128) void chunk_out_kernel()
{
    extern __shared__ float sm[];
    float* sk  = sm;
    float* sv  = sk + CHUNK*DHEAD;
    float* sq  = sv + CHUNK*DHEAD;          // padded rows of 65
    float* skv = sq + CHUNK*(DHEAD+1);
    float* sz  = skv + DHEAD*DHEAD;

    const int blk = blockIdx.x;
    const int bh = blk / NCHUNK;
    const int c  = blk % NCHUNK;
    const int t  = threadIdx.x;             // token within chunk

    const size_t base = ((size_t)bh*SEQ + (size_t)c*CHUNK)*DHEAD;
    const float4* k4 = (const float4*)(g_k + base);
    const float4* v4 = (const float4*)(g_v + base);
    const float4* q4 = (const float4*)(g_q + base);

    // cooperative loads
    for (int i = t; i < CHUNK*DHEAD/4; i += 128) {
        ((float4*)sk)[i] = k4[i];
        ((float4*)sv)[i] = v4[i];
        float4 qv = q4[i];
        int row = i >> 4;                   // 16 float4 per row
        int col = (i & 15) * 4;
        float* d = sq + row*(DHEAD+1) + col;
        d[0]=qv.x; d[1]=qv.y; d[2]=qv.z; d[3]=qv.w;
    }
    const float4* kv4 = (const float4*)(g_kv_pre + (size_t)blk*(DHEAD*DHEAD));
    for (int i = t; i < DHEAD*DHEAD/4; i += 128) ((float4*)skv)[i] = kv4[i];
    if (t < DHEAD) sz[t] = g_z_pre[(size_t)blk*DHEAD + t];
    __syncthreads();

    // q row in registers (static indices -> stays in RF)
    float qreg[DHEAD];
#pragma unroll
    for (int i = 0; i < DHEAD; i++) qreg[i] = sq[t*(DHEAD+1) + i];

    float ctx[DHEAD];
#pragma unroll
    for (int i = 0; i < DHEAD; i++) ctx[i] = 0.f;
    float nu = 0.f;

    // inter-chunk prefix state (rolled outer loop; inner unrolled via float4)
    for (int dk = 0; dk < DHEAD; dk++) {
        float qv = sq[t*(DHEAD+1) + dk];
        nu += qv * sz[dk];
        const float4* kvr = (const float4*)(skv + dk*DHEAD);
#pragma unroll
        for (int i = 0; i < DHEAD/4; i++) {
            float4 w = kvr[i];
            ctx[i*4+0] += qv*w.x;
            ctx[i*4+1] += qv*w.y;
            ctx[i*4+2] += qv*w.z;
            ctx[i*4+3] += qv*w.w;
        }
    }

    // intra-chunk causal part
    for (int s = 0; s <= t; s++) {
        const float4* skr = (const float4*)(sk + s*DHEAD);
        float score = 0.f;
#pragma unroll
        for (int i = 0; i < DHEAD/4; i++) {
            float4 kk = skr[i];
            score += qreg[i*4+0]*kk.x + qreg[i*4+1]*kk.y
                   + qreg[i*4+2]*kk.z + qreg[i*4+3]*kk.w;
        }
        nu += score;
        const float4* svr = (const float4*)(sv + s*DHEAD);
#pragma unroll
        for (int i = 0; i < DHEAD/4; i++) {
            float4 vv = svr[i];
            ctx[i*4+0] += score*vv.x;
            ctx[i*4+1] += score*vv.y;
            ctx[i*4+2] += score*vv.z;
            ctx[i*4+3] += score*vv.w;
        }
    }

    const float inv = 1.f / nu;
    const int b = bh / NHEAD, h = bh % NHEAD;
    const int s_glob = c*CHUNK + t;
    float* outp = g_ctx + ((size_t)(b*SEQ + s_glob))*DMODEL + h*DHEAD;
#pragma unroll
    for (int i = 0; i < DHEAD; i += 4) {
        *(float4*)(outp + i) = make_float4(ctx[i]*inv, ctx[i+1]*inv,
                                           ctx[i+2]*inv, ctx[i+3]*inv);
    }
}

// ---------------------------------------------------------------------------
// Kernel 5: output projection  out = ctx @ Wo^T + bo   (4096 x 512 x 512)
// ---------------------------------------------------------------------------
__global__ __launch_bounds__(256) void out_gemm_kernel(
    const float* __restrict__ Wo, const float* __restrict__ bo,
    float* __restrict__ out)
{
    __shared__ float As[BKK][BM+4];
    __shared__ float Bs[BKK][BN+4];
    const int n0 = blockIdx.x * BN;
    const int m0 = blockIdx.y * BM;
    const int tid = threadIdx.x;
    const int tx = tid & 15;
    const int ty = tid >> 4;
    const int lr = tid >> 2;
    const int lc = (tid & 3) * 4;

    float acc[8][8];
#pragma unroll
    for (int i = 0; i < 8; i++)
#pragma unroll
        for (int j = 0; j < 8; j++) acc[i][j] = 0.f;

    for (int k0 = 0; k0 < DMODEL; k0 += BKK) {
#pragma unroll
        for (int half = 0; half < 2; half++) {
            int m = m0 + lr + half*64;
            float4 a = *(const float4*)(g_ctx + (size_t)m*DMODEL + k0 + lc);
            As[lc+0][lr+half*64] = a.x;
            As[lc+1][lr+half*64] = a.y;
            As[lc+2][lr+half*64] = a.z;
            As[lc+3][lr+half*64] = a.w;
        }
#pragma unroll
        for (int half = 0; half < 2; half++) {
            int n = n0 + lr + half*64;
            float4 b = *(const float4*)(Wo + (size_t)n*DMODEL + k0 + lc);
            Bs[lc+0][lr+half*64] = b.x;
            Bs[lc+1][lr+half*64] = b.y;
            Bs[lc+2][lr+half*64] = b.z;
            Bs[lc+3][lr+half*64] = b.w;
        }
        __syncthreads();
#pragma unroll
        for (int kk = 0; kk < BKK; kk++) {
            float a[8], b[8];
#pragma unroll
            for (int i = 0; i < 8; i++) a[i] = As[kk][ty*8+i];
#pragma unroll
            for (int j = 0; j < 8; j++) b[j] = Bs[kk][tx*8+j];
#pragma unroll
            for (int i = 0; i < 8; i++)
#pragma unroll
                for (int j = 0; j < 8; j++) acc[i][j] += a[i]*b[j];
        }
        __syncthreads();
    }

    const int n_base = n0 + tx*8;
#pragma unroll
    for (int i = 0; i < 8; i++) {
        int m = m0 + ty*8 + i;
        float vals[8];
#pragma unroll
        for (int j = 0; j < 8; j++) vals[j] = acc[i][j] + bo[n_base + j];
        float* dst = out + (size_t)m*DMODEL + n_base;
        *(float4*)dst       = make_float4(vals[0], vals[1], vals[2], vals[3]);
        *(float4*)(dst + 4) = make_float4(vals[4], vals[5], vals[6], vals[7]);
    }
}

// ---------------------------------------------------------------------------
extern "C" void kernel_launch(void* const* d_in, const int* in_sizes, int n_in,
                              void* d_out, int out_size)
{
    const float* x     = (const float*)d_in[0];
    const float* Wqk_w = (const float*)d_in[1];
    const float* Wqk_b = (const float*)d_in[2];
    const float* Wv_w  = (const float*)d_in[3];
    const float* Wv_b  = (const float*)d_in[4];
    const float* Wo_w  = (const float*)d_in[5];
    const float* Wo_b  = (const float*)d_in[6];
    float* out = (float*)d_out;

    cudaFuncSetAttribute(chunk_out_kernel,
                         cudaFuncAttributeMaxDynamicSharedMemorySize,
                         SMEM4_BYTES);

    dim3 g1(NFEAT/BN, NTOK/BM);
    qkv_gemm_kernel<<<g1, 256>>>(x, Wqk_w, Wqk_b, Wv_w, Wv_b);

    chunk_local_kernel<<<BHEADS*NCHUNK, 256>>>();
    scan_kernel<<<BHEADS, 256>>>();
    chunk_out_kernel<<<BHEADS*NCHUNK, 128, SMEM4_BYTES>>>();

    dim3 g5(DMODEL/BN, NTOK/BM);
    out_gemm_kernel<<<g5, 256>>>(Wo_w, Wo_b, out);
}

// round 2
// speedup vs baseline: 1.8955x; 1.8955x over previous
#include <cuda_runtime.h>
#include <cuda_bf16.h>
#include <math.h>
#include <stdint.h>

// Problem constants
#define BATCH 2
#define SEQ   2048
#define DMODEL 512
#define NHEAD 8
#define DHEAD 64
#define NTOK  (BATCH*SEQ)          // 4096
#define NQK   1024                 // 2*DMODEL for q|k
#define NFEAT 1536                 // 1024 qk + 512 v
#define CHUNK 128
#define NCHUNK (SEQ/CHUNK)         // 16
#define BHEADS (BATCH*NHEAD)       // 16

// Scratch (device globals; no allocation allowed)
__device__ float g_q[BHEADS*SEQ*DHEAD];     // (b,h,s,d)
__device__ float g_k[BHEADS*SEQ*DHEAD];
__device__ float g_v[BHEADS*SEQ*DHEAD];
__device__ float g_ctx[NTOK*DMODEL];        // (b,s, h*64+d)
__device__ float g_kv_loc[BHEADS*NCHUNK*DHEAD*DHEAD];
__device__ float g_kv_pre[BHEADS*NCHUNK*DHEAD*DHEAD];
__device__ float g_z_loc[BHEADS*NCHUNK*DHEAD];
__device__ float g_z_pre[BHEADS*NCHUNK*DHEAD];

// ---------------------------------------------------------------------------
// Helpers: cp.async, tf32 cvt, mma
// ---------------------------------------------------------------------------
__device__ __forceinline__ uint32_t smem_u32(const void* p) {
    return (uint32_t)__cvta_generic_to_shared(p);
}
__device__ __forceinline__ void cp_async16(uint32_t s, const void* g) {
    asm volatile("cp.async.cg.shared.global [%0], [%1], 16;\n" :: "r"(s), "l"(g));
}
__device__ __forceinline__ void cp_commit() {
    asm volatile("cp.async.commit_group;\n");
}
__device__ __forceinline__ void cp_wait1() {
    asm volatile("cp.async.wait_group 1;\n");
}
__device__ __forceinline__ void cp_wait0() {
    asm volatile("cp.async.wait_group 0;\n");
}
__device__ __forceinline__ uint32_t f2tf(float f) {
    uint32_t r;
    asm("cvt.rna.tf32.f32 %0, %1;" : "=r"(r) : "f"(f));
    return r;
}
__device__ __forceinline__ void mma_tf32(float c[4],
    uint32_t a0, uint32_t a1, uint32_t a2, uint32_t a3,
    uint32_t b0, uint32_t b1)
{
    asm volatile(
        "mma.sync.aligned.m16n8k8.row.col.f32.tf32.tf32.f32 "
        "{%0,%1,%2,%3}, {%4,%5,%6,%7}, {%8,%9}, {%0,%1,%2,%3};"
        : "+f"(c[0]), "+f"(c[1]), "+f"(c[2]), "+f"(c[3])
        : "r"(a0), "r"(a1), "r"(a2), "r"(a3), "r"(b0), "r"(b1));
}

// ---------------------------------------------------------------------------
// TF32 tensor-core GEMM config: 128x128x32 tiles, 8 warps of 64x32.
// Smem layout: As[stage][m][k] and Bs[stage][n][k], k-stride 36 (skew 4
// floats => fragment reads addr%32 = 4*row + k : conflict-free).
// ---------------------------------------------------------------------------
#define KT 32
#define NKT (DMODEL/KT)            // 16
#define ASTR 36
#define TILE_FLOATS (128*ASTR)     // 4608
#define GEMM_SMEM_BYTES (2*2*TILE_FLOATS*4)   // 73728

struct Frags {
    float c[4][4][4];
};

// compute one k-tile (32) from staged smem
__device__ __forceinline__ void gemm_compute_tile(
    const float* __restrict__ A, const float* __restrict__ B,
    int warp_m, int warp_n, int lane, float c[4][4][4])
{
    const int lq = lane >> 2;   // 0..7
    const int lr = lane & 3;    // 0..3
#pragma unroll
    for (int kk = 0; kk < KT; kk += 8) {
        uint32_t af[4][4];
        uint32_t bf[4][2];
#pragma unroll
        for (int mt = 0; mt < 4; mt++) {
            int r = warp_m + mt*16 + lq;
            af[mt][0] = f2tf(A[r*ASTR + kk + lr]);
            af[mt][1] = f2tf(A[(r+8)*ASTR + kk + lr]);
            af[mt][2] = f2tf(A[r*ASTR + kk + 4 + lr]);
            af[mt][3] = f2tf(A[(r+8)*ASTR + kk + 4 + lr]);
        }
#pragma unroll
        for (int nt = 0; nt < 4; nt++) {
            int n = warp_n + nt*8 + lq;
            bf[nt][0] = f2tf(B[n*ASTR + kk + lr]);
            bf[nt][1] = f2tf(B[n*ASTR + kk + 4 + lr]);
        }
#pragma unroll
        for (int mt = 0; mt < 4; mt++)
#pragma unroll
            for (int nt = 0; nt < 4; nt++)
                mma_tf32(c[mt][nt], af[mt][0], af[mt][1], af[mt][2], af[mt][3],
                         bf[nt][0], bf[nt][1]);
    }
}

// ---------------------------------------------------------------------------
// Kernel 1: fused QKV GEMM (tensor cores), Y = x @ W^T + b, epilogue scatter.
// ---------------------------------------------------------------------------
__global__ __launch_bounds__(256) void qkv_tc_gemm(
    const float* __restrict__ x,
    const float* __restrict__ Wqk, const float* __restrict__ bqk,
    const float* __restrict__ Wv,  const float* __restrict__ bv)
{
    extern __shared__ float smem[];
    float* As = smem;                       // [2][128][ASTR]
    float* Bs = smem + 2*TILE_FLOATS;       // [2][128][ASTR]

    const int n0 = blockIdx.x * 128;
    const int m0 = blockIdx.y * 128;
    const int tid = threadIdx.x;
    const int wid = tid >> 5;
    const int lane = tid & 31;
    const int warp_m = (wid & 1) * 64;
    const int warp_n = (wid >> 1) * 32;

    float c[4][4][4];
#pragma unroll
    for (int mt = 0; mt < 4; mt++)
#pragma unroll
        for (int nt = 0; nt < 4; nt++)
#pragma unroll
            for (int i = 0; i < 4; i++) c[mt][nt][i] = 0.f;

    // async tile loader: 1024 float4 per tile, 4 per thread
    auto load_stage = [&](int kt, int stage) {
        const int k0 = kt * KT;
        float* Ad = As + stage * TILE_FLOATS;
        float* Bd = Bs + stage * TILE_FLOATS;
#pragma unroll
        for (int i = 0; i < 4; i++) {
            int idx = tid + i*256;
            int row = idx >> 3;
            int kq  = (idx & 7) * 4;
            cp_async16(smem_u32(Ad + row*ASTR + kq),
                       x + (size_t)(m0 + row)*DMODEL + k0 + kq);
            int n = n0 + row;
            const float* wrow = (n < NQK) ? (Wqk + (size_t)n*DMODEL)
                                          : (Wv + (size_t)(n-NQK)*DMODEL);
            cp_async16(smem_u32(Bd + row*ASTR + kq), wrow + k0 + kq);
        }
        cp_commit();
    };

    load_stage(0, 0);
    load_stage(1, 1);
    for (int kt = 0; kt < NKT; kt++) {
        if (kt < NKT - 1) cp_wait1(); else cp_wait0();
        __syncthreads();
        gemm_compute_tile(As + (kt&1)*TILE_FLOATS, Bs + (kt&1)*TILE_FLOATS,
                          warp_m, warp_n, lane, c);
        __syncthreads();
        if (kt + 2 < NKT) load_stage(kt + 2, kt & 1);
    }

    // Epilogue: bias, elu+1 for qk, scatter to (b,h,s,d)
    const int lq = lane >> 2;
    const int lc = (lane & 3) * 2;
#pragma unroll
    for (int mt = 0; mt < 4; mt++) {
#pragma unroll
        for (int rv = 0; rv < 2; rv++) {
            int m = m0 + warp_m + mt*16 + lq + rv*8;
            int bb = m / SEQ;
            int ss = m % SEQ;
#pragma unroll
            for (int nt = 0; nt < 4; nt++) {
                int nf = n0 + warp_n + nt*8 + lc;
                float v0 = c[mt][nt][rv*2+0];
                float v1 = c[mt][nt][rv*2+1];
                if (nf < NQK) {
                    v0 += bqk[nf];   v1 += bqk[nf+1];
                    v0 = (v0 > 0.f) ? (v0 + 1.f) : expf(v0);
                    v1 = (v1 > 0.f) ? (v1 + 1.f) : expf(v1);
                } else {
                    v0 += bv[nf-NQK]; v1 += bv[nf-NQK+1];
                }
                float* dst;
                if (nf < DMODEL) {
                    int h = nf / DHEAD, d = nf % DHEAD;
                    dst = g_q + (((size_t)(bb*NHEAD + h))*SEQ + ss)*DHEAD + d;
                } else if (nf < NQK) {
                    int nn = nf - DMODEL;
                    int h = nn / DHEAD, d = nn % DHEAD;
                    dst = g_k + (((size_t)(bb*NHEAD + h))*SEQ + ss)*DHEAD + d;
                } else {
                    int nn = nf - NQK;
                    int h = nn / DHEAD, d = nn % DHEAD;
                    dst = g_v + (((size_t)(bb*NHEAD + h))*SEQ + ss)*DHEAD + d;
                }
                *(float2*)dst = make_float2(v0, v1);
            }
        }
    }
}

// ---------------------------------------------------------------------------
// Kernel 2: per-chunk local state, staged smem, 2 barriers total.
// ---------------------------------------------------------------------------
__global__ __launch_bounds__(256) void chunk_local_kernel()
{
    __shared__ float sk[64][DHEAD];
    __shared__ float sv[64][DHEAD];
    const int blk = blockIdx.x;
    const int bh = blk / NCHUNK;
    const int c  = blk % NCHUNK;
    const float* kp = g_k + ((size_t)bh*SEQ + c*CHUNK)*DHEAD;
    const float* vp = g_v + ((size_t)bh*SEQ + c*CHUNK)*DHEAD;
    const int tid = threadIdx.x;
    const int dk0 = tid >> 2;
    const int dv0 = (tid & 3) * 16;

    float acc[16];
#pragma unroll
    for (int i = 0; i < 16; i++) acc[i] = 0.f;
    float zacc = 0.f;

    for (int half = 0; half < 2; half++) {
        const float4* k4 = (const float4*)(kp + half*64*DHEAD);
        const float4* v4 = (const float4*)(vp + half*64*DHEAD);
        __syncthreads();
        for (int i = tid; i < 64*DHEAD/4; i += 256) {
            ((float4*)sk)[i] = k4[i];
            ((float4*)sv)[i] = v4[i];
        }
        __syncthreads();
        for (int s = 0; s < 64; s++) {
            float kv = sk[s][dk0];
            zacc += kv;
            const float4* svr = (const float4*)(&sv[s][dv0]);
#pragma unroll
            for (int j = 0; j < 4; j++) {
                float4 vv = svr[j];
                acc[j*4+0] += kv*vv.x;
                acc[j*4+1] += kv*vv.y;
                acc[j*4+2] += kv*vv.z;
                acc[j*4+3] += kv*vv.w;
            }
        }
    }
    float* kvout = g_kv_loc + (size_t)blk * (DHEAD*DHEAD);
#pragma unroll
    for (int j = 0; j < 4; j++)
        *(float4*)(kvout + dk0*DHEAD + dv0 + j*4) =
            make_float4(acc[j*4], acc[j*4+1], acc[j*4+2], acc[j*4+3]);
    if ((tid & 3) == 0) g_z_loc[(size_t)blk*DHEAD + dk0] = zacc;
}

// ---------------------------------------------------------------------------
// Kernel 3: exclusive prefix scan of chunk states along chunks. grid=BHEADS.
// ---------------------------------------------------------------------------
__global__ __launch_bounds__(256) void scan_kernel()
{
    const int bh = blockIdx.x;
    for (int e = threadIdx.x; e < DHEAD*DHEAD; e += blockDim.x) {
        float run = 0.f;
        for (int c = 0; c < NCHUNK; c++) {
            size_t idx = ((size_t)(bh*NCHUNK + c))*(DHEAD*DHEAD) + e;
            g_kv_pre[idx] = run;
            run += g_kv_loc[idx];
        }
    }
    if (threadIdx.x < DHEAD) {
        float run = 0.f;
        for (int c = 0; c < NCHUNK; c++) {
            size_t idx = ((size_t)(bh*NCHUNK + c))*DHEAD + threadIdx.x;
            g_z_pre[idx] = run;
            run += g_z_loc[idx];
        }
    }
}

// ---------------------------------------------------------------------------
// Kernel 4: per-chunk readout (unchanged this round).
// ---------------------------------------------------------------------------
#define SMEM4_FLOATS (CHUNK*DHEAD + CHUNK*DHEAD + CHUNK*(DHEAD+1) + DHEAD*DHEAD + DHEAD)
#define SMEM4_BYTES (SMEM4_FLOATS*4)

__global__ __launch_bounds__(128) void chunk_out_kernel()
{
    extern __shared__ float sm[];
    float* sk  = sm;
    float* sv  = sk + CHUNK*DHEAD;
    float* sq  = sv + CHUNK*DHEAD;          // padded rows of 65
    float* skv = sq + CHUNK*(DHEAD+1);
    float* sz  = skv + DHEAD*DHEAD;

    const int blk = blockIdx.x;
    const int bh = blk / NCHUNK;
    const int c  = blk % NCHUNK;
    const int t  = threadIdx.x;             // token within chunk

    const size_t base = ((size_t)bh*SEQ + (size_t)c*CHUNK)*DHEAD;
    const float4* k4 = (const float4*)(g_k + base);
    const float4* v4 = (const float4*)(g_v + base);
    const float4* q4 = (const float4*)(g_q + base);

    for (int i = t; i < CHUNK*DHEAD/4; i += 128) {
        ((float4*)sk)[i] = k4[i];
        ((float4*)sv)[i] = v4[i];
        float4 qv = q4[i];
        int row = i >> 4;
        int col = (i & 15) * 4;
        float* d = sq + row*(DHEAD+1) + col;
        d[0]=qv.x; d[1]=qv.y; d[2]=qv.z; d[3]=qv.w;
    }
    const float4* kv4 = (const float4*)(g_kv_pre + (size_t)blk*(DHEAD*DHEAD));
    for (int i = t; i < DHEAD*DHEAD/4; i += 128) ((float4*)skv)[i] = kv4[i];
    if (t < DHEAD) sz[t] = g_z_pre[(size_t)blk*DHEAD + t];
    __syncthreads();

    float qreg[DHEAD];
#pragma unroll
    for (int i = 0; i < DHEAD; i++) qreg[i] = sq[t*(DHEAD+1) + i];

    float ctx[DHEAD];
#pragma unroll
    for (int i = 0; i < DHEAD; i++) ctx[i] = 0.f;
    float nu = 0.f;

    for (int dk = 0; dk < DHEAD; dk++) {
        float qv = sq[t*(DHEAD+1) + dk];
        nu += qv * sz[dk];
        const float4* kvr = (const float4*)(skv + dk*DHEAD);
#pragma unroll
        for (int i = 0; i < DHEAD/4; i++) {
            float4 w = kvr[i];
            ctx[i*4+0] += qv*w.x;
            ctx[i*4+1] += qv*w.y;
            ctx[i*4+2] += qv*w.z;
            ctx[i*4+3] += qv*w.w;
        }
    }

    for (int s = 0; s <= t; s++) {
        const float4* skr = (const float4*)(sk + s*DHEAD);
        float score = 0.f;
#pragma unroll
        for (int i = 0; i < DHEAD/4; i++) {
            float4 kk = skr[i];
            score += qreg[i*4+0]*kk.x + qreg[i*4+1]*kk.y
                   + qreg[i*4+2]*kk.z + qreg[i*4+3]*kk.w;
        }
        nu += score;
        const float4* svr = (const float4*)(sv + s*DHEAD);
#pragma unroll
        for (int i = 0; i < DHEAD/4; i++) {
            float4 vv = svr[i];
            ctx[i*4+0] += score*vv.x;
            ctx[i*4+1] += score*vv.y;
            ctx[i*4+2] += score*vv.z;
            ctx[i*4+3] += score*vv.w;
        }
    }

    const float inv = 1.f / nu;
    const int b = bh / NHEAD, h = bh % NHEAD;
    const int s_glob = c*CHUNK + t;
    float* outp = g_ctx + ((size_t)(b*SEQ + s_glob))*DMODEL + h*DHEAD;
#pragma unroll
    for (int i = 0; i < DHEAD; i += 4) {
        *(float4*)(outp + i) = make_float4(ctx[i]*inv, ctx[i+1]*inv,
                                           ctx[i+2]*inv, ctx[i+3]*inv);
    }
}

// ---------------------------------------------------------------------------
// Kernel 5: output projection (tensor cores), out = ctx @ Wo^T + bo.
// ---------------------------------------------------------------------------
__global__ __launch_bounds__(256) void out_tc_gemm(
    const float* __restrict__ Wo, const float* __restrict__ bo,
    float* __restrict__ out)
{
    extern __shared__ float smem[];
    float* As = smem;
    float* Bs = smem + 2*TILE_FLOATS;

    const int n0 = blockIdx.x * 128;
    const int m0 = blockIdx.y * 128;
    const int tid = threadIdx.x;
    const int wid = tid >> 5;
    const int lane = tid & 31;
    const int warp_m = (wid & 1) * 64;
    const int warp_n = (wid >> 1) * 32;

    float c[4][4][4];
#pragma unroll
    for (int mt = 0; mt < 4; mt++)
#pragma unroll
        for (int nt = 0; nt < 4; nt++)
#pragma unroll
            for (int i = 0; i < 4; i++) c[mt][nt][i] = 0.f;

    auto load_stage = [&](int kt, int stage) {
        const int k0 = kt * KT;
        float* Ad = As + stage * TILE_FLOATS;
        float* Bd = Bs + stage * TILE_FLOATS;
#pragma unroll
        for (int i = 0; i < 4; i++) {
            int idx = tid + i*256;
            int row = idx >> 3;
            int kq  = (idx & 7) * 4;
            cp_async16(smem_u32(Ad + row*ASTR + kq),
                       g_ctx + (size_t)(m0 + row)*DMODEL + k0 + kq);
            cp_async16(smem_u32(Bd + row*ASTR + kq),
                       Wo + (size_t)(n0 + row)*DMODEL + k0 + kq);
        }
        cp_commit();
    };

    load_stage(0, 0);
    load_stage(1, 1);
    for (int kt = 0; kt < NKT; kt++) {
        if (kt < NKT - 1) cp_wait1(); else cp_wait0();
        __syncthreads();
        gemm_compute_tile(As + (kt&1)*TILE_FLOATS, Bs + (kt&1)*TILE_FLOATS,
                          warp_m, warp_n, lane, c);
        __syncthreads();
        if (kt + 2 < NKT) load_stage(kt + 2, kt & 1);
    }

    const int lq = lane >> 2;
    const int lc = (lane & 3) * 2;
#pragma unroll
    for (int mt = 0; mt < 4; mt++) {
#pragma unroll
        for (int rv = 0; rv < 2; rv++) {
            int m = m0 + warp_m + mt*16 + lq + rv*8;
#pragma unroll
            for (int nt = 0; nt < 4; nt++) {
                int nf = n0 + warp_n + nt*8 + lc;
                float v0 = c[mt][nt][rv*2+0] + bo[nf];
                float v1 = c[mt][nt][rv*2+1] + bo[nf+1];
                *(float2*)(out + (size_t)m*DMODEL + nf) = make_float2(v0, v1);
            }
        }
    }
}

// ---------------------------------------------------------------------------
extern "C" void kernel_launch(void* const* d_in, const int* in_sizes, int n_in,
                              void* d_out, int out_size)
{
    const float* x     = (const float*)d_in[0];
    const float* Wqk_w = (const float*)d_in[1];
    const float* Wqk_b = (const float*)d_in[2];
    const float* Wv_w  = (const float*)d_in[3];
    const float* Wv_b  = (const float*)d_in[4];
    const float* Wo_w  = (const float*)d_in[5];
    const float* Wo_b  = (const float*)d_in[6];
    float* out = (float*)d_out;

    static int attr_set = 0;
    if (!attr_set) {
        cudaFuncSetAttribute(qkv_tc_gemm,
            cudaFuncAttributeMaxDynamicSharedMemorySize, GEMM_SMEM_BYTES);
        cudaFuncSetAttribute(out_tc_gemm,
            cudaFuncAttributeMaxDynamicSharedMemorySize, GEMM_SMEM_BYTES);
        cudaFuncSetAttribute(chunk_out_kernel,
            cudaFuncAttributeMaxDynamicSharedMemorySize, SMEM4_BYTES);
        attr_set = 1;
    }

    dim3 g1(NFEAT/128, NTOK/128);
    qkv_tc_gemm<<<g1, 256, GEMM_SMEM_BYTES>>>(x, Wqk_w, Wqk_b, Wv_w, Wv_b);

    chunk_local_kernel<<<BHEADS*NCHUNK, 256>>>();
    scan_kernel<<<BHEADS, 256>>>();
    chunk_out_kernel<<<BHEADS*NCHUNK, 128, SMEM4_BYTES>>>();

    dim3 g5(DMODEL/128, NTOK/128);
    out_tc_gemm<<<g5, 256, GEMM_SMEM_BYTES>>>(Wo_w, Wo_b, out);
}

// round 3
// speedup vs baseline: 2.1635x; 1.1414x over previous
#include <cuda_runtime.h>
#include <cuda_bf16.h>
#include <math.h>
#include <stdint.h>

// Problem constants
#define BATCH 2
#define SEQ   2048
#define DMODEL 512
#define NHEAD 8
#define DHEAD 64
#define NTOK  (BATCH*SEQ)          // 4096
#define NQK   1024
#define NFEAT 1536
#define CHUNK 128
#define NCHUNK (SEQ/CHUNK)         // 16
#define BHEADS (BATCH*NHEAD)       // 16

// Scratch (device globals)
__device__ float g_q[BHEADS*SEQ*DHEAD];
__device__ float g_k[BHEADS*SEQ*DHEAD];
__device__ float g_v[BHEADS*SEQ*DHEAD];
__device__ float g_ctx[NTOK*DMODEL];
__device__ float g_kv_loc[BHEADS*NCHUNK*DHEAD*DHEAD];
__device__ float g_kv_pre[BHEADS*NCHUNK*DHEAD*DHEAD];
__device__ float g_z_loc[BHEADS*NCHUNK*DHEAD];
__device__ float g_z_pre[BHEADS*NCHUNK*DHEAD];
// pre-rounded (tf32-valued fp32) operands
__device__ float g_xr[NTOK*DMODEL];
__device__ float g_wqkr[NQK*DMODEL];
__device__ float g_wvr[DMODEL*DMODEL];
__device__ float g_wor[DMODEL*DMODEL];

// ---------------------------------------------------------------------------
// Helpers
// ---------------------------------------------------------------------------
__device__ __forceinline__ uint32_t smem_u32(const void* p) {
    return (uint32_t)__cvta_generic_to_shared(p);
}
__device__ __forceinline__ void cp_async16(uint32_t s, const void* g) {
    asm volatile("cp.async.cg.shared.global [%0], [%1], 16;\n" :: "r"(s), "l"(g));
}
__device__ __forceinline__ void cp_commit() { asm volatile("cp.async.commit_group;\n"); }
__device__ __forceinline__ void cp_wait1()  { asm volatile("cp.async.wait_group 1;\n"); }
__device__ __forceinline__ void cp_wait0()  { asm volatile("cp.async.wait_group 0;\n"); }
__device__ __forceinline__ uint32_t f2tf(float f) {
    uint32_t r;
    asm("cvt.rna.tf32.f32 %0, %1;" : "=r"(r) : "f"(f));
    return r;
}
__device__ __forceinline__ float tf32v(float f) { return __uint_as_float(f2tf(f)); }
__device__ __forceinline__ void mma_tf32(float c[4],
    uint32_t a0, uint32_t a1, uint32_t a2, uint32_t a3,
    uint32_t b0, uint32_t b1)
{
    asm volatile(
        "mma.sync.aligned.m16n8k8.row.col.f32.tf32.tf32.f32 "
        "{%0,%1,%2,%3}, {%4,%5,%6,%7}, {%8,%9}, {%0,%1,%2,%3};"
        : "+f"(c[0]), "+f"(c[1]), "+f"(c[2]), "+f"(c[3])
        : "r"(a0), "r"(a1), "r"(a2), "r"(a3), "r"(b0), "r"(b1));
}
#define B32(x) __float_as_uint(x)

// ---------------------------------------------------------------------------
// Kernel 0: round inputs to tf32-valued fp32
// ---------------------------------------------------------------------------
#define N4_X   (NTOK*DMODEL/4)     // 524288
#define N4_WQK (NQK*DMODEL/4)      // 131072
#define N4_WV  (DMODEL*DMODEL/4)   // 65536
#define N4_WO  (DMODEL*DMODEL/4)
#define N4_TOT (N4_X+N4_WQK+N4_WV+N4_WO)   // 786432

__global__ __launch_bounds__(256) void round_kernel(
    const float4* __restrict__ x, const float4* __restrict__ wqk,
    const float4* __restrict__ wv, const float4* __restrict__ wo)
{
    int idx = blockIdx.x * 256 + threadIdx.x;
    const float4* src; float4* dst; int off;
    if (idx < N4_X)                         { src = x;   dst = (float4*)g_xr;   off = idx; }
    else if (idx < N4_X+N4_WQK)             { src = wqk; dst = (float4*)g_wqkr; off = idx - N4_X; }
    else if (idx < N4_X+N4_WQK+N4_WV)       { src = wv;  dst = (float4*)g_wvr;  off = idx - N4_X - N4_WQK; }
    else                                    { src = wo;  dst = (float4*)g_wor;  off = idx - N4_X - N4_WQK - N4_WV; }
    float4 v = src[off];
    v.x = tf32v(v.x); v.y = tf32v(v.y); v.z = tf32v(v.z); v.w = tf32v(v.w);
    dst[off] = v;
}

// ---------------------------------------------------------------------------
// TF32 GEMM: 128x128x32 tiles, 8 warps of 64x32, operands pre-rounded (no cvt)
// ---------------------------------------------------------------------------
#define KT 32
#define NKT (DMODEL/KT)            // 16
#define ASTR 36
#define TILE_FLOATS (128*ASTR)
#define GEMM_SMEM_BYTES (2*2*TILE_FLOATS*4)

__device__ __forceinline__ void gemm_compute_tile(
    const float* __restrict__ A, const float* __restrict__ B,
    int warp_m, int warp_n, int lane, float c[4][4][4])
{
    const int lq = lane >> 2;
    const int lr = lane & 3;
#pragma unroll
    for (int kk = 0; kk < KT; kk += 8) {
        uint32_t af[4][4];
        uint32_t bf[4][2];
#pragma unroll
        for (int mt = 0; mt < 4; mt++) {
            int r = warp_m + mt*16 + lq;
            af[mt][0] = B32(A[r*ASTR + kk + lr]);
            af[mt][1] = B32(A[(r+8)*ASTR + kk + lr]);
            af[mt][2] = B32(A[r*ASTR + kk + 4 + lr]);
            af[mt][3] = B32(A[(r+8)*ASTR + kk + 4 + lr]);
        }
#pragma unroll
        for (int nt = 0; nt < 4; nt++) {
            int n = warp_n + nt*8 + lq;
            bf[nt][0] = B32(B[n*ASTR + kk + lr]);
            bf[nt][1] = B32(B[n*ASTR + kk + 4 + lr]);
        }
#pragma unroll
        for (int mt = 0; mt < 4; mt++)
#pragma unroll
            for (int nt = 0; nt < 4; nt++)
                mma_tf32(c[mt][nt], af[mt][0], af[mt][1], af[mt][2], af[mt][3],
                         bf[nt][0], bf[nt][1]);
    }
}

// ---------------------------------------------------------------------------
// Kernel 1: fused QKV GEMM (tensor cores), epilogue: bias, elu+1, tf32 round,
// scatter to head-major.
// ---------------------------------------------------------------------------
__global__ __launch_bounds__(256) void qkv_tc_gemm(
    const float* __restrict__ bqk, const float* __restrict__ bv)
{
    extern __shared__ float smem[];
    float* As = smem;
    float* Bs = smem + 2*TILE_FLOATS;

    const int n0 = blockIdx.x * 128;
    const int m0 = blockIdx.y * 128;
    const int tid = threadIdx.x;
    const int wid = tid >> 5;
    const int lane = tid & 31;
    const int warp_m = (wid & 1) * 64;
    const int warp_n = (wid >> 1) * 32;

    float c[4][4][4];
#pragma unroll
    for (int mt = 0; mt < 4; mt++)
#pragma unroll
        for (int nt = 0; nt < 4; nt++)
#pragma unroll
            for (int i = 0; i < 4; i++) c[mt][nt][i] = 0.f;

    auto load_stage = [&](int kt, int stage) {
        const int k0 = kt * KT;
        float* Ad = As + stage * TILE_FLOATS;
        float* Bd = Bs + stage * TILE_FLOATS;
#pragma unroll
        for (int i = 0; i < 4; i++) {
            int idx = tid + i*256;
            int row = idx >> 3;
            int kq  = (idx & 7) * 4;
            cp_async16(smem_u32(Ad + row*ASTR + kq),
                       g_xr + (size_t)(m0 + row)*DMODEL + k0 + kq);
            int n = n0 + row;
            const float* wrow = (n < NQK) ? (g_wqkr + (size_t)n*DMODEL)
                                          : (g_wvr + (size_t)(n-NQK)*DMODEL);
            cp_async16(smem_u32(Bd + row*ASTR + kq), wrow + k0 + kq);
        }
        cp_commit();
    };

    load_stage(0, 0);
    load_stage(1, 1);
    for (int kt = 0; kt < NKT; kt++) {
        if (kt < NKT - 1) cp_wait1(); else cp_wait0();
        __syncthreads();
        gemm_compute_tile(As + (kt&1)*TILE_FLOATS, Bs + (kt&1)*TILE_FLOATS,
                          warp_m, warp_n, lane, c);
        __syncthreads();
        if (kt + 2 < NKT) load_stage(kt + 2, kt & 1);
    }

    const int lq = lane >> 2;
    const int lc = (lane & 3) * 2;
#pragma unroll
    for (int mt = 0; mt < 4; mt++) {
#pragma unroll
        for (int rv = 0; rv < 2; rv++) {
            int m = m0 + warp_m + mt*16 + lq + rv*8;
            int bb = m / SEQ;
            int ss = m % SEQ;
#pragma unroll
            for (int nt = 0; nt < 4; nt++) {
                int nf = n0 + warp_n + nt*8 + lc;
                float v0 = c[mt][nt][rv*2+0];
                float v1 = c[mt][nt][rv*2+1];
                if (nf < NQK) {
                    v0 += bqk[nf];   v1 += bqk[nf+1];
                    v0 = (v0 > 0.f) ? (v0 + 1.f) : expf(v0);
                    v1 = (v1 > 0.f) ? (v1 + 1.f) : expf(v1);
                } else {
                    v0 += bv[nf-NQK]; v1 += bv[nf-NQK+1];
                }
                v0 = tf32v(v0); v1 = tf32v(v1);
                float* dst;
                if (nf < DMODEL) {
                    int h = nf / DHEAD, d = nf % DHEAD;
                    dst = g_q + (((size_t)(bb*NHEAD + h))*SEQ + ss)*DHEAD + d;
                } else if (nf < NQK) {
                    int nn = nf - DMODEL;
                    int h = nn / DHEAD, d = nn % DHEAD;
                    dst = g_k + (((size_t)(bb*NHEAD + h))*SEQ + ss)*DHEAD + d;
                } else {
                    int nn = nf - NQK;
                    int h = nn / DHEAD, d = nn % DHEAD;
                    dst = g_v + (((size_t)(bb*NHEAD + h))*SEQ + ss)*DHEAD + d;
                }
                *(float2*)dst = make_float2(v0, v1);
            }
        }
    }
}

// ---------------------------------------------------------------------------
// Kernel 2: per-chunk local state
// ---------------------------------------------------------------------------
__global__ __launch_bounds__(256) void chunk_local_kernel()
{
    __shared__ float sk[64][DHEAD];
    __shared__ float sv[64][DHEAD];
    const int blk = blockIdx.x;
    const int bh = blk / NCHUNK;
    const int c  = blk % NCHUNK;
    const float* kp = g_k + ((size_t)bh*SEQ + c*CHUNK)*DHEAD;
    const float* vp = g_v + ((size_t)bh*SEQ + c*CHUNK)*DHEAD;
    const int tid = threadIdx.x;
    const int dk0 = tid >> 2;
    const int dv0 = (tid & 3) * 16;

    float acc[16];
#pragma unroll
    for (int i = 0; i < 16; i++) acc[i] = 0.f;
    float zacc = 0.f;

    for (int half = 0; half < 2; half++) {
        const float4* k4 = (const float4*)(kp + half*64*DHEAD);
        const float4* v4 = (const float4*)(vp + half*64*DHEAD);
        __syncthreads();
        for (int i = tid; i < 64*DHEAD/4; i += 256) {
            ((float4*)sk)[i] = k4[i];
            ((float4*)sv)[i] = v4[i];
        }
        __syncthreads();
        for (int s = 0; s < 64; s++) {
            float kv = sk[s][dk0];
            zacc += kv;
            const float4* svr = (const float4*)(&sv[s][dv0]);
#pragma unroll
            for (int j = 0; j < 4; j++) {
                float4 vv = svr[j];
                acc[j*4+0] += kv*vv.x;
                acc[j*4+1] += kv*vv.y;
                acc[j*4+2] += kv*vv.z;
                acc[j*4+3] += kv*vv.w;
            }
        }
    }
    float* kvout = g_kv_loc + (size_t)blk * (DHEAD*DHEAD);
#pragma unroll
    for (int j = 0; j < 4; j++)
        *(float4*)(kvout + dk0*DHEAD + dv0 + j*4) =
            make_float4(acc[j*4], acc[j*4+1], acc[j*4+2], acc[j*4+3]);
    if ((tid & 3) == 0) g_z_loc[(size_t)blk*DHEAD + dk0] = zacc;
}

// ---------------------------------------------------------------------------
// Kernel 3: exclusive prefix scan along chunks
// ---------------------------------------------------------------------------
__global__ __launch_bounds__(256) void scan_kernel()
{
    const int bh = blockIdx.x;
    for (int e = threadIdx.x; e < DHEAD*DHEAD; e += blockDim.x) {
        float run = 0.f;
        for (int c = 0; c < NCHUNK; c++) {
            size_t idx = ((size_t)(bh*NCHUNK + c))*(DHEAD*DHEAD) + e;
            g_kv_pre[idx] = run;
            run += g_kv_loc[idx];
        }
    }
    if (threadIdx.x < DHEAD) {
        float run = 0.f;
        for (int c = 0; c < NCHUNK; c++) {
            size_t idx = ((size_t)(bh*NCHUNK + c))*DHEAD + threadIdx.x;
            g_z_pre[idx] = run;
            run += g_z_loc[idx];
        }
    }
}

// ---------------------------------------------------------------------------
// Kernel 4: tensor-core chunk readout.
// Per block (bh,chunk): S = Q K^T (masked), ctx/nu = [S|Q]*[V,1 ; KVpre,zpre].
// 8 warps; warp w owns token rows [16w,16w+16).
// ---------------------------------------------------------------------------
#define SQ_STR  68
#define SK_STR  68
#define SVT_STR 132
#define SKVT_STR 68
#define SS_STR  36
#define SQ_OFF   0
#define SK_OFF   (SQ_OFF + 128*SQ_STR)          // 8704
#define SVT_OFF  (SK_OFF + 128*SK_STR)          // 17408
#define SKVT_OFF (SVT_OFF + 72*SVT_STR)         // 26912
#define SS_OFF   (SKVT_OFF + 72*SKVT_STR)       // 31808
#define CO_SMEM_FLOATS (SS_OFF + 128*SS_STR)    // 36416
#define CO_SMEM_BYTES (CO_SMEM_FLOATS*4)        // 145664

__global__ __launch_bounds__(256) void chunk_out_tc_kernel()
{
    extern __shared__ float sm[];
    float* sq   = sm + SQ_OFF;
    float* sk   = sm + SK_OFF;
    float* svt  = sm + SVT_OFF;
    float* skvt = sm + SKVT_OFF;
    float* ss   = sm + SS_OFF;

    const int blk = blockIdx.x;
    const int bh = blk / NCHUNK;
    const int c  = blk % NCHUNK;
    const int tid = threadIdx.x;
    const int wid = tid >> 5;
    const int lane = tid & 31;
    const int lq = lane >> 2;
    const int lr = lane & 3;
    const int wm = wid * 16;

    const size_t base = ((size_t)bh*SEQ + (size_t)c*CHUNK)*DHEAD;

    // --- load q,k rows (padded stride, float4) ---
    {
        const float4* q4 = (const float4*)(g_q + base);
        const float4* k4 = (const float4*)(g_k + base);
#pragma unroll
        for (int i = 0; i < 8; i++) {
            int idx = tid + i*256;          // 0..2047
            int row = idx >> 4;
            int c4  = (idx & 15) * 4;
            *(float4*)(sq + row*SQ_STR + c4) = q4[idx];
            *(float4*)(sk + row*SK_STR + c4) = k4[idx];
        }
    }
    // --- v transposed: svt[d][t] = v[t][d]; row 64 = ones; rows 65..71 = 0 ---
    {
        const float* vp = g_v + base;
        int t  = tid >> 1;
        int dh = (tid & 1) * 32;
#pragma unroll
        for (int i = 0; i < 8; i++) {
            float4 vv = *(const float4*)(vp + t*DHEAD + dh + i*4);
            svt[(dh + i*4 + 0)*SVT_STR + t] = vv.x;
            svt[(dh + i*4 + 1)*SVT_STR + t] = vv.y;
            svt[(dh + i*4 + 2)*SVT_STR + t] = vv.z;
            svt[(dh + i*4 + 3)*SVT_STR + t] = vv.w;
        }
        if (tid < 128) {
            svt[64*SVT_STR + tid] = 1.0f;
#pragma unroll
            for (int r = 65; r < 72; r++) svt[r*SVT_STR + tid] = 0.f;
        }
    }
    // --- kv_pre transposed: skvt[n][dk] = kv_pre[dk][n]; row 64 = z_pre ---
    {
        const float* kvp = g_kv_pre + (size_t)blk*(DHEAD*DHEAD);
        int dk = tid >> 1;
        if (dk < 64) {
            int nh = (tid & 1) * 32;
#pragma unroll
            for (int i = 0; i < 8; i++) {
                float4 vv = *(const float4*)(kvp + dk*DHEAD + nh + i*4);
                skvt[(nh + i*4 + 0)*SKVT_STR + dk] = tf32v(vv.x);
                skvt[(nh + i*4 + 1)*SKVT_STR + dk] = tf32v(vv.y);
                skvt[(nh + i*4 + 2)*SKVT_STR + dk] = tf32v(vv.z);
                skvt[(nh + i*4 + 3)*SKVT_STR + dk] = tf32v(vv.w);
            }
        }
        if (tid < 64) {
            skvt[64*SKVT_STR + tid] = tf32v(g_z_pre[(size_t)blk*DHEAD + tid]);
#pragma unroll
            for (int r = 65; r < 72; r++) skvt[r*SKVT_STR + tid] = 0.f;
        }
    }
    __syncthreads();

    // accumulators: 9 n-tiles (cols 0..71; col 64 = nu)
    float acc[9][4];
#pragma unroll
    for (int nt = 0; nt < 9; nt++)
#pragma unroll
        for (int i = 0; i < 4; i++) acc[nt][i] = 0.f;

    const int r0 = wm + lq;

    // --- 4 key-column blocks of 32 ---
    for (int j = 0; j < 4; j++) {
        const int j32 = j * 32;
        const bool live = (j32 <= wm + 15);

        if (live) {
            float sfrag[4][4];
#pragma unroll
            for (int nt = 0; nt < 4; nt++)
#pragma unroll
                for (int i = 0; i < 4; i++) sfrag[nt][i] = 0.f;
#pragma unroll
            for (int kk = 0; kk < 64; kk += 8) {
                uint32_t a0 = B32(sq[r0*SQ_STR + kk + lr]);
                uint32_t a1 = B32(sq[(r0+8)*SQ_STR + kk + lr]);
                uint32_t a2 = B32(sq[r0*SQ_STR + kk + 4 + lr]);
                uint32_t a3 = B32(sq[(r0+8)*SQ_STR + kk + 4 + lr]);
#pragma unroll
                for (int nt = 0; nt < 4; nt++) {
                    uint32_t b0 = B32(sk[(j32 + nt*8 + lq)*SK_STR + kk + lr]);
                    uint32_t b1 = B32(sk[(j32 + nt*8 + lq)*SK_STR + kk + 4 + lr]);
                    mma_tf32(sfrag[nt], a0, a1, a2, a3, b0, b1);
                }
            }
            // mask + tf32 round + store to ss
#pragma unroll
            for (int nt = 0; nt < 4; nt++) {
                int colg = j32 + nt*8 + 2*lr;
                int cl   = nt*8 + 2*lr;
                float v00 = (colg   <= r0) ? sfrag[nt][0] : 0.f;
                float v01 = (colg+1 <= r0) ? sfrag[nt][1] : 0.f;
                float v10 = (colg   <= r0+8) ? sfrag[nt][2] : 0.f;
                float v11 = (colg+1 <= r0+8) ? sfrag[nt][3] : 0.f;
                *(float2*)(ss + r0*SS_STR + cl)     = make_float2(tf32v(v00), tf32v(v01));
                *(float2*)(ss + (r0+8)*SS_STR + cl) = make_float2(tf32v(v10), tf32v(v11));
            }
        } else {
#pragma unroll
            for (int nt = 0; nt < 4; nt++) {
                int cl = nt*8 + 2*lr;
                *(float2*)(ss + r0*SS_STR + cl)     = make_float2(0.f, 0.f);
                *(float2*)(ss + (r0+8)*SS_STR + cl) = make_float2(0.f, 0.f);
            }
        }
        __syncthreads();

        if (live) {
#pragma unroll
            for (int kk = 0; kk < 32; kk += 8) {
                uint32_t a0 = B32(ss[r0*SS_STR + kk + lr]);
                uint32_t a1 = B32(ss[(r0+8)*SS_STR + kk + lr]);
                uint32_t a2 = B32(ss[r0*SS_STR + kk + 4 + lr]);
                uint32_t a3 = B32(ss[(r0+8)*SS_STR + kk + 4 + lr]);
#pragma unroll
                for (int nt = 0; nt < 9; nt++) {
                    uint32_t b0 = B32(svt[(nt*8 + lq)*SVT_STR + j32 + kk + lr]);
                    uint32_t b1 = B32(svt[(nt*8 + lq)*SVT_STR + j32 + kk + 4 + lr]);
                    mma_tf32(acc[nt], a0, a1, a2, a3, b0, b1);
                }
            }
        }
        __syncthreads();
    }

    // --- inter-chunk part: Q @ [KV_pre | z_pre] ---
#pragma unroll
    for (int kk = 0; kk < 64; kk += 8) {
        uint32_t a0 = B32(sq[r0*SQ_STR + kk + lr]);
        uint32_t a1 = B32(sq[(r0+8)*SQ_STR + kk + lr]);
        uint32_t a2 = B32(sq[r0*SQ_STR + kk + 4 + lr]);
        uint32_t a3 = B32(sq[(r0+8)*SQ_STR + kk + 4 + lr]);
#pragma unroll
        for (int nt = 0; nt < 9; nt++) {
            uint32_t b0 = B32(skvt[(nt*8 + lq)*SKVT_STR + kk + lr]);
            uint32_t b1 = B32(skvt[(nt*8 + lq)*SKVT_STR + kk + 4 + lr]);
            mma_tf32(acc[nt], a0, a1, a2, a3, b0, b1);
        }
    }

    // --- epilogue: nu broadcast, divide, tf32 round, store to g_ctx ---
    float nu0 = __shfl_sync(0xffffffffu, acc[8][0], lane & 28);
    float nu1 = __shfl_sync(0xffffffffu, acc[8][2], lane & 28);
    float inv0 = 1.f / nu0;
    float inv1 = 1.f / nu1;

    const int b = bh / NHEAD, h = bh % NHEAD;
    const int s0 = c*CHUNK + r0;
    float* out0 = g_ctx + ((size_t)(b*SEQ + s0))*DMODEL + h*DHEAD;
    float* out1 = g_ctx + ((size_t)(b*SEQ + s0 + 8))*DMODEL + h*DHEAD;
#pragma unroll
    for (int nt = 0; nt < 8; nt++) {
        int cl = nt*8 + 2*lr;
        *(float2*)(out0 + cl) = make_float2(tf32v(acc[nt][0]*inv0), tf32v(acc[nt][1]*inv0));
        *(float2*)(out1 + cl) = make_float2(tf32v(acc[nt][2]*inv1), tf32v(acc[nt][3]*inv1));
    }
}

// ---------------------------------------------------------------------------
// Kernel 5: output projection (tensor cores), pre-rounded operands
// ---------------------------------------------------------------------------
__global__ __launch_bounds__(256) void out_tc_gemm(
    const float* __restrict__ bo, float* __restrict__ out)
{
    extern __shared__ float smem[];
    float* As = smem;
    float* Bs = smem + 2*TILE_FLOATS;

    const int n0 = blockIdx.x * 128;
    const int m0 = blockIdx.y * 128;
    const int tid = threadIdx.x;
    const int wid = tid >> 5;
    const int lane = tid & 31;
    const int warp_m = (wid & 1) * 64;
    const int warp_n = (wid >> 1) * 32;

    float c[4][4][4];
#pragma unroll
    for (int mt = 0; mt < 4; mt++)
#pragma unroll
        for (int nt = 0; nt < 4; nt++)
#pragma unroll
            for (int i = 0; i < 4; i++) c[mt][nt][i] = 0.f;

    auto load_stage = [&](int kt, int stage) {
        const int k0 = kt * KT;
        float* Ad = As + stage * TILE_FLOATS;
        float* Bd = Bs + stage * TILE_FLOATS;
#pragma unroll
        for (int i = 0; i < 4; i++) {
            int idx = tid + i*256;
            int row = idx >> 3;
            int kq  = (idx & 7) * 4;
            cp_async16(smem_u32(Ad + row*ASTR + kq),
                       g_ctx + (size_t)(m0 + row)*DMODEL + k0 + kq);
            cp_async16(smem_u32(Bd + row*ASTR + kq),
                       g_wor + (size_t)(n0 + row)*DMODEL + k0 + kq);
        }
        cp_commit();
    };

    load_stage(0, 0);
    load_stage(1, 1);
    for (int kt = 0; kt < NKT; kt++) {
        if (kt < NKT - 1) cp_wait1(); else cp_wait0();
        __syncthreads();
        gemm_compute_tile(As + (kt&1)*TILE_FLOATS, Bs + (kt&1)*TILE_FLOATS,
                          warp_m, warp_n, lane, c);
        __syncthreads();
        if (kt + 2 < NKT) load_stage(kt + 2, kt & 1);
    }

    const int lq = lane >> 2;
    const int lc = (lane & 3) * 2;
#pragma unroll
    for (int mt = 0; mt < 4; mt++) {
#pragma unroll
        for (int rv = 0; rv < 2; rv++) {
            int m = m0 + warp_m + mt*16 + lq + rv*8;
#pragma unroll
            for (int nt = 0; nt < 4; nt++) {
                int nf = n0 + warp_n + nt*8 + lc;
                float v0 = c[mt][nt][rv*2+0] + bo[nf];
                float v1 = c[mt][nt][rv*2+1] + bo[nf+1];
                *(float2*)(out + (size_t)m*DMODEL + nf) = make_float2(v0, v1);
            }
        }
    }
}

// ---------------------------------------------------------------------------
extern "C" void kernel_launch(void* const* d_in, const int* in_sizes, int n_in,
                              void* d_out, int out_size)
{
    const float* x     = (const float*)d_in[0];
    const float* Wqk_w = (const float*)d_in[1];
    const float* Wqk_b = (const float*)d_in[2];
    const float* Wv_w  = (const float*)d_in[3];
    const float* Wv_b  = (const float*)d_in[4];
    const float* Wo_w  = (const float*)d_in[5];
    const float* Wo_b  = (const float*)d_in[6];
    float* out = (float*)d_out;

    cudaFuncSetAttribute(qkv_tc_gemm,
        cudaFuncAttributeMaxDynamicSharedMemorySize, GEMM_SMEM_BYTES);
    cudaFuncSetAttribute(out_tc_gemm,
        cudaFuncAttributeMaxDynamicSharedMemorySize, GEMM_SMEM_BYTES);
    cudaFuncSetAttribute(chunk_out_tc_kernel,
        cudaFuncAttributeMaxDynamicSharedMemorySize, CO_SMEM_BYTES);

    round_kernel<<<N4_TOT/256, 256>>>((const float4*)x, (const float4*)Wqk_w,
                                      (const float4*)Wv_w, (const float4*)Wo_w);

    dim3 g1(NFEAT/128, NTOK/128);
    qkv_tc_gemm<<<g1, 256, GEMM_SMEM_BYTES>>>(Wqk_b, Wv_b);

    chunk_local_kernel<<<BHEADS*NCHUNK, 256>>>();
    scan_kernel<<<BHEADS, 256>>>();
    chunk_out_tc_kernel<<<BHEADS*NCHUNK, 256, CO_SMEM_BYTES>>>();

    dim3 g5(DMODEL/128, NTOK/128);
    out_tc_gemm<<<g5, 256, GEMM_SMEM_BYTES>>>(Wo_b, out);
}

// round 4
// speedup vs baseline: 2.4585x; 1.1363x over previous
#include <cuda_runtime.h>
#include <cuda_bf16.h>
#include <math.h>
#include <stdint.h>

// Problem constants
#define BATCH 2
#define SEQ   2048
#define DMODEL 512
#define NHEAD 8
#define DHEAD 64
#define NTOK  (BATCH*SEQ)          // 4096
#define NQK   1024
#define NFEAT 1536
#define CHUNK 128
#define NCHUNK (SEQ/CHUNK)         // 16
#define BHEADS (BATCH*NHEAD)       // 16

// Scratch (device globals)
__device__ float g_q[BHEADS*SEQ*DHEAD];
__device__ float g_k[BHEADS*SEQ*DHEAD];
__device__ float g_v[BHEADS*SEQ*DHEAD];
__device__ float g_ctx[NTOK*DMODEL];
__device__ float g_kv_pre[BHEADS*NCHUNK*DHEAD*DHEAD];
__device__ float g_z_pre[BHEADS*NCHUNK*DHEAD];
// pre-rounded (tf32-valued fp32) operands
__device__ float g_xr[NTOK*DMODEL];
__device__ float g_wqkr[NQK*DMODEL];
__device__ float g_wvr[DMODEL*DMODEL];
__device__ float g_wor[DMODEL*DMODEL];

// ---------------------------------------------------------------------------
// Helpers
// ---------------------------------------------------------------------------
__device__ __forceinline__ uint32_t smem_u32(const void* p) {
    return (uint32_t)__cvta_generic_to_shared(p);
}
__device__ __forceinline__ void cp_async16(uint32_t s, const void* g) {
    asm volatile("cp.async.cg.shared.global [%0], [%1], 16;\n" :: "r"(s), "l"(g));
}
__device__ __forceinline__ void cp_commit() { asm volatile("cp.async.commit_group;\n"); }
__device__ __forceinline__ void cp_wait1()  { asm volatile("cp.async.wait_group 1;\n"); }
__device__ __forceinline__ void cp_wait0()  { asm volatile("cp.async.wait_group 0;\n"); }
__device__ __forceinline__ uint32_t f2tf(float f) {
    uint32_t r;
    asm("cvt.rna.tf32.f32 %0, %1;" : "=r"(r) : "f"(f));
    return r;
}
__device__ __forceinline__ float tf32v(float f) { return __uint_as_float(f2tf(f)); }
__device__ __forceinline__ void mma_tf32(float c[4],
    uint32_t a0, uint32_t a1, uint32_t a2, uint32_t a3,
    uint32_t b0, uint32_t b1)
{
    asm volatile(
        "mma.sync.aligned.m16n8k8.row.col.f32.tf32.tf32.f32 "
        "{%0,%1,%2,%3}, {%4,%5,%6,%7}, {%8,%9}, {%0,%1,%2,%3};"
        : "+f"(c[0]), "+f"(c[1]), "+f"(c[2]), "+f"(c[3])
        : "r"(a0), "r"(a1), "r"(a2), "r"(a3), "r"(b0), "r"(b1));
}
#define B32(x) __float_as_uint(x)

// ---------------------------------------------------------------------------
// Kernel 0: round inputs to tf32-valued fp32
// ---------------------------------------------------------------------------
#define N4_X   (NTOK*DMODEL/4)
#define N4_WQK (NQK*DMODEL/4)
#define N4_WV  (DMODEL*DMODEL/4)
#define N4_WO  (DMODEL*DMODEL/4)
#define N4_TOT (N4_X+N4_WQK+N4_WV+N4_WO)

__global__ __launch_bounds__(256) void round_kernel(
    const float4* __restrict__ x, const float4* __restrict__ wqk,
    const float4* __restrict__ wv, const float4* __restrict__ wo)
{
    int idx = blockIdx.x * 256 + threadIdx.x;
    const float4* src; float4* dst; int off;
    if (idx < N4_X)                         { src = x;   dst = (float4*)g_xr;   off = idx; }
    else if (idx < N4_X+N4_WQK)             { src = wqk; dst = (float4*)g_wqkr; off = idx - N4_X; }
    else if (idx < N4_X+N4_WQK+N4_WV)       { src = wv;  dst = (float4*)g_wvr;  off = idx - N4_X - N4_WQK; }
    else                                    { src = wo;  dst = (float4*)g_wor;  off = idx - N4_X - N4_WQK - N4_WV; }
    float4 v = src[off];
    v.x = tf32v(v.x); v.y = tf32v(v.y); v.z = tf32v(v.z); v.w = tf32v(v.w);
    dst[off] = v;
}

// ---------------------------------------------------------------------------
// TF32 GEMM: 128x128x32 tiles, 8 warps of 64x32, operands pre-rounded
// ---------------------------------------------------------------------------
#define KT 32
#define NKT (DMODEL/KT)
#define ASTR 36
#define TILE_FLOATS (128*ASTR)
#define GEMM_SMEM_BYTES (2*2*TILE_FLOATS*4)

__device__ __forceinline__ void gemm_compute_tile(
    const float* __restrict__ A, const float* __restrict__ B,
    int warp_m, int warp_n, int lane, float c[4][4][4])
{
    const int lq = lane >> 2;
    const int lr = lane & 3;
#pragma unroll
    for (int kk = 0; kk < KT; kk += 8) {
        uint32_t af[4][4];
        uint32_t bf[4][2];
#pragma unroll
        for (int mt = 0; mt < 4; mt++) {
            int r = warp_m + mt*16 + lq;
            af[mt][0] = B32(A[r*ASTR + kk + lr]);
            af[mt][1] = B32(A[(r+8)*ASTR + kk + lr]);
            af[mt][2] = B32(A[r*ASTR + kk + 4 + lr]);
            af[mt][3] = B32(A[(r+8)*ASTR + kk + 4 + lr]);
        }
#pragma unroll
        for (int nt = 0; nt < 4; nt++) {
            int n = warp_n + nt*8 + lq;
            bf[nt][0] = B32(B[n*ASTR + kk + lr]);
            bf[nt][1] = B32(B[n*ASTR + kk + 4 + lr]);
        }
#pragma unroll
        for (int mt = 0; mt < 4; mt++)
#pragma unroll
            for (int nt = 0; nt < 4; nt++)
                mma_tf32(c[mt][nt], af[mt][0], af[mt][1], af[mt][2], af[mt][3],
                         bf[nt][0], bf[nt][1]);
    }
}

// ---------------------------------------------------------------------------
// Kernel 1: fused QKV GEMM (tensor cores)
// ---------------------------------------------------------------------------
__global__ __launch_bounds__(256) void qkv_tc_gemm(
    const float* __restrict__ bqk, const float* __restrict__ bv)
{
    extern __shared__ float smem[];
    float* As = smem;
    float* Bs = smem + 2*TILE_FLOATS;

    const int n0 = blockIdx.x * 128;
    const int m0 = blockIdx.y * 128;
    const int tid = threadIdx.x;
    const int wid = tid >> 5;
    const int lane = tid & 31;
    const int warp_m = (wid & 1) * 64;
    const int warp_n = (wid >> 1) * 32;

    float c[4][4][4];
#pragma unroll
    for (int mt = 0; mt < 4; mt++)
#pragma unroll
        for (int nt = 0; nt < 4; nt++)
#pragma unroll
            for (int i = 0; i < 4; i++) c[mt][nt][i] = 0.f;

    auto load_stage = [&](int kt, int stage) {
        const int k0 = kt * KT;
        float* Ad = As + stage * TILE_FLOATS;
        float* Bd = Bs + stage * TILE_FLOATS;
#pragma unroll
        for (int i = 0; i < 4; i++) {
            int idx = tid + i*256;
            int row = idx >> 3;
            int kq  = (idx & 7) * 4;
            cp_async16(smem_u32(Ad + row*ASTR + kq),
                       g_xr + (size_t)(m0 + row)*DMODEL + k0 + kq);
            int n = n0 + row;
            const float* wrow = (n < NQK) ? (g_wqkr + (size_t)n*DMODEL)
                                          : (g_wvr + (size_t)(n-NQK)*DMODEL);
            cp_async16(smem_u32(Bd + row*ASTR + kq), wrow + k0 + kq);
        }
        cp_commit();
    };

    load_stage(0, 0);
    load_stage(1, 1);
    for (int kt = 0; kt < NKT; kt++) {
        if (kt < NKT - 1) cp_wait1(); else cp_wait0();
        __syncthreads();
        gemm_compute_tile(As + (kt&1)*TILE_FLOATS, Bs + (kt&1)*TILE_FLOATS,
                          warp_m, warp_n, lane, c);
        __syncthreads();
        if (kt + 2 < NKT) load_stage(kt + 2, kt & 1);
    }

    const int lq = lane >> 2;
    const int lc = (lane & 3) * 2;
#pragma unroll
    for (int mt = 0; mt < 4; mt++) {
#pragma unroll
        for (int rv = 0; rv < 2; rv++) {
            int m = m0 + warp_m + mt*16 + lq + rv*8;
            int bb = m / SEQ;
            int ss = m % SEQ;
#pragma unroll
            for (int nt = 0; nt < 4; nt++) {
                int nf = n0 + warp_n + nt*8 + lc;
                float v0 = c[mt][nt][rv*2+0];
                float v1 = c[mt][nt][rv*2+1];
                if (nf < NQK) {
                    v0 += bqk[nf];   v1 += bqk[nf+1];
                    v0 = (v0 > 0.f) ? (v0 + 1.f) : expf(v0);
                    v1 = (v1 > 0.f) ? (v1 + 1.f) : expf(v1);
                } else {
                    v0 += bv[nf-NQK]; v1 += bv[nf-NQK+1];
                }
                v0 = tf32v(v0); v1 = tf32v(v1);
                float* dst;
                if (nf < DMODEL) {
                    int h = nf / DHEAD, d = nf % DHEAD;
                    dst = g_q + (((size_t)(bb*NHEAD + h))*SEQ + ss)*DHEAD + d;
                } else if (nf < NQK) {
                    int nn = nf - DMODEL;
                    int h = nn / DHEAD, d = nn % DHEAD;
                    dst = g_k + (((size_t)(bb*NHEAD + h))*SEQ + ss)*DHEAD + d;
                } else {
                    int nn = nf - NQK;
                    int h = nn / DHEAD, d = nn % DHEAD;
                    dst = g_v + (((size_t)(bb*NHEAD + h))*SEQ + ss)*DHEAD + d;
                }
                *(float2*)dst = make_float2(v0, v1);
            }
        }
    }
}

// ---------------------------------------------------------------------------
// Kernel 2 (NEW): fused chunk state + exclusive prefix scan.
// grid = (BHEADS, NSLAB). Running KV state lives in registers; before
// consuming chunk c, the state (= sum of chunks < c) is stored to g_kv_pre.
// Each block owns a 32-wide dv slab. cp.async double-buffers K/V tiles.
// ---------------------------------------------------------------------------
#define NSLAB 2
#define DVS (DHEAD/NSLAB)          // 32
#define CS_K_FLOATS (CHUNK*DHEAD)  // 8192
#define CS_V_FLOATS (CHUNK*DVS)    // 4096
#define CS_SMEM_BYTES (2*(CS_K_FLOATS+CS_V_FLOATS)*4)   // 98304

__global__ __launch_bounds__(256) void chunk_state_kernel()
{
    extern __shared__ float sm[];
    float* ks = sm;                          // [2][128][64]
    float* vs = sm + 2*CS_K_FLOATS;          // [2][128][32]

    const int bh   = blockIdx.x;
    const int slab = blockIdx.y;
    const int tid  = threadIdx.x;
    const int dk0  = tid >> 2;               // 0..63
    const int dvq  = (tid & 3) * 8;          // 0,8,16,24 within slab

    const float* kp = g_k + (size_t)bh*SEQ*DHEAD;
    const float* vp = g_v + (size_t)bh*SEQ*DHEAD + slab*DVS;

    auto load_stage = [&](int c, int st) {
        const float* kc = kp + (size_t)c*CHUNK*DHEAD;
        const float* vc = vp + (size_t)c*CHUNK*DHEAD;
        float* kd = ks + st*CS_K_FLOATS;
        float* vd = vs + st*CS_V_FLOATS;
        // K: 2048 float4
#pragma unroll
        for (int i = 0; i < 8; i++) {
            int idx = tid + i*256;
            int row = idx >> 4;
            int c4  = (idx & 15) * 4;
            cp_async16(smem_u32(kd + row*DHEAD + c4), kc + row*DHEAD + c4);
        }
        // V slab: 1024 float4 (row stride in gmem = DHEAD)
#pragma unroll
        for (int i = 0; i < 4; i++) {
            int idx = tid + i*256;
            int row = idx >> 3;
            int c4  = (idx & 7) * 4;
            cp_async16(smem_u32(vd + row*DVS + c4), vc + (size_t)row*DHEAD + c4);
        }
        cp_commit();
    };

    float acc[8];
#pragma unroll
    for (int i = 0; i < 8; i++) acc[i] = 0.f;
    float zacc = 0.f;

    load_stage(0, 0);
    load_stage(1, 1);

    for (int c = 0; c < NCHUNK; c++) {
        // exclusive prefix: store current state for chunk c
        float* kvout = g_kv_pre + ((size_t)(bh*NCHUNK + c))*(DHEAD*DHEAD)
                       + dk0*DHEAD + slab*DVS + dvq;
        *(float4*)kvout       = make_float4(acc[0], acc[1], acc[2], acc[3]);
        *(float4*)(kvout + 4) = make_float4(acc[4], acc[5], acc[6], acc[7]);
        if (slab == 0 && (tid & 3) == 0)
            g_z_pre[(size_t)(bh*NCHUNK + c)*DHEAD + dk0] = zacc;

        if (c < NCHUNK - 1) cp_wait1(); else cp_wait0();
        __syncthreads();

        const int st = c & 1;
        const float* kd = ks + st*CS_K_FLOATS;
        const float* vd = vs + st*CS_V_FLOATS;
        for (int s = 0; s < CHUNK; s++) {
            float kv = kd[s*DHEAD + dk0];
            zacc += kv;
            float4 v0 = *(const float4*)(vd + s*DVS + dvq);
            float4 v1 = *(const float4*)(vd + s*DVS + dvq + 4);
            acc[0] += kv*v0.x; acc[1] += kv*v0.y;
            acc[2] += kv*v0.z; acc[3] += kv*v0.w;
            acc[4] += kv*v1.x; acc[5] += kv*v1.y;
            acc[6] += kv*v1.z; acc[7] += kv*v1.w;
        }
        __syncthreads();
        if (c + 2 < NCHUNK) load_stage(c + 2, st);
    }
}

// ---------------------------------------------------------------------------
// Kernel 4: tensor-core chunk readout (unchanged from round 3)
// ---------------------------------------------------------------------------
#define SQ_STR  68
#define SK_STR  68
#define SVT_STR 132
#define SKVT_STR 68
#define SS_STR  36
#define SQ_OFF   0
#define SK_OFF   (SQ_OFF + 128*SQ_STR)
#define SVT_OFF  (SK_OFF + 128*SK_STR)
#define SKVT_OFF (SVT_OFF + 72*SVT_STR)
#define SS_OFF   (SKVT_OFF + 72*SKVT_STR)
#define CO_SMEM_FLOATS (SS_OFF + 128*SS_STR)
#define CO_SMEM_BYTES (CO_SMEM_FLOATS*4)

__global__ __launch_bounds__(256) void chunk_out_tc_kernel()
{
    extern __shared__ float sm[];
    float* sq   = sm + SQ_OFF;
    float* sk   = sm + SK_OFF;
    float* svt  = sm + SVT_OFF;
    float* skvt = sm + SKVT_OFF;
    float* ss   = sm + SS_OFF;

    const int blk = blockIdx.x;
    const int bh = blk / NCHUNK;
    const int c  = blk % NCHUNK;
    const int tid = threadIdx.x;
    const int wid = tid >> 5;
    const int lane = tid & 31;
    const int lq = lane >> 2;
    const int lr = lane & 3;
    const int wm = wid * 16;

    const size_t base = ((size_t)bh*SEQ + (size_t)c*CHUNK)*DHEAD;

    {
        const float4* q4 = (const float4*)(g_q + base);
        const float4* k4 = (const float4*)(g_k + base);
#pragma unroll
        for (int i = 0; i < 8; i++) {
            int idx = tid + i*256;
            int row = idx >> 4;
            int c4  = (idx & 15) * 4;
            *(float4*)(sq + row*SQ_STR + c4) = q4[idx];
            *(float4*)(sk + row*SK_STR + c4) = k4[idx];
        }
    }
    {
        const float* vp = g_v + base;
        int t  = tid >> 1;
        int dh = (tid & 1) * 32;
#pragma unroll
        for (int i = 0; i < 8; i++) {
            float4 vv = *(const float4*)(vp + t*DHEAD + dh + i*4);
            svt[(dh + i*4 + 0)*SVT_STR + t] = vv.x;
            svt[(dh + i*4 + 1)*SVT_STR + t] = vv.y;
            svt[(dh + i*4 + 2)*SVT_STR + t] = vv.z;
            svt[(dh + i*4 + 3)*SVT_STR + t] = vv.w;
        }
        if (tid < 128) {
            svt[64*SVT_STR + tid] = 1.0f;
#pragma unroll
            for (int r = 65; r < 72; r++) svt[r*SVT_STR + tid] = 0.f;
        }
    }
    {
        const float* kvp = g_kv_pre + (size_t)blk*(DHEAD*DHEAD);
        int dk = tid >> 1;
        if (dk < 64) {
            int nh = (tid & 1) * 32;
#pragma unroll
            for (int i = 0; i < 8; i++) {
                float4 vv = *(const float4*)(kvp + dk*DHEAD + nh + i*4);
                skvt[(nh + i*4 + 0)*SKVT_STR + dk] = tf32v(vv.x);
                skvt[(nh + i*4 + 1)*SKVT_STR + dk] = tf32v(vv.y);
                skvt[(nh + i*4 + 2)*SKVT_STR + dk] = tf32v(vv.z);
                skvt[(nh + i*4 + 3)*SKVT_STR + dk] = tf32v(vv.w);
            }
        }
        if (tid < 64) {
            skvt[64*SKVT_STR + tid] = tf32v(g_z_pre[(size_t)blk*DHEAD + tid]);
#pragma unroll
            for (int r = 65; r < 72; r++) skvt[r*SKVT_STR + tid] = 0.f;
        }
    }
    __syncthreads();

    float acc[9][4];
#pragma unroll
    for (int nt = 0; nt < 9; nt++)
#pragma unroll
        for (int i = 0; i < 4; i++) acc[nt][i] = 0.f;

    const int r0 = wm + lq;

    for (int j = 0; j < 4; j++) {
        const int j32 = j * 32;
        const bool live = (j32 <= wm + 15);

        if (live) {
            float sfrag[4][4];
#pragma unroll
            for (int nt = 0; nt < 4; nt++)
#pragma unroll
                for (int i = 0; i < 4; i++) sfrag[nt][i] = 0.f;
#pragma unroll
            for (int kk = 0; kk < 64; kk += 8) {
                uint32_t a0 = B32(sq[r0*SQ_STR + kk + lr]);
                uint32_t a1 = B32(sq[(r0+8)*SQ_STR + kk + lr]);
                uint32_t a2 = B32(sq[r0*SQ_STR + kk + 4 + lr]);
                uint32_t a3 = B32(sq[(r0+8)*SQ_STR + kk + 4 + lr]);
#pragma unroll
                for (int nt = 0; nt < 4; nt++) {
                    uint32_t b0 = B32(sk[(j32 + nt*8 + lq)*SK_STR + kk + lr]);
                    uint32_t b1 = B32(sk[(j32 + nt*8 + lq)*SK_STR + kk + 4 + lr]);
                    mma_tf32(sfrag[nt], a0, a1, a2, a3, b0, b1);
                }
            }
#pragma unroll
            for (int nt = 0; nt < 4; nt++) {
                int colg = j32 + nt*8 + 2*lr;
                int cl   = nt*8 + 2*lr;
                float v00 = (colg   <= r0) ? sfrag[nt][0] : 0.f;
                float v01 = (colg+1 <= r0) ? sfrag[nt][1] : 0.f;
                float v10 = (colg   <= r0+8) ? sfrag[nt][2] : 0.f;
                float v11 = (colg+1 <= r0+8) ? sfrag[nt][3] : 0.f;
                *(float2*)(ss + r0*SS_STR + cl)     = make_float2(tf32v(v00), tf32v(v01));
                *(float2*)(ss + (r0+8)*SS_STR + cl) = make_float2(tf32v(v10), tf32v(v11));
            }
        } else {
#pragma unroll
            for (int nt = 0; nt < 4; nt++) {
                int cl = nt*8 + 2*lr;
                *(float2*)(ss + r0*SS_STR + cl)     = make_float2(0.f, 0.f);
                *(float2*)(ss + (r0+8)*SS_STR + cl) = make_float2(0.f, 0.f);
            }
        }
        __syncthreads();

        if (live) {
#pragma unroll
            for (int kk = 0; kk < 32; kk += 8) {
                uint32_t a0 = B32(ss[r0*SS_STR + kk + lr]);
                uint32_t a1 = B32(ss[(r0+8)*SS_STR + kk + lr]);
                uint32_t a2 = B32(ss[r0*SS_STR + kk + 4 + lr]);
                uint32_t a3 = B32(ss[(r0+8)*SS_STR + kk + 4 + lr]);
#pragma unroll
                for (int nt = 0; nt < 9; nt++) {
                    uint32_t b0 = B32(svt[(nt*8 + lq)*SVT_STR + j32 + kk + lr]);
                    uint32_t b1 = B32(svt[(nt*8 + lq)*SVT_STR + j32 + kk + 4 + lr]);
                    mma_tf32(acc[nt], a0, a1, a2, a3, b0, b1);
                }
            }
        }
        __syncthreads();
    }

#pragma unroll
    for (int kk = 0; kk < 64; kk += 8) {
        uint32_t a0 = B32(sq[r0*SQ_STR + kk + lr]);
        uint32_t a1 = B32(sq[(r0+8)*SQ_STR + kk + lr]);
        uint32_t a2 = B32(sq[r0*SQ_STR + kk + 4 + lr]);
        uint32_t a3 = B32(sq[(r0+8)*SQ_STR + kk + 4 + lr]);
#pragma unroll
        for (int nt = 0; nt < 9; nt++) {
            uint32_t b0 = B32(skvt[(nt*8 + lq)*SKVT_STR + kk + lr]);
            uint32_t b1 = B32(skvt[(nt*8 + lq)*SKVT_STR + kk + 4 + lr]);
            mma_tf32(acc[nt], a0, a1, a2, a3, b0, b1);
        }
    }

    float nu0 = __shfl_sync(0xffffffffu, acc[8][0], lane & 28);
    float nu1 = __shfl_sync(0xffffffffu, acc[8][2], lane & 28);
    float inv0 = 1.f / nu0;
    float inv1 = 1.f / nu1;

    const int b = bh / NHEAD, h = bh % NHEAD;
    const int s0 = c*CHUNK + r0;
    float* out0 = g_ctx + ((size_t)(b*SEQ + s0))*DMODEL + h*DHEAD;
    float* out1 = g_ctx + ((size_t)(b*SEQ + s0 + 8))*DMODEL + h*DHEAD;
#pragma unroll
    for (int nt = 0; nt < 8; nt++) {
        int cl = nt*8 + 2*lr;
        *(float2*)(out0 + cl) = make_float2(tf32v(acc[nt][0]*inv0), tf32v(acc[nt][1]*inv0));
        *(float2*)(out1 + cl) = make_float2(tf32v(acc[nt][2]*inv1), tf32v(acc[nt][3]*inv1));
    }
}

// ---------------------------------------------------------------------------
// Kernel 5: output projection (tensor cores)
// ---------------------------------------------------------------------------
__global__ __launch_bounds__(256) void out_tc_gemm(
    const float* __restrict__ bo, float* __restrict__ out)
{
    extern __shared__ float smem[];
    float* As = smem;
    float* Bs = smem + 2*TILE_FLOATS;

    const int n0 = blockIdx.x * 128;
    const int m0 = blockIdx.y * 128;
    const int tid = threadIdx.x;
    const int wid = tid >> 5;
    const int lane = tid & 31;
    const int warp_m = (wid & 1) * 64;
    const int warp_n = (wid >> 1) * 32;

    float c[4][4][4];
#pragma unroll
    for (int mt = 0; mt < 4; mt++)
#pragma unroll
        for (int nt = 0; nt < 4; nt++)
#pragma unroll
            for (int i = 0; i < 4; i++) c[mt][nt][i] = 0.f;

    auto load_stage = [&](int kt, int stage) {
        const int k0 = kt * KT;
        float* Ad = As + stage * TILE_FLOATS;
        float* Bd = Bs + stage * TILE_FLOATS;
#pragma unroll
        for (int i = 0; i < 4; i++) {
            int idx = tid + i*256;
            int row = idx >> 3;
            int kq  = (idx & 7) * 4;
            cp_async16(smem_u32(Ad + row*ASTR + kq),
                       g_ctx + (size_t)(m0 + row)*DMODEL + k0 + kq);
            cp_async16(smem_u32(Bd + row*ASTR + kq),
                       g_wor + (size_t)(n0 + row)*DMODEL + k0 + kq);
        }
        cp_commit();
    };

    load_stage(0, 0);
    load_stage(1, 1);
    for (int kt = 0; kt < NKT; kt++) {
        if (kt < NKT - 1) cp_wait1(); else cp_wait0();
        __syncthreads();
        gemm_compute_tile(As + (kt&1)*TILE_FLOATS, Bs + (kt&1)*TILE_FLOATS,
                          warp_m, warp_n, lane, c);
        __syncthreads();
        if (kt + 2 < NKT) load_stage(kt + 2, kt & 1);
    }

    const int lq = lane >> 2;
    const int lc = (lane & 3) * 2;
#pragma unroll
    for (int mt = 0; mt < 4; mt++) {
#pragma unroll
        for (int rv = 0; rv < 2; rv++) {
            int m = m0 + warp_m + mt*16 + lq + rv*8;
#pragma unroll
            for (int nt = 0; nt < 4; nt++) {
                int nf = n0 + warp_n + nt*8 + lc;
                float v0 = c[mt][nt][rv*2+0] + bo[nf];
                float v1 = c[mt][nt][rv*2+1] + bo[nf+1];
                *(float2*)(out + (size_t)m*DMODEL + nf) = make_float2(v0, v1);
            }
        }
    }
}

// ---------------------------------------------------------------------------
extern "C" void kernel_launch(void* const* d_in, const int* in_sizes, int n_in,
                              void* d_out, int out_size)
{
    const float* x     = (const float*)d_in[0];
    const float* Wqk_w = (const float*)d_in[1];
    const float* Wqk_b = (const float*)d_in[2];
    const float* Wv_w  = (const float*)d_in[3];
    const float* Wv_b  = (const float*)d_in[4];
    const float* Wo_w  = (const float*)d_in[5];
    const float* Wo_b  = (const float*)d_in[6];
    float* out = (float*)d_out;

    cudaFuncSetAttribute(qkv_tc_gemm,
        cudaFuncAttributeMaxDynamicSharedMemorySize, GEMM_SMEM_BYTES);
    cudaFuncSetAttribute(out_tc_gemm,
        cudaFuncAttributeMaxDynamicSharedMemorySize, GEMM_SMEM_BYTES);
    cudaFuncSetAttribute(chunk_out_tc_kernel,
        cudaFuncAttributeMaxDynamicSharedMemorySize, CO_SMEM_BYTES);
    cudaFuncSetAttribute(chunk_state_kernel,
        cudaFuncAttributeMaxDynamicSharedMemorySize, CS_SMEM_BYTES);

    round_kernel<<<N4_TOT/256, 256>>>((const float4*)x, (const float4*)Wqk_w,
                                      (const float4*)Wv_w, (const float4*)Wo_w);

    dim3 g1(NFEAT/128, NTOK/128);
    qkv_tc_gemm<<<g1, 256, GEMM_SMEM_BYTES>>>(Wqk_b, Wv_b);

    dim3 g2(BHEADS, NSLAB);
    chunk_state_kernel<<<g2, 256, CS_SMEM_BYTES>>>();

    chunk_out_tc_kernel<<<BHEADS*NCHUNK, 256, CO_SMEM_BYTES>>>();

    dim3 g5(DMODEL/128, NTOK/128);
    out_tc_gemm<<<g5, 256, GEMM_SMEM_BYTES>>>(Wo_b, out);
}

// round 5
// speedup vs baseline: 3.1475x; 1.2803x over previous
#include <cuda_runtime.h>
#include <cuda_bf16.h>
#include <math.h>
#include <stdint.h>

// Problem constants
#define BATCH 2
#define SEQ   2048
#define DMODEL 512
#define NHEAD 8
#define DHEAD 64
#define NTOK  (BATCH*SEQ)          // 4096
#define NQK   1024
#define NFEAT 1536
#define CHUNK 128
#define NCHUNK (SEQ/CHUNK)         // 16
#define BHEADS (BATCH*NHEAD)       // 16

// Scratch (device globals)
__device__ float g_q[BHEADS*SEQ*DHEAD];
__device__ float g_k[BHEADS*SEQ*DHEAD];
__device__ float g_v[BHEADS*SEQ*DHEAD];
__device__ float g_ctx[NTOK*DMODEL];
__device__ float g_kv_pre[BHEADS*NCHUNK*DHEAD*DHEAD];
__device__ float g_z_pre[BHEADS*NCHUNK*DHEAD];
// pre-rounded (tf32-valued fp32) operands
__device__ float g_xr[NTOK*DMODEL];
__device__ float g_wqkr[NQK*DMODEL];
__device__ float g_wvr[DMODEL*DMODEL];
__device__ float g_wor[DMODEL*DMODEL];

// ---------------------------------------------------------------------------
// Helpers
// ---------------------------------------------------------------------------
__device__ __forceinline__ uint32_t smem_u32(const void* p) {
    return (uint32_t)__cvta_generic_to_shared(p);
}
__device__ __forceinline__ void cp_async16(uint32_t s, const void* g) {
    asm volatile("cp.async.cg.shared.global [%0], [%1], 16;\n" :: "r"(s), "l"(g));
}
__device__ __forceinline__ void cp_commit() { asm volatile("cp.async.commit_group;\n"); }
__device__ __forceinline__ void cp_wait1()  { asm volatile("cp.async.wait_group 1;\n"); }
__device__ __forceinline__ void cp_wait0()  { asm volatile("cp.async.wait_group 0;\n"); }
__device__ __forceinline__ uint32_t f2tf(float f) {
    uint32_t r;
    asm("cvt.rna.tf32.f32 %0, %1;" : "=r"(r) : "f"(f));
    return r;
}
__device__ __forceinline__ float tf32v(float f) { return __uint_as_float(f2tf(f)); }
__device__ __forceinline__ void mma_tf32(float c[4],
    uint32_t a0, uint32_t a1, uint32_t a2, uint32_t a3,
    uint32_t b0, uint32_t b1)
{
    asm volatile(
        "mma.sync.aligned.m16n8k8.row.col.f32.tf32.tf32.f32 "
        "{%0,%1,%2,%3}, {%4,%5,%6,%7}, {%8,%9}, {%0,%1,%2,%3};"
        : "+f"(c[0]), "+f"(c[1]), "+f"(c[2]), "+f"(c[3])
        : "r"(a0), "r"(a1), "r"(a2), "r"(a3), "r"(b0), "r"(b1));
}
__device__ __forceinline__ void ldsm_x4(uint32_t& r0, uint32_t& r1,
                                        uint32_t& r2, uint32_t& r3, uint32_t addr)
{
    asm volatile("ldmatrix.sync.aligned.m8n8.x4.shared.b16 {%0,%1,%2,%3}, [%4];"
                 : "=r"(r0), "=r"(r1), "=r"(r2), "=r"(r3) : "r"(addr));
}
__device__ __forceinline__ void ldsm_x2(uint32_t& r0, uint32_t& r1, uint32_t addr)
{
    asm volatile("ldmatrix.sync.aligned.m8n8.x2.shared.b16 {%0,%1}, [%2];"
                 : "=r"(r0), "=r"(r1) : "r"(addr));
}
#define B32(x) __float_as_uint(x)

// ---------------------------------------------------------------------------
// Kernel 0: round inputs to tf32-valued fp32
// ---------------------------------------------------------------------------
#define N4_X   (NTOK*DMODEL/4)
#define N4_WQK (NQK*DMODEL/4)
#define N4_WV  (DMODEL*DMODEL/4)
#define N4_WO  (DMODEL*DMODEL/4)
#define N4_TOT (N4_X+N4_WQK+N4_WV+N4_WO)

__global__ __launch_bounds__(256) void round_kernel(
    const float4* __restrict__ x, const float4* __restrict__ wqk,
    const float4* __restrict__ wv, const float4* __restrict__ wo)
{
    int idx = blockIdx.x * 256 + threadIdx.x;
    const float4* src; float4* dst; int off;
    if (idx < N4_X)                         { src = x;   dst = (float4*)g_xr;   off = idx; }
    else if (idx < N4_X+N4_WQK)             { src = wqk; dst = (float4*)g_wqkr; off = idx - N4_X; }
    else if (idx < N4_X+N4_WQK+N4_WV)       { src = wv;  dst = (float4*)g_wvr;  off = idx - N4_X - N4_WQK; }
    else                                    { src = wo;  dst = (float4*)g_wor;  off = idx - N4_X - N4_WQK - N4_WV; }
    float4 v = src[off];
    v.x = tf32v(v.x); v.y = tf32v(v.y); v.z = tf32v(v.z); v.w = tf32v(v.w);
    dst[off] = v;
}

// ---------------------------------------------------------------------------
// TF32 GEMM: 128x128x32 tiles, 8 warps of 64x32, ldmatrix fragment loads
// ---------------------------------------------------------------------------
#define KT 32
#define NKT (DMODEL/KT)
#define ASTR 36
#define TILE_FLOATS (128*ASTR)
#define GEMM_SMEM_BYTES (2*2*TILE_FLOATS*4)

__device__ __forceinline__ void gemm_compute_tile(
    const float* __restrict__ A, const float* __restrict__ B,
    int warp_m, int warp_n, int lane, float c[4][4][4])
{
    const uint32_t Ab = smem_u32(A);
    const uint32_t Bb = smem_u32(B);
    const int arow = warp_m + (lane & 15);
    const int acol = ((lane >> 4) & 1) * 4;
    const int bg   = lane >> 3;
    const int brow = warp_n + (bg >> 1) * 8 + (lane & 7);
    const int bcol = (bg & 1) * 4;
#pragma unroll
    for (int kk = 0; kk < KT; kk += 8) {
        uint32_t af[4][4];
        uint32_t bf[4][2];
#pragma unroll
        for (int mt = 0; mt < 4; mt++)
            ldsm_x4(af[mt][0], af[mt][1], af[mt][2], af[mt][3],
                    Ab + (uint32_t)(((arow + mt*16)*ASTR + kk + acol)*4));
#pragma unroll
        for (int p = 0; p < 2; p++)
            ldsm_x4(bf[2*p][0], bf[2*p][1], bf[2*p+1][0], bf[2*p+1][1],
                    Bb + (uint32_t)(((brow + p*16)*ASTR + kk + bcol)*4));
#pragma unroll
        for (int mt = 0; mt < 4; mt++)
#pragma unroll
            for (int nt = 0; nt < 4; nt++)
                mma_tf32(c[mt][nt], af[mt][0], af[mt][1], af[mt][2], af[mt][3],
                         bf[nt][0], bf[nt][1]);
    }
}

// ---------------------------------------------------------------------------
// Kernel 1: fused QKV GEMM (tensor cores)
// ---------------------------------------------------------------------------
__global__ __launch_bounds__(256, 2) void qkv_tc_gemm(
    const float* __restrict__ bqk, const float* __restrict__ bv)
{
    extern __shared__ float smem[];
    float* As = smem;
    float* Bs = smem + 2*TILE_FLOATS;

    const int n0 = blockIdx.x * 128;
    const int m0 = blockIdx.y * 128;
    const int tid = threadIdx.x;
    const int wid = tid >> 5;
    const int lane = tid & 31;
    const int warp_m = (wid & 1) * 64;
    const int warp_n = (wid >> 1) * 32;

    float c[4][4][4];
#pragma unroll
    for (int mt = 0; mt < 4; mt++)
#pragma unroll
        for (int nt = 0; nt < 4; nt++)
#pragma unroll
            for (int i = 0; i < 4; i++) c[mt][nt][i] = 0.f;

    auto load_stage = [&](int kt, int stage) {
        const int k0 = kt * KT;
        float* Ad = As + stage * TILE_FLOATS;
        float* Bd = Bs + stage * TILE_FLOATS;
#pragma unroll
        for (int i = 0; i < 4; i++) {
            int idx = tid + i*256;
            int row = idx >> 3;
            int kq  = (idx & 7) * 4;
            cp_async16(smem_u32(Ad + row*ASTR + kq),
                       g_xr + (size_t)(m0 + row)*DMODEL + k0 + kq);
            int n = n0 + row;
            const float* wrow = (n < NQK) ? (g_wqkr + (size_t)n*DMODEL)
                                          : (g_wvr + (size_t)(n-NQK)*DMODEL);
            cp_async16(smem_u32(Bd + row*ASTR + kq), wrow + k0 + kq);
        }
        cp_commit();
    };

    load_stage(0, 0);
    load_stage(1, 1);
    for (int kt = 0; kt < NKT; kt++) {
        if (kt < NKT - 1) cp_wait1(); else cp_wait0();
        __syncthreads();
        gemm_compute_tile(As + (kt&1)*TILE_FLOATS, Bs + (kt&1)*TILE_FLOATS,
                          warp_m, warp_n, lane, c);
        __syncthreads();
        if (kt + 2 < NKT) load_stage(kt + 2, kt & 1);
    }

    const int lq = lane >> 2;
    const int lc = (lane & 3) * 2;
#pragma unroll
    for (int mt = 0; mt < 4; mt++) {
#pragma unroll
        for (int rv = 0; rv < 2; rv++) {
            int m = m0 + warp_m + mt*16 + lq + rv*8;
            int bb = m / SEQ;
            int ss = m % SEQ;
#pragma unroll
            for (int nt = 0; nt < 4; nt++) {
                int nf = n0 + warp_n + nt*8 + lc;
                float v0 = c[mt][nt][rv*2+0];
                float v1 = c[mt][nt][rv*2+1];
                if (nf < NQK) {
                    v0 += bqk[nf];   v1 += bqk[nf+1];
                    v0 = (v0 > 0.f) ? (v0 + 1.f) : expf(v0);
                    v1 = (v1 > 0.f) ? (v1 + 1.f) : expf(v1);
                } else {
                    v0 += bv[nf-NQK]; v1 += bv[nf-NQK+1];
                }
                v0 = tf32v(v0); v1 = tf32v(v1);
                float* dst;
                if (nf < DMODEL) {
                    int h = nf / DHEAD, d = nf % DHEAD;
                    dst = g_q + (((size_t)(bb*NHEAD + h))*SEQ + ss)*DHEAD + d;
                } else if (nf < NQK) {
                    int nn = nf - DMODEL;
                    int h = nn / DHEAD, d = nn % DHEAD;
                    dst = g_k + (((size_t)(bb*NHEAD + h))*SEQ + ss)*DHEAD + d;
                } else {
                    int nn = nf - NQK;
                    int h = nn / DHEAD, d = nn % DHEAD;
                    dst = g_v + (((size_t)(bb*NHEAD + h))*SEQ + ss)*DHEAD + d;
                }
                *(float2*)dst = make_float2(v0, v1);
            }
        }
    }
}

// ---------------------------------------------------------------------------
// Kernel 2: fused chunk state + exclusive prefix, split dk & dv -> 64 blocks
// ---------------------------------------------------------------------------
#define CSK 32
#define CS2_TILE (CHUNK*CSK)               // 4096 floats
#define CS2_SMEM_BYTES (2*2*CS2_TILE*4)    // 65536

__global__ __launch_bounds__(256) void chunk_state_kernel()
{
    extern __shared__ float sm[];
    float* ks = sm;                         // [2][128][32]
    float* vs = sm + 2*CS2_TILE;            // [2][128][32]

    const int bh  = blockIdx.x;
    const int slk = blockIdx.y;             // dk slab
    const int slv = blockIdx.z;             // dv slab
    const int tid = threadIdx.x;
    const int dkl = tid >> 3;               // 0..31
    const int dvq = (tid & 7) * 4;          // 0..28

    const float* kp = g_k + (size_t)bh*SEQ*DHEAD + slk*CSK;
    const float* vp = g_v + (size_t)bh*SEQ*DHEAD + slv*CSK;

    auto load_stage = [&](int c, int st) {
        const float* kc = kp + (size_t)c*CHUNK*DHEAD;
        const float* vc = vp + (size_t)c*CHUNK*DHEAD;
        float* kd = ks + st*CS2_TILE;
        float* vd = vs + st*CS2_TILE;
#pragma unroll
        for (int i = 0; i < 4; i++) {
            int idx = tid + i*256;          // 0..1023
            int row = idx >> 3;
            int c4  = (idx & 7) * 4;
            cp_async16(smem_u32(kd + row*CSK + c4), kc + (size_t)row*DHEAD + c4);
            cp_async16(smem_u32(vd + row*CSK + c4), vc + (size_t)row*DHEAD + c4);
        }
        cp_commit();
    };

    float acc[4] = {0.f, 0.f, 0.f, 0.f};
    float zacc = 0.f;

    load_stage(0, 0);
    load_stage(1, 1);

    for (int c = 0; c < NCHUNK; c++) {
        float* kvout = g_kv_pre + ((size_t)(bh*NCHUNK + c))*(DHEAD*DHEAD)
                       + (slk*CSK + dkl)*DHEAD + slv*CSK + dvq;
        *(float4*)kvout = make_float4(acc[0], acc[1], acc[2], acc[3]);
        if (slv == 0 && (tid & 7) == 0)
            g_z_pre[(size_t)(bh*NCHUNK + c)*DHEAD + slk*CSK + dkl] = zacc;

        if (c < NCHUNK - 1) cp_wait1(); else cp_wait0();
        __syncthreads();

        const int st = c & 1;
        const float* kd = ks + st*CS2_TILE;
        const float* vd = vs + st*CS2_TILE;
#pragma unroll 8
        for (int s = 0; s < CHUNK; s++) {
            float kv = kd[s*CSK + dkl];
            zacc += kv;
            float4 v0 = *(const float4*)(vd + s*CSK + dvq);
            acc[0] += kv*v0.x; acc[1] += kv*v0.y;
            acc[2] += kv*v0.z; acc[3] += kv*v0.w;
        }
        __syncthreads();
        if (c + 2 < NCHUNK) load_stage(c + 2, st);
    }
}

// ---------------------------------------------------------------------------
// Kernel 4: tensor-core chunk readout with ldmatrix fragment loads
// ---------------------------------------------------------------------------
#define SQ_STR  68
#define SK_STR  68
#define SVT_STR 132
#define SKVT_STR 68
#define SS_STR  36
#define SQ_OFF   0
#define SK_OFF   (SQ_OFF + 128*SQ_STR)
#define SVT_OFF  (SK_OFF + 128*SK_STR)
#define SKVT_OFF (SVT_OFF + 72*SVT_STR)
#define SS_OFF   (SKVT_OFF + 72*SKVT_STR)
#define CO_SMEM_FLOATS (SS_OFF + 128*SS_STR)
#define CO_SMEM_BYTES (CO_SMEM_FLOATS*4)

__global__ __launch_bounds__(256) void chunk_out_tc_kernel()
{
    extern __shared__ float sm[];
    float* sq   = sm + SQ_OFF;
    float* sk   = sm + SK_OFF;
    float* svt  = sm + SVT_OFF;
    float* skvt = sm + SKVT_OFF;
    float* ss   = sm + SS_OFF;

    const int blk = blockIdx.x;
    const int bh = blk / NCHUNK;
    const int c  = blk % NCHUNK;
    const int tid = threadIdx.x;
    const int wid = tid >> 5;
    const int lane = tid & 31;
    const int lq = lane >> 2;
    const int lr = lane & 3;
    const int wm = wid * 16;

    const size_t base = ((size_t)bh*SEQ + (size_t)c*CHUNK)*DHEAD;

    {
        const float4* q4 = (const float4*)(g_q + base);
        const float4* k4 = (const float4*)(g_k + base);
#pragma unroll
        for (int i = 0; i < 8; i++) {
            int idx = tid + i*256;
            int row = idx >> 4;
            int c4  = (idx & 15) * 4;
            *(float4*)(sq + row*SQ_STR + c4) = q4[idx];
            *(float4*)(sk + row*SK_STR + c4) = k4[idx];
        }
    }
    {
        const float* vp = g_v + base;
        int t  = tid >> 1;
        int dh = (tid & 1) * 32;
#pragma unroll
        for (int i = 0; i < 8; i++) {
            float4 vv = *(const float4*)(vp + t*DHEAD + dh + i*4);
            svt[(dh + i*4 + 0)*SVT_STR + t] = vv.x;
            svt[(dh + i*4 + 1)*SVT_STR + t] = vv.y;
            svt[(dh + i*4 + 2)*SVT_STR + t] = vv.z;
            svt[(dh + i*4 + 3)*SVT_STR + t] = vv.w;
        }
        if (tid < 128) {
            svt[64*SVT_STR + tid] = 1.0f;
#pragma unroll
            for (int r = 65; r < 72; r++) svt[r*SVT_STR + tid] = 0.f;
        }
    }
    {
        const float* kvp = g_kv_pre + (size_t)blk*(DHEAD*DHEAD);
        int dk = tid >> 1;
        if (dk < 64) {
            int nh = (tid & 1) * 32;
#pragma unroll
            for (int i = 0; i < 8; i++) {
                float4 vv = *(const float4*)(kvp + dk*DHEAD + nh + i*4);
                skvt[(nh + i*4 + 0)*SKVT_STR + dk] = tf32v(vv.x);
                skvt[(nh + i*4 + 1)*SKVT_STR + dk] = tf32v(vv.y);
                skvt[(nh + i*4 + 2)*SKVT_STR + dk] = tf32v(vv.z);
                skvt[(nh + i*4 + 3)*SKVT_STR + dk] = tf32v(vv.w);
            }
        }
        if (tid < 64) {
            skvt[64*SKVT_STR + tid] = tf32v(g_z_pre[(size_t)blk*DHEAD + tid]);
#pragma unroll
            for (int r = 65; r < 72; r++) skvt[r*SKVT_STR + tid] = 0.f;
        }
    }
    __syncthreads();

    // ldmatrix addressing helpers (per thread)
    const int ar   = lane & 15;             // fragment row within 16
    const int acol = ((lane >> 4) & 1) * 4; // k offset 0/4
    const int bg   = lane >> 3;
    const int bnt  = (bg >> 1) * 8 + (lane & 7);  // row within nt-pair block
    const int bcol = (bg & 1) * 4;
    const uint32_t sqb   = smem_u32(sq);
    const uint32_t skb   = smem_u32(sk);
    const uint32_t svtb  = smem_u32(svt);
    const uint32_t skvtb = smem_u32(skvt);
    const uint32_t ssb   = smem_u32(ss);

    // hoisted Q fragments (reused in all QK^T blocks and the inter-chunk GEMM)
    uint32_t qf[8][4];
#pragma unroll
    for (int ksi = 0; ksi < 8; ksi++)
        ldsm_x4(qf[ksi][0], qf[ksi][1], qf[ksi][2], qf[ksi][3],
                sqb + (uint32_t)(((wm + ar)*SQ_STR + ksi*8 + acol)*4));

    float acc[9][4];
#pragma unroll
    for (int nt = 0; nt < 9; nt++)
#pragma unroll
        for (int i = 0; i < 4; i++) acc[nt][i] = 0.f;

    const int r0 = wm + lq;

    for (int j = 0; j < 4; j++) {
        const int j32 = j * 32;
        const bool live = (j32 <= wm + 15);

        if (live) {
            float sfrag[4][4];
#pragma unroll
            for (int nt = 0; nt < 4; nt++)
#pragma unroll
                for (int i = 0; i < 4; i++) sfrag[nt][i] = 0.f;
#pragma unroll
            for (int ksi = 0; ksi < 8; ksi++) {
                uint32_t bf[4][2];
#pragma unroll
                for (int p = 0; p < 2; p++)
                    ldsm_x4(bf[2*p][0], bf[2*p][1], bf[2*p+1][0], bf[2*p+1][1],
                            skb + (uint32_t)(((j32 + bnt + p*16)*SK_STR + ksi*8 + bcol)*4));
#pragma unroll
                for (int nt = 0; nt < 4; nt++)
                    mma_tf32(sfrag[nt], qf[ksi][0], qf[ksi][1], qf[ksi][2], qf[ksi][3],
                             bf[nt][0], bf[nt][1]);
            }
            // mask + tf32 round + store to ss
#pragma unroll
            for (int nt = 0; nt < 4; nt++) {
                int colg = j32 + nt*8 + 2*lr;
                int cl   = nt*8 + 2*lr;
                float v00 = (colg   <= r0) ? sfrag[nt][0] : 0.f;
                float v01 = (colg+1 <= r0) ? sfrag[nt][1] : 0.f;
                float v10 = (colg   <= r0+8) ? sfrag[nt][2] : 0.f;
                float v11 = (colg+1 <= r0+8) ? sfrag[nt][3] : 0.f;
                *(float2*)(ss + r0*SS_STR + cl)     = make_float2(tf32v(v00), tf32v(v01));
                *(float2*)(ss + (r0+8)*SS_STR + cl) = make_float2(tf32v(v10), tf32v(v11));
            }
        } else {
#pragma unroll
            for (int nt = 0; nt < 4; nt++) {
                int cl = nt*8 + 2*lr;
                *(float2*)(ss + r0*SS_STR + cl)     = make_float2(0.f, 0.f);
                *(float2*)(ss + (r0+8)*SS_STR + cl) = make_float2(0.f, 0.f);
            }
        }
        __syncthreads();

        if (live) {
#pragma unroll
            for (int ksi = 0; ksi < 4; ksi++) {
                uint32_t a0, a1, a2, a3;
                ldsm_x4(a0, a1, a2, a3,
                        ssb + (uint32_t)(((wm + ar)*SS_STR + ksi*8 + acol)*4));
                uint32_t bf[8][2];
#pragma unroll
                for (int p = 0; p < 4; p++)
                    ldsm_x4(bf[2*p][0], bf[2*p][1], bf[2*p+1][0], bf[2*p+1][1],
                            svtb + (uint32_t)(((bnt + p*16)*SVT_STR + j32 + ksi*8 + bcol)*4));
                uint32_t b80, b81;
                ldsm_x2(b80, b81,
                        svtb + (uint32_t)(((64 + (lane & 7))*SVT_STR + j32 + ksi*8 + ((lane>>3)&1)*4)*4));
#pragma unroll
                for (int nt = 0; nt < 8; nt++)
                    mma_tf32(acc[nt], a0, a1, a2, a3, bf[nt][0], bf[nt][1]);
                mma_tf32(acc[8], a0, a1, a2, a3, b80, b81);
            }
        }
        __syncthreads();
    }

    // inter-chunk: Q @ [KV_pre | z_pre]
#pragma unroll
    for (int ksi = 0; ksi < 8; ksi++) {
        uint32_t bf[8][2];
#pragma unroll
        for (int p = 0; p < 4; p++)
            ldsm_x4(bf[2*p][0], bf[2*p][1], bf[2*p+1][0], bf[2*p+1][1],
                    skvtb + (uint32_t)(((bnt + p*16)*SKVT_STR + ksi*8 + bcol)*4));
        uint32_t b80, b81;
        ldsm_x2(b80, b81,
                skvtb + (uint32_t)(((64 + (lane & 7))*SKVT_STR + ksi*8 + ((lane>>3)&1)*4)*4));
#pragma unroll
        for (int nt = 0; nt < 8; nt++)
            mma_tf32(acc[nt], qf[ksi][0], qf[ksi][1], qf[ksi][2], qf[ksi][3],
                     bf[nt][0], bf[nt][1]);
        mma_tf32(acc[8], qf[ksi][0], qf[ksi][1], qf[ksi][2], qf[ksi][3], b80, b81);
    }

    float nu0 = __shfl_sync(0xffffffffu, acc[8][0], lane & 28);
    float nu1 = __shfl_sync(0xffffffffu, acc[8][2], lane & 28);
    float inv0 = 1.f / nu0;
    float inv1 = 1.f / nu1;

    const int b = bh / NHEAD, h = bh % NHEAD;
    const int s0 = c*CHUNK + r0;
    float* out0 = g_ctx + ((size_t)(b*SEQ + s0))*DMODEL + h*DHEAD;
    float* out1 = g_ctx + ((size_t)(b*SEQ + s0 + 8))*DMODEL + h*DHEAD;
#pragma unroll
    for (int nt = 0; nt < 8; nt++) {
        int cl = nt*8 + 2*lr;
        *(float2*)(out0 + cl) = make_float2(tf32v(acc[nt][0]*inv0), tf32v(acc[nt][1]*inv0));
        *(float2*)(out1 + cl) = make_float2(tf32v(acc[nt][2]*inv1), tf32v(acc[nt][3]*inv1));
    }
}

// ---------------------------------------------------------------------------
// Kernel 5: output projection (tensor cores)
// ---------------------------------------------------------------------------
__global__ __launch_bounds__(256, 2) void out_tc_gemm(
    const float* __restrict__ bo, float* __restrict__ out)
{
    extern __shared__ float smem[];
    float* As = smem;
    float* Bs = smem + 2*TILE_FLOATS;

    const int n0 = blockIdx.x * 128;
    const int m0 = blockIdx.y * 128;
    const int tid = threadIdx.x;
    const int wid = tid >> 5;
    const int lane = tid & 31;
    const int warp_m = (wid & 1) * 64;
    const int warp_n = (wid >> 1) * 32;

    float c[4][4][4];
#pragma unroll
    for (int mt = 0; mt < 4; mt++)
#pragma unroll
        for (int nt = 0; nt < 4; nt++)
#pragma unroll
            for (int i = 0; i < 4; i++) c[mt][nt][i] = 0.f;

    auto load_stage = [&](int kt, int stage) {
        const int k0 = kt * KT;
        float* Ad = As + stage * TILE_FLOATS;
        float* Bd = Bs + stage * TILE_FLOATS;
#pragma unroll
        for (int i = 0; i < 4; i++) {
            int idx = tid + i*256;
            int row = idx >> 3;
            int kq  = (idx & 7) * 4;
            cp_async16(smem_u32(Ad + row*ASTR + kq),
                       g_ctx + (size_t)(m0 + row)*DMODEL + k0 + kq);
            cp_async16(smem_u32(Bd + row*ASTR + kq),
                       g_wor + (size_t)(n0 + row)*DMODEL + k0 + kq);
        }
        cp_commit();
    };

    load_stage(0, 0);
    load_stage(1, 1);
    for (int kt = 0; kt < NKT; kt++) {
        if (kt < NKT - 1) cp_wait1(); else cp_wait0();
        __syncthreads();
        gemm_compute_tile(As + (kt&1)*TILE_FLOATS, Bs + (kt&1)*TILE_FLOATS,
                          warp_m, warp_n, lane, c);
        __syncthreads();
        if (kt + 2 < NKT) load_stage(kt + 2, kt & 1);
    }

    const int lq = lane >> 2;
    const int lc = (lane & 3) * 2;
#pragma unroll
    for (int mt = 0; mt < 4; mt++) {
#pragma unroll
        for (int rv = 0; rv < 2; rv++) {
            int m = m0 + warp_m + mt*16 + lq + rv*8;
#pragma unroll
            for (int nt = 0; nt < 4; nt++) {
                int nf = n0 + warp_n + nt*8 + lc;
                float v0 = c[mt][nt][rv*2+0] + bo[nf];
                float v1 = c[mt][nt][rv*2+1] + bo[nf+1];
                *(float2*)(out + (size_t)m*DMODEL + nf) = make_float2(v0, v1);
            }
        }
    }
}

// ---------------------------------------------------------------------------
extern "C" void kernel_launch(void* const* d_in, const int* in_sizes, int n_in,
                              void* d_out, int out_size)
{
    const float* x     = (const float*)d_in[0];
    const float* Wqk_w = (const float*)d_in[1];
    const float* Wqk_b = (const float*)d_in[2];
    const float* Wv_w  = (const float*)d_in[3];
    const float* Wv_b  = (const float*)d_in[4];
    const float* Wo_w  = (const float*)d_in[5];
    const float* Wo_b  = (const float*)d_in[6];
    float* out = (float*)d_out;

    cudaFuncSetAttribute(qkv_tc_gemm,
        cudaFuncAttributeMaxDynamicSharedMemorySize, GEMM_SMEM_BYTES);
    cudaFuncSetAttribute(out_tc_gemm,
        cudaFuncAttributeMaxDynamicSharedMemorySize, GEMM_SMEM_BYTES);
    cudaFuncSetAttribute(chunk_out_tc_kernel,
        cudaFuncAttributeMaxDynamicSharedMemorySize, CO_SMEM_BYTES);
    cudaFuncSetAttribute(chunk_state_kernel,
        cudaFuncAttributeMaxDynamicSharedMemorySize, CS2_SMEM_BYTES);

    round_kernel<<<N4_TOT/256, 256>>>((const float4*)x, (const float4*)Wqk_w,
                                      (const float4*)Wv_w, (const float4*)Wo_w);

    dim3 g1(NFEAT/128, NTOK/128);
    qkv_tc_gemm<<<g1, 256, GEMM_SMEM_BYTES>>>(Wqk_b, Wv_b);

    dim3 g2(BHEADS, 2, 2);
    chunk_state_kernel<<<g2, 256, CS2_SMEM_BYTES>>>();

    chunk_out_tc_kernel<<<BHEADS*NCHUNK, 256, CO_SMEM_BYTES>>>();

    dim3 g5(DMODEL/128, NTOK/128);
    out_tc_gemm<<<g5, 256, GEMM_SMEM_BYTES>>>(Wo_b, out);
}

// round 6
// speedup vs baseline: 3.2462x; 1.0314x over previous
#include <cuda_runtime.h>
#include <cuda_bf16.h>
#include <math.h>
#include <stdint.h>

// Problem constants
#define BATCH 2
#define SEQ   2048
#define DMODEL 512
#define NHEAD 8
#define DHEAD 64
#define NTOK  (BATCH*SEQ)          // 4096
#define NQK   1024
#define NFEAT 1536
#define CHUNK 128
#define NCHUNK (SEQ/CHUNK)         // 16
#define BHEADS (BATCH*NHEAD)       // 16

// Scratch (device globals)
__device__ float g_q[BHEADS*SEQ*DHEAD];
__device__ float g_k[BHEADS*SEQ*DHEAD];
__device__ float g_v[BHEADS*SEQ*DHEAD];
__device__ float g_ctx[NTOK*DMODEL];
__device__ float g_kv_pre[BHEADS*NCHUNK*DHEAD*DHEAD];
__device__ float g_z_pre[BHEADS*NCHUNK*DHEAD];
// pre-rounded (tf32-valued fp32) operands
__device__ float g_xr[NTOK*DMODEL];
__device__ float g_wqkr[NQK*DMODEL];
__device__ float g_wvr[DMODEL*DMODEL];
__device__ float g_wor[DMODEL*DMODEL];

// ---------------------------------------------------------------------------
// Helpers
// ---------------------------------------------------------------------------
__device__ __forceinline__ uint32_t smem_u32(const void* p) {
    return (uint32_t)__cvta_generic_to_shared(p);
}
__device__ __forceinline__ void cp_async16(uint32_t s, const void* g) {
    asm volatile("cp.async.cg.shared.global [%0], [%1], 16;\n" :: "r"(s), "l"(g));
}
__device__ __forceinline__ void cp_commit() { asm volatile("cp.async.commit_group;\n"); }
__device__ __forceinline__ void cp_wait1()  { asm volatile("cp.async.wait_group 1;\n"); }
__device__ __forceinline__ void cp_wait0()  { asm volatile("cp.async.wait_group 0;\n"); }
__device__ __forceinline__ uint32_t f2tf(float f) {
    uint32_t r;
    asm("cvt.rna.tf32.f32 %0, %1;" : "=r"(r) : "f"(f));
    return r;
}
__device__ __forceinline__ float tf32v(float f) { return __uint_as_float(f2tf(f)); }
__device__ __forceinline__ void mma_tf32(float c[4],
    uint32_t a0, uint32_t a1, uint32_t a2, uint32_t a3,
    uint32_t b0, uint32_t b1)
{
    asm volatile(
        "mma.sync.aligned.m16n8k8.row.col.f32.tf32.tf32.f32 "
        "{%0,%1,%2,%3}, {%4,%5,%6,%7}, {%8,%9}, {%0,%1,%2,%3};"
        : "+f"(c[0]), "+f"(c[1]), "+f"(c[2]), "+f"(c[3])
        : "r"(a0), "r"(a1), "r"(a2), "r"(a3), "r"(b0), "r"(b1));
}
__device__ __forceinline__ void ldsm_x4(uint32_t& r0, uint32_t& r1,
                                        uint32_t& r2, uint32_t& r3, uint32_t addr)
{
    asm volatile("ldmatrix.sync.aligned.m8n8.x4.shared.b16 {%0,%1,%2,%3}, [%4];"
                 : "=r"(r0), "=r"(r1), "=r"(r2), "=r"(r3) : "r"(addr));
}
#define B32(x) __float_as_uint(x)

// ---------------------------------------------------------------------------
// Kernel 0: round inputs to tf32-valued fp32
// ---------------------------------------------------------------------------
#define N4_X   (NTOK*DMODEL/4)
#define N4_WQK (NQK*DMODEL/4)
#define N4_WV  (DMODEL*DMODEL/4)
#define N4_WO  (DMODEL*DMODEL/4)
#define N4_TOT (N4_X+N4_WQK+N4_WV+N4_WO)

__global__ __launch_bounds__(256) void round_kernel(
    const float4* __restrict__ x, const float4* __restrict__ wqk,
    const float4* __restrict__ wv, const float4* __restrict__ wo)
{
    int idx = blockIdx.x * 256 + threadIdx.x;
    const float4* src; float4* dst; int off;
    if (idx < N4_X)                         { src = x;   dst = (float4*)g_xr;   off = idx; }
    else if (idx < N4_X+N4_WQK)             { src = wqk; dst = (float4*)g_wqkr; off = idx - N4_X; }
    else if (idx < N4_X+N4_WQK+N4_WV)       { src = wv;  dst = (float4*)g_wvr;  off = idx - N4_X - N4_WQK; }
    else                                    { src = wo;  dst = (float4*)g_wor;  off = idx - N4_X - N4_WQK - N4_WV; }
    float4 v = src[off];
    v.x = tf32v(v.x); v.y = tf32v(v.y); v.z = tf32v(v.z); v.w = tf32v(v.w);
    dst[off] = v;
}

// ---------------------------------------------------------------------------
// TF32 GEMM: 128x128x32 tiles, 8 warps of 64x32, 3-stage pipeline,
// ldmatrix fragment loads, 1 barrier per k-tile.
// ---------------------------------------------------------------------------
#define KT 32
#define NKT (DMODEL/KT)
#define ASTR 36
#define TILE_FLOATS (128*ASTR)
#define NSTAGE 3
#define GEMM_SMEM_BYTES (NSTAGE*2*TILE_FLOATS*4)   // 110592

__device__ __forceinline__ void gemm_compute_tile(
    const float* __restrict__ A, const float* __restrict__ B,
    int warp_m, int warp_n, int lane, float c[4][4][4])
{
    const uint32_t Ab = smem_u32(A);
    const uint32_t Bb = smem_u32(B);
    const int arow = warp_m + (lane & 15);
    const int acol = ((lane >> 4) & 1) * 4;
    const int bg   = lane >> 3;
    const int brow = warp_n + (bg >> 1) * 8 + (lane & 7);
    const int bcol = (bg & 1) * 4;
#pragma unroll
    for (int kk = 0; kk < KT; kk += 8) {
        uint32_t af[4][4];
        uint32_t bf[4][2];
#pragma unroll
        for (int mt = 0; mt < 4; mt++)
            ldsm_x4(af[mt][0], af[mt][1], af[mt][2], af[mt][3],
                    Ab + (uint32_t)(((arow + mt*16)*ASTR + kk + acol)*4));
#pragma unroll
        for (int p = 0; p < 2; p++)
            ldsm_x4(bf[2*p][0], bf[2*p][1], bf[2*p+1][0], bf[2*p+1][1],
                    Bb + (uint32_t)(((brow + p*16)*ASTR + kk + bcol)*4));
#pragma unroll
        for (int mt = 0; mt < 4; mt++)
#pragma unroll
            for (int nt = 0; nt < 4; nt++)
                mma_tf32(c[mt][nt], af[mt][0], af[mt][1], af[mt][2], af[mt][3],
                         bf[nt][0], bf[nt][1]);
    }
}

// ---------------------------------------------------------------------------
// Kernel 1: fused QKV GEMM (tensor cores)
// ---------------------------------------------------------------------------
__global__ __launch_bounds__(256, 2) void qkv_tc_gemm(
    const float* __restrict__ bqk, const float* __restrict__ bv)
{
    extern __shared__ float smem[];
    float* As = smem;
    float* Bs = smem + NSTAGE*TILE_FLOATS;

    const int n0 = blockIdx.x * 128;
    const int m0 = blockIdx.y * 128;
    const int tid = threadIdx.x;
    const int wid = tid >> 5;
    const int lane = tid & 31;
    const int warp_m = (wid & 1) * 64;
    const int warp_n = (wid >> 1) * 32;

    float c[4][4][4];
#pragma unroll
    for (int mt = 0; mt < 4; mt++)
#pragma unroll
        for (int nt = 0; nt < 4; nt++)
#pragma unroll
            for (int i = 0; i < 4; i++) c[mt][nt][i] = 0.f;

    auto load_stage = [&](int kt, int stage) {
        const int k0 = kt * KT;
        float* Ad = As + stage * TILE_FLOATS;
        float* Bd = Bs + stage * TILE_FLOATS;
#pragma unroll
        for (int i = 0; i < 4; i++) {
            int idx = tid + i*256;
            int row = idx >> 3;
            int kq  = (idx & 7) * 4;
            cp_async16(smem_u32(Ad + row*ASTR + kq),
                       g_xr + (size_t)(m0 + row)*DMODEL + k0 + kq);
            int n = n0 + row;
            const float* wrow = (n < NQK) ? (g_wqkr + (size_t)n*DMODEL)
                                          : (g_wvr + (size_t)(n-NQK)*DMODEL);
            cp_async16(smem_u32(Bd + row*ASTR + kq), wrow + k0 + kq);
        }
        cp_commit();
    };

    load_stage(0, 0);
    load_stage(1, 1);
    for (int kt = 0; kt < NKT; kt++) {
        if (kt < NKT - 1) cp_wait1(); else cp_wait0();
        __syncthreads();
        int st = kt % NSTAGE;
        gemm_compute_tile(As + st*TILE_FLOATS, Bs + st*TILE_FLOATS,
                          warp_m, warp_n, lane, c);
        if (kt + 2 < NKT) load_stage(kt + 2, (kt + 2) % NSTAGE);
    }

    const int lq = lane >> 2;
    const int lc = (lane & 3) * 2;
#pragma unroll
    for (int mt = 0; mt < 4; mt++) {
#pragma unroll
        for (int rv = 0; rv < 2; rv++) {
            int m = m0 + warp_m + mt*16 + lq + rv*8;
            int bb = m / SEQ;
            int ss = m % SEQ;
#pragma unroll
            for (int nt = 0; nt < 4; nt++) {
                int nf = n0 + warp_n + nt*8 + lc;
                float v0 = c[mt][nt][rv*2+0];
                float v1 = c[mt][nt][rv*2+1];
                if (nf < NQK) {
                    v0 += bqk[nf];   v1 += bqk[nf+1];
                    v0 = (v0 > 0.f) ? (v0 + 1.f) : expf(v0);
                    v1 = (v1 > 0.f) ? (v1 + 1.f) : expf(v1);
                } else {
                    v0 += bv[nf-NQK]; v1 += bv[nf-NQK+1];
                }
                v0 = tf32v(v0); v1 = tf32v(v1);
                float* dst;
                if (nf < DMODEL) {
                    int h = nf / DHEAD, d = nf % DHEAD;
                    dst = g_q + (((size_t)(bb*NHEAD + h))*SEQ + ss)*DHEAD + d;
                } else if (nf < NQK) {
                    int nn = nf - DMODEL;
                    int h = nn / DHEAD, d = nn % DHEAD;
                    dst = g_k + (((size_t)(bb*NHEAD + h))*SEQ + ss)*DHEAD + d;
                } else {
                    int nn = nf - NQK;
                    int h = nn / DHEAD, d = nn % DHEAD;
                    dst = g_v + (((size_t)(bb*NHEAD + h))*SEQ + ss)*DHEAD + d;
                }
                *(float2*)dst = make_float2(v0, v1);
            }
        }
    }
}

// ---------------------------------------------------------------------------
// Kernel 2: fused chunk state + exclusive prefix, split dk & dv -> 64 blocks
// ---------------------------------------------------------------------------
#define CSK 32
#define CS2_TILE (CHUNK*CSK)               // 4096 floats
#define CS2_SMEM_BYTES (2*2*CS2_TILE*4)    // 65536

__global__ __launch_bounds__(256) void chunk_state_kernel()
{
    extern __shared__ float sm[];
    float* ks = sm;                         // [2][128][32]
    float* vs = sm + 2*CS2_TILE;            // [2][128][32]

    const int bh  = blockIdx.x;
    const int slk = blockIdx.y;             // dk slab
    const int slv = blockIdx.z;             // dv slab
    const int tid = threadIdx.x;
    const int dkl = tid >> 3;               // 0..31
    const int dvq = (tid & 7) * 4;          // 0..28

    const float* kp = g_k + (size_t)bh*SEQ*DHEAD + slk*CSK;
    const float* vp = g_v + (size_t)bh*SEQ*DHEAD + slv*CSK;

    auto load_stage = [&](int c, int st) {
        const float* kc = kp + (size_t)c*CHUNK*DHEAD;
        const float* vc = vp + (size_t)c*CHUNK*DHEAD;
        float* kd = ks + st*CS2_TILE;
        float* vd = vs + st*CS2_TILE;
#pragma unroll
        for (int i = 0; i < 4; i++) {
            int idx = tid + i*256;          // 0..1023
            int row = idx >> 3;
            int c4  = (idx & 7) * 4;
            cp_async16(smem_u32(kd + row*CSK + c4), kc + (size_t)row*DHEAD + c4);
            cp_async16(smem_u32(vd + row*CSK + c4), vc + (size_t)row*DHEAD + c4);
        }
        cp_commit();
    };

    float acc[4] = {0.f, 0.f, 0.f, 0.f};
    float zacc = 0.f;

    load_stage(0, 0);
    load_stage(1, 1);

    for (int c = 0; c < NCHUNK; c++) {
        float* kvout = g_kv_pre + ((size_t)(bh*NCHUNK + c))*(DHEAD*DHEAD)
                       + (slk*CSK + dkl)*DHEAD + slv*CSK + dvq;
        *(float4*)kvout = make_float4(acc[0], acc[1], acc[2], acc[3]);
        if (slv == 0 && (tid & 7) == 0)
            g_z_pre[(size_t)(bh*NCHUNK + c)*DHEAD + slk*CSK + dkl] = zacc;

        if (c < NCHUNK - 1) cp_wait1(); else cp_wait0();
        __syncthreads();

        const int st = c & 1;
        const float* kd = ks + st*CS2_TILE;
        const float* vd = vs + st*CS2_TILE;
#pragma unroll 8
        for (int s = 0; s < CHUNK; s++) {
            float kv = kd[s*CSK + dkl];
            zacc += kv;
            float4 v0 = *(const float4*)(vd + s*CSK + dvq);
            acc[0] += kv*v0.x; acc[1] += kv*v0.y;
            acc[2] += kv*v0.z; acc[3] += kv*v0.w;
        }
        __syncthreads();
        if (c + 2 < NCHUNK) load_stage(c + 2, st);
    }
}

// ---------------------------------------------------------------------------
// Kernel 4: tensor-core chunk readout, warp-independent causal blocks.
// Q fragments loaded direct from gmem; nu via shuffle reduction.
// smem: sk[128*68] svt[64*132] skvt[64*68] ss[128*36] sz[64]  = 102.3 KB
// ---------------------------------------------------------------------------
#define SK_STR  68
#define SVT_STR 132
#define SKVT_STR 68
#define SS_STR  36
#define SK_OFF   0
#define SVT_OFF  (SK_OFF + 128*SK_STR)          // 8704
#define SKVT_OFF (SVT_OFF + 64*SVT_STR)         // 17152
#define SS_OFF   (SKVT_OFF + 64*SKVT_STR)       // 21504
#define SZ_OFF   (SS_OFF + 128*SS_STR)          // 26112
#define CO_SMEM_FLOATS (SZ_OFF + 64)            // 26176
#define CO_SMEM_BYTES (CO_SMEM_FLOATS*4)        // 104704

__global__ __launch_bounds__(256, 2) void chunk_out_tc_kernel()
{
    extern __shared__ float sm[];
    float* sk   = sm + SK_OFF;
    float* svt  = sm + SVT_OFF;
    float* skvt = sm + SKVT_OFF;
    float* ss   = sm + SS_OFF;
    float* sz   = sm + SZ_OFF;

    const int blk = blockIdx.x;
    const int bh = blk / NCHUNK;
    const int c  = blk % NCHUNK;
    const int tid = threadIdx.x;
    const int wid = tid >> 5;
    const int lane = tid & 31;
    const int lq = lane >> 2;
    const int lr = lane & 3;
    const int wm = wid * 16;

    const size_t base = ((size_t)bh*SEQ + (size_t)c*CHUNK)*DHEAD;

    // Q fragments direct from gmem (issued first for latency overlap)
    const float* qp = g_q + base;
    uint32_t qf[8][4];
#pragma unroll
    for (int ksi = 0; ksi < 8; ksi++) {
        qf[ksi][0] = B32(qp[(wm + lq)*DHEAD + ksi*8 + lr]);
        qf[ksi][1] = B32(qp[(wm + lq + 8)*DHEAD + ksi*8 + lr]);
        qf[ksi][2] = B32(qp[(wm + lq)*DHEAD + ksi*8 + lr + 4]);
        qf[ksi][3] = B32(qp[(wm + lq + 8)*DHEAD + ksi*8 + lr + 4]);
    }

    // --- K rows into smem ---
    {
        const float4* k4 = (const float4*)(g_k + base);
#pragma unroll
        for (int i = 0; i < 8; i++) {
            int idx = tid + i*256;
            int row = idx >> 4;
            int c4  = (idx & 15) * 4;
            *(float4*)(sk + row*SK_STR + c4) = k4[idx];
        }
    }
    // --- V transposed: svt[d][t] = v[t][d], 64 rows ---
    {
        const float* vp = g_v + base;
        int t  = tid >> 1;
        int dh = (tid & 1) * 32;
#pragma unroll
        for (int i = 0; i < 8; i++) {
            float4 vv = *(const float4*)(vp + t*DHEAD + dh + i*4);
            svt[(dh + i*4 + 0)*SVT_STR + t] = vv.x;
            svt[(dh + i*4 + 1)*SVT_STR + t] = vv.y;
            svt[(dh + i*4 + 2)*SVT_STR + t] = vv.z;
            svt[(dh + i*4 + 3)*SVT_STR + t] = vv.w;
        }
    }
    // --- kv_pre transposed: skvt[n][dk] = kv_pre[dk][n], 64 rows ---
    {
        const float* kvp = g_kv_pre + (size_t)blk*(DHEAD*DHEAD);
        int dk = tid >> 1;
        if (dk < 64) {
            int nh = (tid & 1) * 32;
#pragma unroll
            for (int i = 0; i < 8; i++) {
                float4 vv = *(const float4*)(kvp + dk*DHEAD + nh + i*4);
                skvt[(nh + i*4 + 0)*SKVT_STR + dk] = tf32v(vv.x);
                skvt[(nh + i*4 + 1)*SKVT_STR + dk] = tf32v(vv.y);
                skvt[(nh + i*4 + 2)*SKVT_STR + dk] = tf32v(vv.z);
                skvt[(nh + i*4 + 3)*SKVT_STR + dk] = tf32v(vv.w);
            }
        }
        if (tid < 64) sz[tid] = tf32v(g_z_pre[(size_t)blk*DHEAD + tid]);
    }
    __syncthreads();

    // ldmatrix addressing (per thread)
    const int ar   = lane & 15;
    const int acol = ((lane >> 4) & 1) * 4;
    const int bg   = lane >> 3;
    const int bnt  = (bg >> 1) * 8 + (lane & 7);
    const int bcol = (bg & 1) * 4;
    const uint32_t skb   = smem_u32(sk);
    const uint32_t svtb  = smem_u32(svt);
    const uint32_t skvtb = smem_u32(skvt);
    const uint32_t ssb   = smem_u32(ss);

    float acc[8][4];
#pragma unroll
    for (int nt = 0; nt < 8; nt++)
#pragma unroll
        for (int i = 0; i < 4; i++) acc[nt][i] = 0.f;

    const int r0 = wm + lq;
    float pnu0 = 0.f, pnu1 = 0.f;

    // --- causal key-column blocks (warp-independent; no block barriers) ---
    for (int j = 0; j <= (wm + 15) / 32; j++) {
        const int j32 = j * 32;

        float sfrag[4][4];
#pragma unroll
        for (int nt = 0; nt < 4; nt++)
#pragma unroll
            for (int i = 0; i < 4; i++) sfrag[nt][i] = 0.f;
#pragma unroll
        for (int ksi = 0; ksi < 8; ksi++) {
            uint32_t bf[4][2];
#pragma unroll
            for (int p = 0; p < 2; p++)
                ldsm_x4(bf[2*p][0], bf[2*p][1], bf[2*p+1][0], bf[2*p+1][1],
                        skb + (uint32_t)(((j32 + bnt + p*16)*SK_STR + ksi*8 + bcol)*4));
#pragma unroll
            for (int nt = 0; nt < 4; nt++)
                mma_tf32(sfrag[nt], qf[ksi][0], qf[ksi][1], qf[ksi][2], qf[ksi][3],
                         bf[nt][0], bf[nt][1]);
        }
        // mask + tf32 round + nu partial + store to warp-private ss rows
#pragma unroll
        for (int nt = 0; nt < 4; nt++) {
            int colg = j32 + nt*8 + 2*lr;
            int cl   = nt*8 + 2*lr;
            float v00 = tf32v((colg   <= r0)   ? sfrag[nt][0] : 0.f);
            float v01 = tf32v((colg+1 <= r0)   ? sfrag[nt][1] : 0.f);
            float v10 = tf32v((colg   <= r0+8) ? sfrag[nt][2] : 0.f);
            float v11 = tf32v((colg+1 <= r0+8) ? sfrag[nt][3] : 0.f);
            pnu0 += v00 + v01;
            pnu1 += v10 + v11;
            *(float2*)(ss + r0*SS_STR + cl)     = make_float2(v00, v01);
            *(float2*)(ss + (r0+8)*SS_STR + cl) = make_float2(v10, v11);
        }
        __syncwarp();

        // S-block @ V-block
#pragma unroll
        for (int ksi = 0; ksi < 4; ksi++) {
            uint32_t a0, a1, a2, a3;
            ldsm_x4(a0, a1, a2, a3,
                    ssb + (uint32_t)(((wm + ar)*SS_STR + ksi*8 + acol)*4));
            uint32_t bf[8][2];
#pragma unroll
            for (int p = 0; p < 4; p++)
                ldsm_x4(bf[2*p][0], bf[2*p][1], bf[2*p+1][0], bf[2*p+1][1],
                        svtb + (uint32_t)(((bnt + p*16)*SVT_STR + j32 + ksi*8 + bcol)*4));
#pragma unroll
            for (int nt = 0; nt < 8; nt++)
                mma_tf32(acc[nt], a0, a1, a2, a3, bf[nt][0], bf[nt][1]);
        }
        __syncwarp();
    }

    // --- inter-chunk: Q @ KV_pre, and nu += q . z_pre ---
#pragma unroll
    for (int ksi = 0; ksi < 8; ksi++) {
        uint32_t bf[8][2];
#pragma unroll
        for (int p = 0; p < 4; p++)
            ldsm_x4(bf[2*p][0], bf[2*p][1], bf[2*p+1][0], bf[2*p+1][1],
                    skvtb + (uint32_t)(((bnt + p*16)*SKVT_STR + ksi*8 + bcol)*4));
#pragma unroll
        for (int nt = 0; nt < 8; nt++)
            mma_tf32(acc[nt], qf[ksi][0], qf[ksi][1], qf[ksi][2], qf[ksi][3],
                     bf[nt][0], bf[nt][1]);
        float z0 = sz[ksi*8 + lr];
        float z1 = sz[ksi*8 + 4 + lr];
        pnu0 += __uint_as_float(qf[ksi][0])*z0 + __uint_as_float(qf[ksi][2])*z1;
        pnu1 += __uint_as_float(qf[ksi][1])*z0 + __uint_as_float(qf[ksi][3])*z1;
    }

    // reduce nu over the 4 lanes sharing a row
    pnu0 += __shfl_xor_sync(0xffffffffu, pnu0, 1);
    pnu0 += __shfl_xor_sync(0xffffffffu, pnu0, 2);
    pnu1 += __shfl_xor_sync(0xffffffffu, pnu1, 1);
    pnu1 += __shfl_xor_sync(0xffffffffu, pnu1, 2);
    float inv0 = 1.f / pnu0;
    float inv1 = 1.f / pnu1;

    const int b = bh / NHEAD, h = bh % NHEAD;
    const int s0 = c*CHUNK + r0;
    float* out0 = g_ctx + ((size_t)(b*SEQ + s0))*DMODEL + h*DHEAD;
    float* out1 = g_ctx + ((size_t)(b*SEQ + s0 + 8))*DMODEL + h*DHEAD;
#pragma unroll
    for (int nt = 0; nt < 8; nt++) {
        int cl = nt*8 + 2*lr;
        *(float2*)(out0 + cl) = make_float2(tf32v(acc[nt][0]*inv0), tf32v(acc[nt][1]*inv0));
        *(float2*)(out1 + cl) = make_float2(tf32v(acc[nt][2]*inv1), tf32v(acc[nt][3]*inv1));
    }
}

// ---------------------------------------------------------------------------
// Kernel 5: output projection (tensor cores)
// ---------------------------------------------------------------------------
__global__ __launch_bounds__(256, 2) void out_tc_gemm(
    const float* __restrict__ bo, float* __restrict__ out)
{
    extern __shared__ float smem[];
    float* As = smem;
    float* Bs = smem + NSTAGE*TILE_FLOATS;

    const int n0 = blockIdx.x * 128;
    const int m0 = blockIdx.y * 128;
    const int tid = threadIdx.x;
    const int wid = tid >> 5;
    const int lane = tid & 31;
    const int warp_m = (wid & 1) * 64;
    const int warp_n = (wid >> 1) * 32;

    float c[4][4][4];
#pragma unroll
    for (int mt = 0; mt < 4; mt++)
#pragma unroll
        for (int nt = 0; nt < 4; nt++)
#pragma unroll
            for (int i = 0; i < 4; i++) c[mt][nt][i] = 0.f;

    auto load_stage = [&](int kt, int stage) {
        const int k0 = kt * KT;
        float* Ad = As + stage * TILE_FLOATS;
        float* Bd = Bs + stage * TILE_FLOATS;
#pragma unroll
        for (int i = 0; i < 4; i++) {
            int idx = tid + i*256;
            int row = idx >> 3;
            int kq  = (idx & 7) * 4;
            cp_async16(smem_u32(Ad + row*ASTR + kq),
                       g_ctx + (size_t)(m0 + row)*DMODEL + k0 + kq);
            cp_async16(smem_u32(Bd + row*ASTR + kq),
                       g_wor + (size_t)(n0 + row)*DMODEL + k0 + kq);
        }
        cp_commit();
    };

    load_stage(0, 0);
    load_stage(1, 1);
    for (int kt = 0; kt < NKT; kt++) {
        if (kt < NKT - 1) cp_wait1(); else cp_wait0();
        __syncthreads();
        int st = kt % NSTAGE;
        gemm_compute_tile(As + st*TILE_FLOATS, Bs + st*TILE_FLOATS,
                          warp_m, warp_n, lane, c);
        if (kt + 2 < NKT) load_stage(kt + 2, (kt + 2) % NSTAGE);
    }

    const int lq = lane >> 2;
    const int lc = (lane & 3) * 2;
#pragma unroll
    for (int mt = 0; mt < 4; mt++) {
#pragma unroll
        for (int rv = 0; rv < 2; rv++) {
            int m = m0 + warp_m + mt*16 + lq + rv*8;
#pragma unroll
            for (int nt = 0; nt < 4; nt++) {
                int nf = n0 + warp_n + nt*8 + lc;
                float v0 = c[mt][nt][rv*2+0] + bo[nf];
                float v1 = c[mt][nt][rv*2+1] + bo[nf+1];
                *(float2*)(out + (size_t)m*DMODEL + nf) = make_float2(v0, v1);
            }
        }
    }
}

// ---------------------------------------------------------------------------
extern "C" void kernel_launch(void* const* d_in, const int* in_sizes, int n_in,
                              void* d_out, int out_size)
{
    const float* x     = (const float*)d_in[0];
    const float* Wqk_w = (const float*)d_in[1];
    const float* Wqk_b = (const float*)d_in[2];
    const float* Wv_w  = (const float*)d_in[3];
    const float* Wv_b  = (const float*)d_in[4];
    const float* Wo_w  = (const float*)d_in[5];
    const float* Wo_b  = (const float*)d_in[6];
    float* out = (float*)d_out;

    cudaFuncSetAttribute(qkv_tc_gemm,
        cudaFuncAttributeMaxDynamicSharedMemorySize, GEMM_SMEM_BYTES);
    cudaFuncSetAttribute(out_tc_gemm,
        cudaFuncAttributeMaxDynamicSharedMemorySize, GEMM_SMEM_BYTES);
    cudaFuncSetAttribute(chunk_out_tc_kernel,
        cudaFuncAttributeMaxDynamicSharedMemorySize, CO_SMEM_BYTES);
    cudaFuncSetAttribute(chunk_state_kernel,
        cudaFuncAttributeMaxDynamicSharedMemorySize, CS2_SMEM_BYTES);

    round_kernel<<<N4_TOT/256, 256>>>((const float4*)x, (const float4*)Wqk_w,
                                      (const float4*)Wv_w, (const float4*)Wo_w);

    dim3 g1(NFEAT/128, NTOK/128);
    qkv_tc_gemm<<<g1, 256, GEMM_SMEM_BYTES>>>(Wqk_b, Wv_b);

    dim3 g2(BHEADS, 2, 2);
    chunk_state_kernel<<<g2, 256, CS2_SMEM_BYTES>>>();

    chunk_out_tc_kernel<<<BHEADS*NCHUNK, 256, CO_SMEM_BYTES>>>();

    dim3 g5(DMODEL/128, NTOK/128);
    out_tc_gemm<<<g5, 256, GEMM_SMEM_BYTES>>>(Wo_b, out);
}

// round 8
// speedup vs baseline: 4.5793x; 1.4107x over previous
#include <cuda_runtime.h>
#include <cuda_fp16.h>
#include <math.h>
#include <stdint.h>

// Problem constants
#define BATCH 2
#define SEQ   2048
#define DMODEL 512
#define NHEAD 8
#define DHEAD 64
#define NTOK  (BATCH*SEQ)          // 4096
#define NQK   1024
#define NFEAT 1536
#define CHUNK 128
#define NCHUNK (SEQ/CHUNK)         // 16
#define BHEADS (BATCH*NHEAD)       // 16

// Scratch (device globals)
__device__ __half g_qh[BHEADS*SEQ*DHEAD];
__device__ __half g_kh[BHEADS*SEQ*DHEAD];
__device__ __half g_vh[BHEADS*SEQ*DHEAD];
__device__ __half g_ctxh[NTOK*DMODEL];
__device__ float  g_kv_pre[BHEADS*NCHUNK*DHEAD*DHEAD];
__device__ float  g_z_pre[BHEADS*NCHUNK*DHEAD];
// fp16 copies of inputs
__device__ __half g_xh[NTOK*DMODEL];
__device__ __half g_wqkh[NQK*DMODEL];
__device__ __half g_wvh[DMODEL*DMODEL];
__device__ __half g_woh[DMODEL*DMODEL];

// ---------------------------------------------------------------------------
// Helpers
// ---------------------------------------------------------------------------
__device__ __forceinline__ uint32_t smem_u32(const void* p) {
    return (uint32_t)__cvta_generic_to_shared(p);
}
__device__ __forceinline__ void cp_async16(uint32_t s, const void* g) {
    asm volatile("cp.async.cg.shared.global [%0], [%1], 16;\n" :: "r"(s), "l"(g));
}
__device__ __forceinline__ void cp_commit() { asm volatile("cp.async.commit_group;\n"); }
__device__ __forceinline__ void cp_wait1()  { asm volatile("cp.async.wait_group 1;\n"); }
__device__ __forceinline__ void cp_wait0()  { asm volatile("cp.async.wait_group 0;\n"); }

__device__ __forceinline__ void mma_f16(float c[4],
    uint32_t a0, uint32_t a1, uint32_t a2, uint32_t a3,
    uint32_t b0, uint32_t b1)
{
    asm volatile(
        "mma.sync.aligned.m16n8k16.row.col.f32.f16.f16.f32 "
        "{%0,%1,%2,%3}, {%4,%5,%6,%7}, {%8,%9}, {%0,%1,%2,%3};"
        : "+f"(c[0]), "+f"(c[1]), "+f"(c[2]), "+f"(c[3])
        : "r"(a0), "r"(a1), "r"(a2), "r"(a3), "r"(b0), "r"(b1));
}
__device__ __forceinline__ void ldsm_x4(uint32_t& r0, uint32_t& r1,
                                        uint32_t& r2, uint32_t& r3, uint32_t addr)
{
    asm volatile("ldmatrix.sync.aligned.m8n8.x4.shared.b16 {%0,%1,%2,%3}, [%4];"
                 : "=r"(r0), "=r"(r1), "=r"(r2), "=r"(r3) : "r"(addr));
}

// ---------------------------------------------------------------------------
// Kernel 0: convert inputs fp32 -> fp16 (rn)
// ---------------------------------------------------------------------------
#define N8_X   (NTOK*DMODEL/8)       // 262144
#define N8_WQK (NQK*DMODEL/8)        // 65536
#define N8_WV  (DMODEL*DMODEL/8)     // 32768
#define N8_WO  (DMODEL*DMODEL/8)
#define N8_TOT (N8_X+N8_WQK+N8_WV+N8_WO)   // 393216

__global__ __launch_bounds__(256) void conv_kernel(
    const float4* __restrict__ x, const float4* __restrict__ wqk,
    const float4* __restrict__ wv, const float4* __restrict__ wo)
{
    int idx = blockIdx.x * 256 + threadIdx.x;
    const float4* src; __half* dst; int off;
    if (idx < N8_X)                    { src = x;   dst = g_xh;   off = idx; }
    else if (idx < N8_X+N8_WQK)        { src = wqk; dst = g_wqkh; off = idx - N8_X; }
    else if (idx < N8_X+N8_WQK+N8_WV)  { src = wv;  dst = g_wvh;  off = idx - N8_X - N8_WQK; }
    else                               { src = wo;  dst = g_woh;  off = idx - N8_X - N8_WQK - N8_WV; }
    float4 a = src[2*off];
    float4 b = src[2*off+1];
    half2 h[4];
    h[0] = __floats2half2_rn(a.x, a.y);
    h[1] = __floats2half2_rn(a.z, a.w);
    h[2] = __floats2half2_rn(b.x, b.y);
    h[3] = __floats2half2_rn(b.z, b.w);
    *(uint4*)(dst + (size_t)off*8) = *(uint4*)h;
}

// ---------------------------------------------------------------------------
// FP16 GEMM core: 128x128 tiles, k-tile 64, 8 warps of 64x32, 3-stage pipe.
// Smem rows: 64 halves data + 8 skew = 72 halves (144 B).
// ---------------------------------------------------------------------------
#define KTH 64
#define NKTH (DMODEL/KTH)            // 8
#define ASTRH 72
#define TILE_HALFS (128*ASTRH)       // 9216
#define TILE_HB (TILE_HALFS*2)       // 18432 bytes
#define NSTAGE 3
#define GEMM_SMEM_BYTES (NSTAGE*2*TILE_HB)   // 110592

__device__ __forceinline__ void gemm_tile_f16(
    const __half* A, const __half* B,
    int warp_m, int warp_n, int lane, float c[4][4][4])
{
    const uint32_t Ab = smem_u32(A);
    const uint32_t Bb = smem_u32(B);
    const int arow = warp_m + (lane & 15);
    const int acol = ((lane >> 4) & 1) * 8;
    const int bg   = lane >> 3;
    const int brow = warp_n + (bg >> 1) * 8 + (lane & 7);
    const int bcol = (bg & 1) * 8;
#pragma unroll
    for (int kk = 0; kk < KTH; kk += 16) {
        uint32_t af[4][4];
        uint32_t bf[4][2];
#pragma unroll
        for (int mt = 0; mt < 4; mt++)
            ldsm_x4(af[mt][0], af[mt][1], af[mt][2], af[mt][3],
                    Ab + (uint32_t)(((arow + mt*16)*ASTRH + kk + acol)*2));
#pragma unroll
        for (int p = 0; p < 2; p++)
            ldsm_x4(bf[2*p][0], bf[2*p][1], bf[2*p+1][0], bf[2*p+1][1],
                    Bb + (uint32_t)(((brow + p*16)*ASTRH + kk + bcol)*2));
#pragma unroll
        for (int mt = 0; mt < 4; mt++)
#pragma unroll
            for (int nt = 0; nt < 4; nt++)
                mma_f16(c[mt][nt], af[mt][0], af[mt][1], af[mt][2], af[mt][3],
                        bf[nt][0], bf[nt][1]);
    }
}

// ---------------------------------------------------------------------------
// Kernel 1: fused QKV GEMM (fp16 HMMA), epilogue bias + elu+1 + head scatter
// ---------------------------------------------------------------------------
__global__ __launch_bounds__(256, 2) void qkv_f16_gemm(
    const float* __restrict__ bqk, const float* __restrict__ bv)
{
    extern __shared__ __half smh[];
    __half* As = smh;
    __half* Bs = smh + NSTAGE*TILE_HALFS;

    const int n0 = blockIdx.x * 128;
    const int m0 = blockIdx.y * 128;
    const int tid = threadIdx.x;
    const int wid = tid >> 5;
    const int lane = tid & 31;
    const int warp_m = (wid & 1) * 64;
    const int warp_n = (wid >> 1) * 32;

    float c[4][4][4];
#pragma unroll
    for (int mt = 0; mt < 4; mt++)
#pragma unroll
        for (int nt = 0; nt < 4; nt++)
#pragma unroll
            for (int i = 0; i < 4; i++) c[mt][nt][i] = 0.f;

    auto load_stage = [&](int kt, int stage) {
        const int k0 = kt * KTH;
        __half* Ad = As + stage * TILE_HALFS;
        __half* Bd = Bs + stage * TILE_HALFS;
#pragma unroll
        for (int it = 0; it < 8; it++) {
            int i = tid + it*256;
            int reg = i >> 10;                  // 0 = A, 1 = B
            int row = (i & 1023) >> 3;
            int seg = (i & 7) * 8;              // halves
            if (reg == 0) {
                cp_async16(smem_u32(Ad + row*ASTRH + seg),
                           g_xh + (size_t)(m0 + row)*DMODEL + k0 + seg);
            } else {
                int n = n0 + row;
                const __half* wrow = (n < NQK) ? (g_wqkh + (size_t)n*DMODEL)
                                               : (g_wvh + (size_t)(n-NQK)*DMODEL);
                cp_async16(smem_u32(Bd + row*ASTRH + seg), wrow + k0 + seg);
            }
        }
        cp_commit();
    };

    load_stage(0, 0);
    load_stage(1, 1);
    for (int kt = 0; kt < NKTH; kt++) {
        if (kt < NKTH - 1) cp_wait1(); else cp_wait0();
        __syncthreads();
        int st = kt % NSTAGE;
        gemm_tile_f16(As + st*TILE_HALFS, Bs + st*TILE_HALFS,
                      warp_m, warp_n, lane, c);
        if (kt + 2 < NKTH) load_stage(kt + 2, (kt + 2) % NSTAGE);
    }

    const int lq = lane >> 2;
    const int lc = (lane & 3) * 2;
#pragma unroll
    for (int mt = 0; mt < 4; mt++) {
#pragma unroll
        for (int rv = 0; rv < 2; rv++) {
            int m = m0 + warp_m + mt*16 + lq + rv*8;
            int bb = m / SEQ;
            int ss = m % SEQ;
#pragma unroll
            for (int nt = 0; nt < 4; nt++) {
                int nf = n0 + warp_n + nt*8 + lc;
                float v0 = c[mt][nt][rv*2+0];
                float v1 = c[mt][nt][rv*2+1];
                if (nf < NQK) {
                    v0 += bqk[nf];   v1 += bqk[nf+1];
                    v0 = (v0 > 0.f) ? (v0 + 1.f) : expf(v0);
                    v1 = (v1 > 0.f) ? (v1 + 1.f) : expf(v1);
                } else {
                    v0 += bv[nf-NQK]; v1 += bv[nf-NQK+1];
                }
                __half* dst;
                if (nf < DMODEL) {
                    int h = nf / DHEAD, d = nf % DHEAD;
                    dst = g_qh + (((size_t)(bb*NHEAD + h))*SEQ + ss)*DHEAD + d;
                } else if (nf < NQK) {
                    int nn = nf - DMODEL;
                    int h = nn / DHEAD, d = nn % DHEAD;
                    dst = g_kh + (((size_t)(bb*NHEAD + h))*SEQ + ss)*DHEAD + d;
                } else {
                    int nn = nf - NQK;
                    int h = nn / DHEAD, d = nn % DHEAD;
                    dst = g_vh + (((size_t)(bb*NHEAD + h))*SEQ + ss)*DHEAD + d;
                }
                *(half2*)dst = __floats2half2_rn(v0, v1);
            }
        }
    }
}

// ---------------------------------------------------------------------------
// Kernel 2: fused chunk state + exclusive prefix (fp16 inputs, fp32 state)
// ---------------------------------------------------------------------------
#define CSK 32
#define CS2_TILE (CHUNK*CSK)               // 4096 halves
#define CS2_SMEM_BYTES (2*2*CS2_TILE*2)    // 32768

__global__ __launch_bounds__(256) void chunk_state_kernel()
{
    extern __shared__ __half smh[];
    __half* ks = smh;                        // [2][128][32]
    __half* vs = smh + 2*CS2_TILE;           // [2][128][32]

    const int bh  = blockIdx.x;
    const int slk = blockIdx.y;
    const int slv = blockIdx.z;
    const int tid = threadIdx.x;
    const int dkl = tid >> 3;                // 0..31
    const int dvq = (tid & 7) * 4;           // 0..28

    const __half* kp = g_kh + (size_t)bh*SEQ*DHEAD + slk*CSK;
    const __half* vp = g_vh + (size_t)bh*SEQ*DHEAD + slv*CSK;

    auto load_stage = [&](int c, int st) {
        const __half* kc = kp + (size_t)c*CHUNK*DHEAD;
        const __half* vc = vp + (size_t)c*CHUNK*DHEAD;
        __half* kd = ks + st*CS2_TILE;
        __half* vd = vs + st*CS2_TILE;
#pragma unroll
        for (int i = 0; i < 4; i++) {
            int idx = tid + i*256;           // 0..1023
            int reg = idx >> 9;              // 0 = k, 1 = v
            int row = (idx & 511) >> 2;
            int seg = (idx & 3) * 8;         // halves
            if (reg == 0)
                cp_async16(smem_u32(kd + row*CSK + seg), kc + (size_t)row*DHEAD + seg);
            else
                cp_async16(smem_u32(vd + row*CSK + seg), vc + (size_t)row*DHEAD + seg);
        }
        cp_commit();
    };

    float acc[4] = {0.f, 0.f, 0.f, 0.f};
    float zacc = 0.f;

    load_stage(0, 0);
    load_stage(1, 1);

    for (int c = 0; c < NCHUNK; c++) {
        float* kvout = g_kv_pre + ((size_t)(bh*NCHUNK + c))*(DHEAD*DHEAD)
                       + (slk*CSK + dkl)*DHEAD + slv*CSK + dvq;
        *(float4*)kvout = make_float4(acc[0], acc[1], acc[2], acc[3]);
        if (slv == 0 && (tid & 7) == 0)
            g_z_pre[(size_t)(bh*NCHUNK + c)*DHEAD + slk*CSK + dkl] = zacc;

        if (c < NCHUNK - 1) cp_wait1(); else cp_wait0();
        __syncthreads();

        const int st = c & 1;
        const __half* kd = ks + st*CS2_TILE;
        const __half* vd = vs + st*CS2_TILE;
#pragma unroll 8
        for (int s = 0; s < CHUNK; s++) {
            float kv = __half2float(kd[s*CSK + dkl]);
            zacc += kv;
            half2 va = *(const half2*)(vd + s*CSK + dvq);
            half2 vb = *(const half2*)(vd + s*CSK + dvq + 2);
            float2 f0 = __half22float2(va);
            float2 f1 = __half22float2(vb);
            acc[0] += kv*f0.x; acc[1] += kv*f0.y;
            acc[2] += kv*f1.x; acc[3] += kv*f1.y;
        }
        __syncthreads();
        if (c + 2 < NCHUNK) load_stage(c + 2, st);
    }
}

// ---------------------------------------------------------------------------
// Kernel 4: fp16 tensor-core chunk readout, warp-independent causal blocks.
// smem (halves): sk[128*72] svt[64*136] skvt[64*72] ss[128*40], then sz[64] f32
// ---------------------------------------------------------------------------
#define SK_STRH  72
#define SVT_STRH 136
#define SKVT_STRH 72
#define SS_STRH  40
#define SK_OFFH   0
#define SVT_OFFH  (SK_OFFH + 128*SK_STRH)        // 9216
#define SKVT_OFFH (SVT_OFFH + 64*SVT_STRH)       // 17920
#define SS_OFFH   (SKVT_OFFH + 64*SKVT_STRH)     // 22528
#define CO_HALFS  (SS_OFFH + 128*SS_STRH)        // 27648
#define CO_SMEM_BYTES (CO_HALFS*2 + 64*4)        // 55552

__global__ __launch_bounds__(256, 2) void chunk_out_f16_kernel()
{
    extern __shared__ __half smh[];
    __half* sk   = smh + SK_OFFH;
    __half* svt  = smh + SVT_OFFH;
    __half* skvt = smh + SKVT_OFFH;
    __half* ss   = smh + SS_OFFH;
    float*  sz   = (float*)(smh + CO_HALFS);

    const int blk = blockIdx.x;
    const int bh = blk / NCHUNK;
    const int c  = blk % NCHUNK;
    const int tid = threadIdx.x;
    const int wid = tid >> 5;
    const int lane = tid & 31;
    const int lq = lane >> 2;
    const int lr = lane & 3;
    const int wm = wid * 16;

    const size_t base = ((size_t)bh*SEQ + (size_t)c*CHUNK)*DHEAD;

    // Q fragments direct from gmem (half2-aligned loads)
    const __half* qp = g_qh + base;
    uint32_t qf[4][4];
#pragma unroll
    for (int s = 0; s < 4; s++) {
        qf[s][0] = *(const uint32_t*)(qp + (wm + lq)*DHEAD     + s*16 + lr*2);
        qf[s][1] = *(const uint32_t*)(qp + (wm + lq + 8)*DHEAD + s*16 + lr*2);
        qf[s][2] = *(const uint32_t*)(qp + (wm + lq)*DHEAD     + s*16 + 8 + lr*2);
        qf[s][3] = *(const uint32_t*)(qp + (wm + lq + 8)*DHEAD + s*16 + 8 + lr*2);
    }

    // K rows into smem (8-half segments)
    {
        const uint4* k4 = (const uint4*)(g_kh + base);
#pragma unroll
        for (int i = 0; i < 4; i++) {
            int idx = tid + i*256;              // 0..1023
            int row = idx >> 3;
            int seg = (idx & 7) * 8;
            *(uint4*)(sk + row*SK_STRH + seg) = k4[idx];
        }
    }
    // V transposed: svt[d][t]
    {
        const __half* vp = g_vh + base;
        int t  = tid >> 1;
        int dh = (tid & 1) * 32;
#pragma unroll
        for (int i = 0; i < 4; i++) {
            uint4 vv = *(const uint4*)(vp + t*DHEAD + dh + i*8);
            __half h[8];
            *(uint4*)h = vv;
#pragma unroll
            for (int j = 0; j < 8; j++)
                svt[(dh + i*8 + j)*SVT_STRH + t] = h[j];
        }
    }
    // kv_pre transposed to half: skvt[n][dk]
    {
        const float* kvp = g_kv_pre + (size_t)blk*(DHEAD*DHEAD);
        int dk = tid >> 1;
        if (dk < 64) {
            int nh = (tid & 1) * 32;
#pragma unroll
            for (int i = 0; i < 8; i++) {
                float4 vv = *(const float4*)(kvp + dk*DHEAD + nh + i*4);
                skvt[(nh + i*4 + 0)*SKVT_STRH + dk] = __float2half_rn(vv.x);
                skvt[(nh + i*4 + 1)*SKVT_STRH + dk] = __float2half_rn(vv.y);
                skvt[(nh + i*4 + 2)*SKVT_STRH + dk] = __float2half_rn(vv.z);
                skvt[(nh + i*4 + 3)*SKVT_STRH + dk] = __float2half_rn(vv.w);
            }
        }
        if (tid < 64) sz[tid] = g_z_pre[(size_t)blk*DHEAD + tid];
    }
    __syncthreads();

    // ldmatrix addressing
    const int ar   = lane & 15;
    const int acol = ((lane >> 4) & 1) * 8;
    const int bg   = lane >> 3;
    const int bnt  = (bg >> 1) * 8 + (lane & 7);
    const int bcol = (bg & 1) * 8;
    const uint32_t skb   = smem_u32(sk);
    const uint32_t svtb  = smem_u32(svt);
    const uint32_t skvtb = smem_u32(skvt);
    const uint32_t ssb   = smem_u32(ss);

    float acc[8][4];
#pragma unroll
    for (int nt = 0; nt < 8; nt++)
#pragma unroll
        for (int i = 0; i < 4; i++) acc[nt][i] = 0.f;

    const int r0 = wm + lq;
    float pnu0 = 0.f, pnu1 = 0.f;

    for (int j = 0; j <= (wm + 15) / 32; j++) {
        const int j32 = j * 32;

        // S block = Q (16 x 64) x K^T (64 x 32)
        float sfrag[4][4];
#pragma unroll
        for (int nt = 0; nt < 4; nt++)
#pragma unroll
            for (int i = 0; i < 4; i++) sfrag[nt][i] = 0.f;
#pragma unroll
        for (int s = 0; s < 4; s++) {
            uint32_t bf[4][2];
#pragma unroll
            for (int p = 0; p < 2; p++)
                ldsm_x4(bf[2*p][0], bf[2*p][1], bf[2*p+1][0], bf[2*p+1][1],
                        skb + (uint32_t)(((j32 + bnt + p*16)*SK_STRH + s*16 + bcol)*2));
#pragma unroll
            for (int nt = 0; nt < 4; nt++)
                mma_f16(sfrag[nt], qf[s][0], qf[s][1], qf[s][2], qf[s][3],
                        bf[nt][0], bf[nt][1]);
        }
        // mask + nu partials + store S to warp-private ss rows (as half)
#pragma unroll
        for (int nt = 0; nt < 4; nt++) {
            int colg = j32 + nt*8 + 2*lr;
            int cl   = nt*8 + 2*lr;
            float v00 = (colg   <= r0)   ? sfrag[nt][0] : 0.f;
            float v01 = (colg+1 <= r0)   ? sfrag[nt][1] : 0.f;
            float v10 = (colg   <= r0+8) ? sfrag[nt][2] : 0.f;
            float v11 = (colg+1 <= r0+8) ? sfrag[nt][3] : 0.f;
            pnu0 += v00 + v01;
            pnu1 += v10 + v11;
            *(half2*)(ss + r0*SS_STRH + cl)     = __floats2half2_rn(v00, v01);
            *(half2*)(ss + (r0+8)*SS_STRH + cl) = __floats2half2_rn(v10, v11);
        }
        __syncwarp();

        // ctx += S block (16x32) x V block (32x64)
#pragma unroll
        for (int s = 0; s < 2; s++) {
            uint32_t a0, a1, a2, a3;
            ldsm_x4(a0, a1, a2, a3,
                    ssb + (uint32_t)(((wm + ar)*SS_STRH + s*16 + acol)*2));
            uint32_t bf[8][2];
#pragma unroll
            for (int p = 0; p < 4; p++)
                ldsm_x4(bf[2*p][0], bf[2*p][1], bf[2*p+1][0], bf[2*p+1][1],
                        svtb + (uint32_t)(((bnt + p*16)*SVT_STRH + j32 + s*16 + bcol)*2));
#pragma unroll
            for (int nt = 0; nt < 8; nt++)
                mma_f16(acc[nt], a0, a1, a2, a3, bf[nt][0], bf[nt][1]);
        }
        __syncwarp();
    }

    // inter-chunk: ctx += Q x KV_pre ; nu += q . z_pre
#pragma unroll
    for (int s = 0; s < 4; s++) {
        uint32_t bf[8][2];
#pragma unroll
        for (int p = 0; p < 4; p++)
            ldsm_x4(bf[2*p][0], bf[2*p][1], bf[2*p+1][0], bf[2*p+1][1],
                    skvtb + (uint32_t)(((bnt + p*16)*SKVT_STRH + s*16 + bcol)*2));
#pragma unroll
        for (int nt = 0; nt < 8; nt++)
            mma_f16(acc[nt], qf[s][0], qf[s][1], qf[s][2], qf[s][3],
                    bf[nt][0], bf[nt][1]);
        float2 q0a = __half22float2(*(half2*)&qf[s][0]);
        float2 q1a = __half22float2(*(half2*)&qf[s][1]);
        float2 q0b = __half22float2(*(half2*)&qf[s][2]);
        float2 q1b = __half22float2(*(half2*)&qf[s][3]);
        float z0 = sz[s*16 + 2*lr],     z1 = sz[s*16 + 2*lr + 1];
        float z2 = sz[s*16 + 8 + 2*lr], z3 = sz[s*16 + 8 + 2*lr + 1];
        pnu0 += q0a.x*z0 + q0a.y*z1 + q0b.x*z2 + q0b.y*z3;
        pnu1 += q1a.x*z0 + q1a.y*z1 + q1b.x*z2 + q1b.y*z3;
    }

    pnu0 += __shfl_xor_sync(0xffffffffu, pnu0, 1);
    pnu0 += __shfl_xor_sync(0xffffffffu, pnu0, 2);
    pnu1 += __shfl_xor_sync(0xffffffffu, pnu1, 1);
    pnu1 += __shfl_xor_sync(0xffffffffu, pnu1, 2);
    float inv0 = 1.f / pnu0;
    float inv1 = 1.f / pnu1;

    const int b = bh / NHEAD, h = bh % NHEAD;
    const int s0 = c*CHUNK + r0;
    __half* out0 = g_ctxh + ((size_t)(b*SEQ + s0))*DMODEL + h*DHEAD;
    __half* out1 = g_ctxh + ((size_t)(b*SEQ + s0 + 8))*DMODEL + h*DHEAD;
#pragma unroll
    for (int nt = 0; nt < 8; nt++) {
        int cl = nt*8 + 2*lr;
        *(half2*)(out0 + cl) = __floats2half2_rn(acc[nt][0]*inv0, acc[nt][1]*inv0);
        *(half2*)(out1 + cl) = __floats2half2_rn(acc[nt][2]*inv1, acc[nt][3]*inv1);
    }
}

// ---------------------------------------------------------------------------
// Kernel 5: output projection (fp16 HMMA), fp32 out + bias
// ---------------------------------------------------------------------------
__global__ __launch_bounds__(256, 2) void out_f16_gemm(
    const float* __restrict__ bo, float* __restrict__ out)
{
    extern __shared__ __half smh[];
    __half* As = smh;
    __half* Bs = smh + NSTAGE*TILE_HALFS;

    const int n0 = blockIdx.x * 128;
    const int m0 = blockIdx.y * 128;
    const int tid = threadIdx.x;
    const int wid = tid >> 5;
    const int lane = tid & 31;
    const int warp_m = (wid & 1) * 64;
    const int warp_n = (wid >> 1) * 32;

    float c[4][4][4];
#pragma unroll
    for (int mt = 0; mt < 4; mt++)
#pragma unroll
        for (int nt = 0; nt < 4; nt++)
#pragma unroll
            for (int i = 0; i < 4; i++) c[mt][nt][i] = 0.f;

    auto load_stage = [&](int kt, int stage) {
        const int k0 = kt * KTH;
        __half* Ad = As + stage * TILE_HALFS;
        __half* Bd = Bs + stage * TILE_HALFS;
#pragma unroll
        for (int it = 0; it < 8; it++) {
            int i = tid + it*256;
            int reg = i >> 10;
            int row = (i & 1023) >> 3;
            int seg = (i & 7) * 8;
            if (reg == 0)
                cp_async16(smem_u32(Ad + row*ASTRH + seg),
                           g_ctxh + (size_t)(m0 + row)*DMODEL + k0 + seg);
            else
                cp_async16(smem_u32(Bd + row*ASTRH + seg),
                           g_woh + (size_t)(n0 + row)*DMODEL + k0 + seg);
        }
        cp_commit();
    };

    load_stage(0, 0);
    load_stage(1, 1);
    for (int kt = 0; kt < NKTH; kt++) {
        if (kt < NKTH - 1) cp_wait1(); else cp_wait0();
        __syncthreads();
        int st = kt % NSTAGE;
        gemm_tile_f16(As + st*TILE_HALFS, Bs + st*TILE_HALFS,
                      warp_m, warp_n, lane, c);
        if (kt + 2 < NKTH) load_stage(kt + 2, (kt + 2) % NSTAGE);
    }

    const int lq = lane >> 2;
    const int lc = (lane & 3) * 2;
#pragma unroll
    for (int mt = 0; mt < 4; mt++) {
#pragma unroll
        for (int rv = 0; rv < 2; rv++) {
            int m = m0 + warp_m + mt*16 + lq + rv*8;
#pragma unroll
            for (int nt = 0; nt < 4; nt++) {
                int nf = n0 + warp_n + nt*8 + lc;
                float v0 = c[mt][nt][rv*2+0] + bo[nf];
                float v1 = c[mt][nt][rv*2+1] + bo[nf+1];
                *(float2*)(out + (size_t)m*DMODEL + nf) = make_float2(v0, v1);
            }
        }
    }
}

// ---------------------------------------------------------------------------
extern "C" void kernel_launch(void* const* d_in, const int* in_sizes, int n_in,
                              void* d_out, int out_size)
{
    const float* x     = (const float*)d_in[0];
    const float* Wqk_w = (const float*)d_in[1];
    const float* Wqk_b = (const float*)d_in[2];
    const float* Wv_w  = (const float*)d_in[3];
    const float* Wv_b  = (const float*)d_in[4];
    const float* Wo_w  = (const float*)d_in[5];
    const float* Wo_b  = (const float*)d_in[6];
    float* out = (float*)d_out;

    cudaFuncSetAttribute(qkv_f16_gemm,
        cudaFuncAttributeMaxDynamicSharedMemorySize, GEMM_SMEM_BYTES);
    cudaFuncSetAttribute(out_f16_gemm,
        cudaFuncAttributeMaxDynamicSharedMemorySize, GEMM_SMEM_BYTES);
    cudaFuncSetAttribute(chunk_out_f16_kernel,
        cudaFuncAttributeMaxDynamicSharedMemorySize, CO_SMEM_BYTES);
    cudaFuncSetAttribute(chunk_state_kernel,
        cudaFuncAttributeMaxDynamicSharedMemorySize, CS2_SMEM_BYTES);

    conv_kernel<<<N8_TOT/256, 256>>>((const float4*)x, (const float4*)Wqk_w,
                                     (const float4*)Wv_w, (const float4*)Wo_w);

    dim3 g1(NFEAT/128, NTOK/128);
    qkv_f16_gemm<<<g1, 256, GEMM_SMEM_BYTES>>>(Wqk_b, Wv_b);

    dim3 g2(BHEADS, 2, 2);
    chunk_state_kernel<<<g2, 256, CS2_SMEM_BYTES>>>();

    chunk_out_f16_kernel<<<BHEADS*NCHUNK, 256, CO_SMEM_BYTES>>>();

    dim3 g5(DMODEL/128, NTOK/128);
    out_f16_gemm<<<g5, 256, GEMM_SMEM_BYTES>>>(Wo_b, out);
}

// round 9
// speedup vs baseline: 5.9451x; 1.2982x over previous
#include <cuda_runtime.h>
#include <cuda_fp16.h>
#include <math.h>
#include <stdint.h>

// Problem constants
#define BATCH 2
#define SEQ   2048
#define DMODEL 512
#define NHEAD 8
#define DHEAD 64
#define NTOK  (BATCH*SEQ)          // 4096
#define NQK   1024
#define NFEAT 1536
#define CHUNK 128
#define NCHUNK (SEQ/CHUNK)         // 16
#define BHEADS (BATCH*NHEAD)       // 16

// Scratch (device globals)
__device__ __half g_qh[BHEADS*SEQ*DHEAD];
__device__ __half g_kh[BHEADS*SEQ*DHEAD];
__device__ __half g_vh[BHEADS*SEQ*DHEAD];
__device__ __half g_ctxh[NTOK*DMODEL];
__device__ __half g_kv_preh[BHEADS*NCHUNK*DHEAD*DHEAD];
__device__ float  g_z_pre[BHEADS*NCHUNK*DHEAD];
// fp16 copies of inputs
__device__ __half g_xh[NTOK*DMODEL];
__device__ __half g_wqkh[NQK*DMODEL];
__device__ __half g_wvh[DMODEL*DMODEL];
__device__ __half g_woh[DMODEL*DMODEL];

// ---------------------------------------------------------------------------
// Helpers
// ---------------------------------------------------------------------------
__device__ __forceinline__ uint32_t smem_u32(const void* p) {
    return (uint32_t)__cvta_generic_to_shared(p);
}
__device__ __forceinline__ void cp_async16(uint32_t s, const void* g) {
    asm volatile("cp.async.cg.shared.global [%0], [%1], 16;\n" :: "r"(s), "l"(g));
}
__device__ __forceinline__ void cp_commit() { asm volatile("cp.async.commit_group;\n"); }
__device__ __forceinline__ void cp_wait1()  { asm volatile("cp.async.wait_group 1;\n"); }
__device__ __forceinline__ void cp_wait0()  { asm volatile("cp.async.wait_group 0;\n"); }

__device__ __forceinline__ void mma_f16(float c[4],
    uint32_t a0, uint32_t a1, uint32_t a2, uint32_t a3,
    uint32_t b0, uint32_t b1)
{
    asm volatile(
        "mma.sync.aligned.m16n8k16.row.col.f32.f16.f16.f32 "
        "{%0,%1,%2,%3}, {%4,%5,%6,%7}, {%8,%9}, {%0,%1,%2,%3};"
        : "+f"(c[0]), "+f"(c[1]), "+f"(c[2]), "+f"(c[3])
        : "r"(a0), "r"(a1), "r"(a2), "r"(a3), "r"(b0), "r"(b1));
}
__device__ __forceinline__ void ldsm_x4(uint32_t& r0, uint32_t& r1,
                                        uint32_t& r2, uint32_t& r3, uint32_t addr)
{
    asm volatile("ldmatrix.sync.aligned.m8n8.x4.shared.b16 {%0,%1,%2,%3}, [%4];"
                 : "=r"(r0), "=r"(r1), "=r"(r2), "=r"(r3) : "r"(addr));
}
__device__ __forceinline__ void ldsm_x4t(uint32_t& r0, uint32_t& r1,
                                         uint32_t& r2, uint32_t& r3, uint32_t addr)
{
    asm volatile("ldmatrix.sync.aligned.m8n8.x4.trans.shared.b16 {%0,%1,%2,%3}, [%4];"
                 : "=r"(r0), "=r"(r1), "=r"(r2), "=r"(r3) : "r"(addr));
}

// ---------------------------------------------------------------------------
// Kernel 0: convert inputs fp32 -> fp16 (rn)
// ---------------------------------------------------------------------------
#define N8_X   (NTOK*DMODEL/8)
#define N8_WQK (NQK*DMODEL/8)
#define N8_WV  (DMODEL*DMODEL/8)
#define N8_WO  (DMODEL*DMODEL/8)
#define N8_TOT (N8_X+N8_WQK+N8_WV+N8_WO)

__global__ __launch_bounds__(256) void conv_kernel(
    const float4* __restrict__ x, const float4* __restrict__ wqk,
    const float4* __restrict__ wv, const float4* __restrict__ wo)
{
    int idx = blockIdx.x * 256 + threadIdx.x;
    const float4* src; __half* dst; int off;
    if (idx < N8_X)                    { src = x;   dst = g_xh;   off = idx; }
    else if (idx < N8_X+N8_WQK)        { src = wqk; dst = g_wqkh; off = idx - N8_X; }
    else if (idx < N8_X+N8_WQK+N8_WV)  { src = wv;  dst = g_wvh;  off = idx - N8_X - N8_WQK; }
    else                               { src = wo;  dst = g_woh;  off = idx - N8_X - N8_WQK - N8_WV; }
    float4 a = src[2*off];
    float4 b = src[2*off+1];
    half2 h[4];
    h[0] = __floats2half2_rn(a.x, a.y);
    h[1] = __floats2half2_rn(a.z, a.w);
    h[2] = __floats2half2_rn(b.x, b.y);
    h[3] = __floats2half2_rn(b.z, b.w);
    *(uint4*)(dst + (size_t)off*8) = *(uint4*)h;
}

// ---------------------------------------------------------------------------
// FP16 GEMM core: 128x128 tiles, k-tile 64, 8 warps of 64x32, 3-stage pipe.
// ---------------------------------------------------------------------------
#define KTH 64
#define NKTH (DMODEL/KTH)            // 8
#define ASTRH 72
#define TILE_HALFS (128*ASTRH)
#define TILE_HB (TILE_HALFS*2)
#define NSTAGE 3
#define GEMM_SMEM_BYTES (NSTAGE*2*TILE_HB)

__device__ __forceinline__ void gemm_tile_f16(
    const __half* A, const __half* B,
    int warp_m, int warp_n, int lane, float c[4][4][4])
{
    const uint32_t Ab = smem_u32(A);
    const uint32_t Bb = smem_u32(B);
    const int arow = warp_m + (lane & 15);
    const int acol = ((lane >> 4) & 1) * 8;
    const int bg   = lane >> 3;
    const int brow = warp_n + (bg >> 1) * 8 + (lane & 7);
    const int bcol = (bg & 1) * 8;
#pragma unroll
    for (int kk = 0; kk < KTH; kk += 16) {
        uint32_t af[4][4];
        uint32_t bf[4][2];
#pragma unroll
        for (int mt = 0; mt < 4; mt++)
            ldsm_x4(af[mt][0], af[mt][1], af[mt][2], af[mt][3],
                    Ab + (uint32_t)(((arow + mt*16)*ASTRH + kk + acol)*2));
#pragma unroll
        for (int p = 0; p < 2; p++)
            ldsm_x4(bf[2*p][0], bf[2*p][1], bf[2*p+1][0], bf[2*p+1][1],
                    Bb + (uint32_t)(((brow + p*16)*ASTRH + kk + bcol)*2));
#pragma unroll
        for (int mt = 0; mt < 4; mt++)
#pragma unroll
            for (int nt = 0; nt < 4; nt++)
                mma_f16(c[mt][nt], af[mt][0], af[mt][1], af[mt][2], af[mt][3],
                        bf[nt][0], bf[nt][1]);
    }
}

// ---------------------------------------------------------------------------
// Kernel 1: fused QKV GEMM (fp16 HMMA), epilogue bias + elu+1 + head scatter
// ---------------------------------------------------------------------------
__global__ __launch_bounds__(256, 2) void qkv_f16_gemm(
    const float* __restrict__ bqk, const float* __restrict__ bv)
{
    extern __shared__ __half smh[];
    __half* As = smh;
    __half* Bs = smh + NSTAGE*TILE_HALFS;

    const int n0 = blockIdx.x * 128;
    const int m0 = blockIdx.y * 128;
    const int tid = threadIdx.x;
    const int wid = tid >> 5;
    const int lane = tid & 31;
    const int warp_m = (wid & 1) * 64;
    const int warp_n = (wid >> 1) * 32;

    float c[4][4][4];
#pragma unroll
    for (int mt = 0; mt < 4; mt++)
#pragma unroll
        for (int nt = 0; nt < 4; nt++)
#pragma unroll
            for (int i = 0; i < 4; i++) c[mt][nt][i] = 0.f;

    auto load_stage = [&](int kt, int stage) {
        const int k0 = kt * KTH;
        __half* Ad = As + stage * TILE_HALFS;
        __half* Bd = Bs + stage * TILE_HALFS;
#pragma unroll
        for (int it = 0; it < 8; it++) {
            int i = tid + it*256;
            int reg = i >> 10;
            int row = (i & 1023) >> 3;
            int seg = (i & 7) * 8;
            if (reg == 0) {
                cp_async16(smem_u32(Ad + row*ASTRH + seg),
                           g_xh + (size_t)(m0 + row)*DMODEL + k0 + seg);
            } else {
                int n = n0 + row;
                const __half* wrow = (n < NQK) ? (g_wqkh + (size_t)n*DMODEL)
                                               : (g_wvh + (size_t)(n-NQK)*DMODEL);
                cp_async16(smem_u32(Bd + row*ASTRH + seg), wrow + k0 + seg);
            }
        }
        cp_commit();
    };

    load_stage(0, 0);
    load_stage(1, 1);
    for (int kt = 0; kt < NKTH; kt++) {
        if (kt < NKTH - 1) cp_wait1(); else cp_wait0();
        __syncthreads();
        int st = kt % NSTAGE;
        gemm_tile_f16(As + st*TILE_HALFS, Bs + st*TILE_HALFS,
                      warp_m, warp_n, lane, c);
        if (kt + 2 < NKTH) load_stage(kt + 2, (kt + 2) % NSTAGE);
    }

    const int lq = lane >> 2;
    const int lc = (lane & 3) * 2;
#pragma unroll
    for (int mt = 0; mt < 4; mt++) {
#pragma unroll
        for (int rv = 0; rv < 2; rv++) {
            int m = m0 + warp_m + mt*16 + lq + rv*8;
            int bb = m / SEQ;
            int ss = m % SEQ;
#pragma unroll
            for (int nt = 0; nt < 4; nt++) {
                int nf = n0 + warp_n + nt*8 + lc;
                float v0 = c[mt][nt][rv*2+0];
                float v1 = c[mt][nt][rv*2+1];
                if (nf < NQK) {
                    v0 += bqk[nf];   v1 += bqk[nf+1];
                    v0 = (v0 > 0.f) ? (v0 + 1.f) : expf(v0);
                    v1 = (v1 > 0.f) ? (v1 + 1.f) : expf(v1);
                } else {
                    v0 += bv[nf-NQK]; v1 += bv[nf-NQK+1];
                }
                __half* dst;
                if (nf < DMODEL) {
                    int h = nf / DHEAD, d = nf % DHEAD;
                    dst = g_qh + (((size_t)(bb*NHEAD + h))*SEQ + ss)*DHEAD + d;
                } else if (nf < NQK) {
                    int nn = nf - DMODEL;
                    int h = nn / DHEAD, d = nn % DHEAD;
                    dst = g_kh + (((size_t)(bb*NHEAD + h))*SEQ + ss)*DHEAD + d;
                } else {
                    int nn = nf - NQK;
                    int h = nn / DHEAD, d = nn % DHEAD;
                    dst = g_vh + (((size_t)(bb*NHEAD + h))*SEQ + ss)*DHEAD + d;
                }
                *(half2*)dst = __floats2half2_rn(v0, v1);
            }
        }
    }
}

// ---------------------------------------------------------------------------
// Kernel 2: chunk state + exclusive prefix via tensor cores.
// grid (BHEADS, 2 dv-slabs). KV state lives in mma accum fragments.
// A = K^T (via ldmatrix.trans), B = V slab (via ldmatrix.trans).
// ---------------------------------------------------------------------------
#define CS_KSTR 72
#define CS_VSTR 40
#define CS_KT (128*CS_KSTR)          // 9216 halves
#define CS_VT (128*CS_VSTR)          // 5120 halves
#define CS_SMEM_BYTES ((2*CS_KT + 2*CS_VT)*2 + 8*64*4)   // 59392

__global__ __launch_bounds__(256) void chunk_state_kernel()
{
    extern __shared__ __half smh[];
    __half* ks = smh;                        // [2][128][72]
    __half* vs = smh + 2*CS_KT;              // [2][128][40]
    float* zred = (float*)(smh + 2*CS_KT + 2*CS_VT);

    const int bh  = blockIdx.x;
    const int slv = blockIdx.y;
    const int tid = threadIdx.x;
    const int wid = tid >> 5;
    const int lane = tid & 31;
    const int d0 = (wid & 3) * 16;           // dk rows of this warp
    const int n0 = (wid >> 2) * 16;          // dv cols within slab
    const int lq = lane >> 2;
    const int lr = lane & 3;

    const __half* kp = g_kh + (size_t)bh*SEQ*DHEAD;
    const __half* vp = g_vh + (size_t)bh*SEQ*DHEAD + slv*32;

    auto load_stage = [&](int c, int st) {
        const __half* kc = kp + (size_t)c*CHUNK*DHEAD;
        const __half* vc = vp + (size_t)c*CHUNK*DHEAD;
        __half* kd = ks + st*CS_KT;
        __half* vd = vs + st*CS_VT;
#pragma unroll
        for (int i = 0; i < 6; i++) {
            int idx = tid + i*256;           // 0..1535
            if (idx < 1024) {
                int row = idx >> 3, seg = (idx & 7) * 8;
                cp_async16(smem_u32(kd + row*CS_KSTR + seg), kc + (size_t)row*DHEAD + seg);
            } else {
                int j = idx - 1024;
                int row = j >> 2, seg = (j & 3) * 8;
                cp_async16(smem_u32(vd + row*CS_VSTR + seg), vc + (size_t)row*DHEAD + seg);
            }
        }
        cp_commit();
    };

    float acc[2][4];
#pragma unroll
    for (int nt = 0; nt < 2; nt++)
#pragma unroll
        for (int i = 0; i < 4; i++) acc[nt][i] = 0.f;
    float zrun = 0.f;

    // trans-ldmatrix per-lane offsets
    const int sA = (lane & 7) + ((lane >> 4) & 1) * 8;   // A: bit4 -> k+8
    const int dA = ((lane >> 3) & 1) * 8;                // A: bit3 -> m+8
    const int sB = (lane & 7) + ((lane >> 3) & 1) * 8;   // B: bit3 -> k+8
    const int nB = ((lane >> 4) & 1) * 8;                // B: bit4 -> n+8

    load_stage(0, 0);
    load_stage(1, 1);

    for (int c = 0; c < NCHUNK; c++) {
        // exclusive-prefix stores (registers; no sync needed)
        {
            __half* kvo = g_kv_preh + ((size_t)(bh*NCHUNK + c))*(DHEAD*DHEAD);
            int col = slv*32 + n0 + 2*lr;
#pragma unroll
            for (int nt = 0; nt < 2; nt++) {
                *(half2*)(kvo + (d0 + lq)*DHEAD + col + nt*8)
                    = __floats2half2_rn(acc[nt][0], acc[nt][1]);
                *(half2*)(kvo + (d0 + lq + 8)*DHEAD + col + nt*8)
                    = __floats2half2_rn(acc[nt][2], acc[nt][3]);
            }
            if (slv == 0 && tid < 64)
                g_z_pre[(size_t)(bh*NCHUNK + c)*DHEAD + tid] = zrun;
        }

        if (c < NCHUNK - 1) cp_wait1(); else cp_wait0();
        __syncthreads();

        const int st = c & 1;
        const uint32_t ksb = smem_u32(ks + st*CS_KT);
        const uint32_t vsb = smem_u32(vs + st*CS_VT);
#pragma unroll
        for (int s0 = 0; s0 < 128; s0 += 16) {
            uint32_t a0, a1, a2, a3, b0, b1, b2, b3;
            ldsm_x4t(a0, a1, a2, a3,
                     ksb + (uint32_t)(((s0 + sA)*CS_KSTR + d0 + dA)*2));
            ldsm_x4t(b0, b1, b2, b3,
                     vsb + (uint32_t)(((s0 + sB)*CS_VSTR + n0 + nB)*2));
            mma_f16(acc[0], a0, a1, a2, a3, b0, b1);
            mma_f16(acc[1], a0, a1, a2, a3, b2, b3);
        }
        // z partial sums (only slv==0 blocks)
        if (slv == 0) {
            int dk2 = (tid & 31) * 2;
            int sg  = tid >> 5;
            const __half* kst = ks + st*CS_KT;
            float z0 = 0.f, z1 = 0.f;
#pragma unroll
            for (int i = 0; i < 16; i++) {
                float2 f = __half22float2(*(const half2*)(kst + (sg*16 + i)*CS_KSTR + dk2));
                z0 += f.x; z1 += f.y;
            }
            zred[sg*64 + dk2]     = z0;
            zred[sg*64 + dk2 + 1] = z1;
        }
        __syncthreads();
        if (slv == 0 && tid < 64) {
            float s = 0.f;
#pragma unroll
            for (int j = 0; j < 8; j++) s += zred[j*64 + tid];
            zrun += s;
        }
        if (c + 2 < NCHUNK) load_stage(c + 2, st);
    }
}

// ---------------------------------------------------------------------------
// Kernel 4: fp16 chunk readout; B operands via ldmatrix.trans (no transpose
// staging). smem (halves): sk[128*72] sv[128*72] skv[64*72] ss[128*40] +sz f32
// ---------------------------------------------------------------------------
#define SK_STRH  72
#define SV_STRH  72
#define SKV_STRH 72
#define SS_STRH  40
#define SK_OFFH  0
#define SV_OFFH  (SK_OFFH + 128*SK_STRH)        // 9216
#define SKV_OFFH (SV_OFFH + 128*SV_STRH)        // 18432
#define SS_OFFH  (SKV_OFFH + 64*SKV_STRH)       // 23040
#define CO_HALFS (SS_OFFH + 128*SS_STRH)        // 28160
#define CO_SMEM_BYTES (CO_HALFS*2 + 64*4)       // 56576

__global__ __launch_bounds__(256, 2) void chunk_out_f16_kernel()
{
    extern __shared__ __half smh[];
    __half* sk  = smh + SK_OFFH;
    __half* sv  = smh + SV_OFFH;
    __half* skv = smh + SKV_OFFH;
    __half* ss  = smh + SS_OFFH;
    float*  sz  = (float*)(smh + CO_HALFS);

    const int blk = blockIdx.x;
    const int bh = blk / NCHUNK;
    const int c  = blk % NCHUNK;
    const int tid = threadIdx.x;
    const int wid = tid >> 5;
    const int lane = tid & 31;
    const int lq = lane >> 2;
    const int lr = lane & 3;
    const int wm = wid * 16;

    const size_t base = ((size_t)bh*SEQ + (size_t)c*CHUNK)*DHEAD;

    // Q fragments direct from gmem
    const __half* qp = g_qh + base;
    uint32_t qf[4][4];
#pragma unroll
    for (int s = 0; s < 4; s++) {
        qf[s][0] = *(const uint32_t*)(qp + (wm + lq)*DHEAD     + s*16 + lr*2);
        qf[s][1] = *(const uint32_t*)(qp + (wm + lq + 8)*DHEAD + s*16 + lr*2);
        qf[s][2] = *(const uint32_t*)(qp + (wm + lq)*DHEAD     + s*16 + 8 + lr*2);
        qf[s][3] = *(const uint32_t*)(qp + (wm + lq + 8)*DHEAD + s*16 + 8 + lr*2);
    }

    // K and V rows into smem (plain row-major, 16B segments)
    {
        const uint4* k4 = (const uint4*)(g_kh + base);
        const uint4* v4 = (const uint4*)(g_vh + base);
#pragma unroll
        for (int i = 0; i < 8; i++) {
            int idx = tid + i*256;              // 0..2047
            int reg = idx >> 10;
            int row = (idx & 1023) >> 3;
            int seg = (idx & 7) * 8;
            if (reg == 0) *(uint4*)(sk + row*SK_STRH + seg) = k4[(idx & 1023)];
            else          *(uint4*)(sv + row*SV_STRH + seg) = v4[(idx & 1023)];
        }
    }
    // kv_pre (fp16) rows into smem
    {
        const uint4* kv4 = (const uint4*)(g_kv_preh + (size_t)blk*(DHEAD*DHEAD));
#pragma unroll
        for (int i = 0; i < 2; i++) {
            int idx = tid + i*256;              // 0..511
            int row = idx >> 3;
            int seg = (idx & 7) * 8;
            *(uint4*)(skv + row*SKV_STRH + seg) = kv4[idx];
        }
        if (tid < 64) sz[tid] = g_z_pre[(size_t)blk*DHEAD + tid];
    }
    __syncthreads();

    // normal ldmatrix addressing (A from ss, B from sk)
    const int ar   = lane & 15;
    const int acol = ((lane >> 4) & 1) * 8;
    const int bg   = lane >> 3;
    const int bnt  = (bg >> 1) * 8 + (lane & 7);
    const int bcol = (bg & 1) * 8;
    // trans ldmatrix addressing (B from sv / skv)
    const int sB = (lane & 7) + ((lane >> 3) & 1) * 8;
    const int nB = ((lane >> 4) & 1) * 8;

    const uint32_t skb  = smem_u32(sk);
    const uint32_t svb  = smem_u32(sv);
    const uint32_t skvb = smem_u32(skv);
    const uint32_t ssb  = smem_u32(ss);

    float acc[8][4];
#pragma unroll
    for (int nt = 0; nt < 8; nt++)
#pragma unroll
        for (int i = 0; i < 4; i++) acc[nt][i] = 0.f;

    const int r0 = wm + lq;
    float pnu0 = 0.f, pnu1 = 0.f;

    for (int j = 0; j <= (wm + 15) / 32; j++) {
        const int j32 = j * 32;

        // S block = Q (16x64) x K^T (64x32)  [B normal: sk rows are keys]
        float sfrag[4][4];
#pragma unroll
        for (int nt = 0; nt < 4; nt++)
#pragma unroll
            for (int i = 0; i < 4; i++) sfrag[nt][i] = 0.f;
#pragma unroll
        for (int s = 0; s < 4; s++) {
            uint32_t bf[4][2];
#pragma unroll
            for (int p = 0; p < 2; p++)
                ldsm_x4(bf[2*p][0], bf[2*p][1], bf[2*p+1][0], bf[2*p+1][1],
                        skb + (uint32_t)(((j32 + bnt + p*16)*SK_STRH + s*16 + bcol)*2));
#pragma unroll
            for (int nt = 0; nt < 4; nt++)
                mma_f16(sfrag[nt], qf[s][0], qf[s][1], qf[s][2], qf[s][3],
                        bf[nt][0], bf[nt][1]);
        }
        // mask + nu partials + store S (half) to warp-private ss rows
#pragma unroll
        for (int nt = 0; nt < 4; nt++) {
            int colg = j32 + nt*8 + 2*lr;
            int cl   = nt*8 + 2*lr;
            float v00 = (colg   <= r0)   ? sfrag[nt][0] : 0.f;
            float v01 = (colg+1 <= r0)   ? sfrag[nt][1] : 0.f;
            float v10 = (colg   <= r0+8) ? sfrag[nt][2] : 0.f;
            float v11 = (colg+1 <= r0+8) ? sfrag[nt][3] : 0.f;
            pnu0 += v00 + v01;
            pnu1 += v10 + v11;
            *(half2*)(ss + r0*SS_STRH + cl)     = __floats2half2_rn(v00, v01);
            *(half2*)(ss + (r0+8)*SS_STRH + cl) = __floats2half2_rn(v10, v11);
        }
        __syncwarp();

        // ctx += S (16x32) x V (32x64)  [B via trans from row-major sv]
#pragma unroll
        for (int s = 0; s < 2; s++) {
            const int k0 = j32 + s*16;
            uint32_t a0, a1, a2, a3;
            ldsm_x4(a0, a1, a2, a3,
                    ssb + (uint32_t)(((wm + ar)*SS_STRH + s*16 + acol)*2));
            uint32_t bf[8][2];
#pragma unroll
            for (int nn = 0; nn < 4; nn++)
                ldsm_x4t(bf[2*nn][0], bf[2*nn][1], bf[2*nn+1][0], bf[2*nn+1][1],
                         svb + (uint32_t)(((k0 + sB)*SV_STRH + nn*16 + nB)*2));
#pragma unroll
            for (int nt = 0; nt < 8; nt++)
                mma_f16(acc[nt], a0, a1, a2, a3, bf[nt][0], bf[nt][1]);
        }
        __syncwarp();
    }

    // inter-chunk: ctx += Q x KV_pre  [B via trans from row-major skv]; nu += q.z
#pragma unroll
    for (int s = 0; s < 4; s++) {
        const int k0 = s*16;
        uint32_t bf[8][2];
#pragma unroll
        for (int nn = 0; nn < 4; nn++)
            ldsm_x4t(bf[2*nn][0], bf[2*nn][1], bf[2*nn+1][0], bf[2*nn+1][1],
                     skvb + (uint32_t)(((k0 + sB)*SKV_STRH + nn*16 + nB)*2));
#pragma unroll
        for (int nt = 0; nt < 8; nt++)
            mma_f16(acc[nt], qf[s][0], qf[s][1], qf[s][2], qf[s][3],
                    bf[nt][0], bf[nt][1]);
        float2 q0a = __half22float2(*(half2*)&qf[s][0]);
        float2 q1a = __half22float2(*(half2*)&qf[s][1]);
        float2 q0b = __half22float2(*(half2*)&qf[s][2]);
        float2 q1b = __half22float2(*(half2*)&qf[s][3]);
        float z0 = sz[s*16 + 2*lr],     z1 = sz[s*16 + 2*lr + 1];
        float z2 = sz[s*16 + 8 + 2*lr], z3 = sz[s*16 + 8 + 2*lr + 1];
        pnu0 += q0a.x*z0 + q0a.y*z1 + q0b.x*z2 + q0b.y*z3;
        pnu1 += q1a.x*z0 + q1a.y*z1 + q1b.x*z2 + q1b.y*z3;
    }

    pnu0 += __shfl_xor_sync(0xffffffffu, pnu0, 1);
    pnu0 += __shfl_xor_sync(0xffffffffu, pnu0, 2);
    pnu1 += __shfl_xor_sync(0xffffffffu, pnu1, 1);
    pnu1 += __shfl_xor_sync(0xffffffffu, pnu1, 2);
    float inv0 = 1.f / pnu0;
    float inv1 = 1.f / pnu1;

    const int b = bh / NHEAD, h = bh % NHEAD;
    const int s0 = c*CHUNK + r0;
    __half* out0 = g_ctxh + ((size_t)(b*SEQ + s0))*DMODEL + h*DHEAD;
    __half* out1 = g_ctxh + ((size_t)(b*SEQ + s0 + 8))*DMODEL + h*DHEAD;
#pragma unroll
    for (int nt = 0; nt < 8; nt++) {
        int cl = nt*8 + 2*lr;
        *(half2*)(out0 + cl) = __floats2half2_rn(acc[nt][0]*inv0, acc[nt][1]*inv0);
        *(half2*)(out1 + cl) = __floats2half2_rn(acc[nt][2]*inv1, acc[nt][3]*inv1);
    }
}

// ---------------------------------------------------------------------------
// Kernel 5: output projection (fp16 HMMA), fp32 out + bias
// ---------------------------------------------------------------------------
__global__ __launch_bounds__(256, 2) void out_f16_gemm(
    const float* __restrict__ bo, float* __restrict__ out)
{
    extern __shared__ __half smh[];
    __half* As = smh;
    __half* Bs = smh + NSTAGE*TILE_HALFS;

    const int n0 = blockIdx.x * 128;
    const int m0 = blockIdx.y * 128;
    const int tid = threadIdx.x;
    const int wid = tid >> 5;
    const int lane = tid & 31;
    const int warp_m = (wid & 1) * 64;
    const int warp_n = (wid >> 1) * 32;

    float c[4][4][4];
#pragma unroll
    for (int mt = 0; mt < 4; mt++)
#pragma unroll
        for (int nt = 0; nt < 4; nt++)
#pragma unroll
            for (int i = 0; i < 4; i++) c[mt][nt][i] = 0.f;

    auto load_stage = [&](int kt, int stage) {
        const int k0 = kt * KTH;
        __half* Ad = As + stage * TILE_HALFS;
        __half* Bd = Bs + stage * TILE_HALFS;
#pragma unroll
        for (int it = 0; it < 8; it++) {
            int i = tid + it*256;
            int reg = i >> 10;
            int row = (i & 1023) >> 3;
            int seg = (i & 7) * 8;
            if (reg == 0)
                cp_async16(smem_u32(Ad + row*ASTRH + seg),
                           g_ctxh + (size_t)(m0 + row)*DMODEL + k0 + seg);
            else
                cp_async16(smem_u32(Bd + row*ASTRH + seg),
                           g_woh + (size_t)(n0 + row)*DMODEL + k0 + seg);
        }
        cp_commit();
    };

    load_stage(0, 0);
    load_stage(1, 1);
    for (int kt = 0; kt < NKTH; kt++) {
        if (kt < NKTH - 1) cp_wait1(); else cp_wait0();
        __syncthreads();
        int st = kt % NSTAGE;
        gemm_tile_f16(As + st*TILE_HALFS, Bs + st*TILE_HALFS,
                      warp_m, warp_n, lane, c);
        if (kt + 2 < NKTH) load_stage(kt + 2, (kt + 2) % NSTAGE);
    }

    const int lq = lane >> 2;
    const int lc = (lane & 3) * 2;
#pragma unroll
    for (int mt = 0; mt < 4; mt++) {
#pragma unroll
        for (int rv = 0; rv < 2; rv++) {
            int m = m0 + warp_m + mt*16 + lq + rv*8;
#pragma unroll
            for (int nt = 0; nt < 4; nt++) {
                int nf = n0 + warp_n + nt*8 + lc;
                float v0 = c[mt][nt][rv*2+0] + bo[nf];
                float v1 = c[mt][nt][rv*2+1] + bo[nf+1];
                *(float2*)(out + (size_t)m*DMODEL + nf) = make_float2(v0, v1);
            }
        }
    }
}

// ---------------------------------------------------------------------------
extern "C" void kernel_launch(void* const* d_in, const int* in_sizes, int n_in,
                              void* d_out, int out_size)
{
    const float* x     = (const float*)d_in[0];
    const float* Wqk_w = (const float*)d_in[1];
    const float* Wqk_b = (const float*)d_in[2];
    const float* Wv_w  = (const float*)d_in[3];
    const float* Wv_b  = (const float*)d_in[4];
    const float* Wo_w  = (const float*)d_in[5];
    const float* Wo_b  = (const float*)d_in[6];
    float* out = (float*)d_out;

    cudaFuncSetAttribute(qkv_f16_gemm,
        cudaFuncAttributeMaxDynamicSharedMemorySize, GEMM_SMEM_BYTES);
    cudaFuncSetAttribute(out_f16_gemm,
        cudaFuncAttributeMaxDynamicSharedMemorySize, GEMM_SMEM_BYTES);
    cudaFuncSetAttribute(chunk_out_f16_kernel,
        cudaFuncAttributeMaxDynamicSharedMemorySize, CO_SMEM_BYTES);
    cudaFuncSetAttribute(chunk_state_kernel,
        cudaFuncAttributeMaxDynamicSharedMemorySize, CS_SMEM_BYTES);

    conv_kernel<<<N8_TOT/256, 256>>>((const float4*)x, (const float4*)Wqk_w,
                                     (const float4*)Wv_w, (const float4*)Wo_w);

    dim3 g1(NFEAT/128, NTOK/128);
    qkv_f16_gemm<<<g1, 256, GEMM_SMEM_BYTES>>>(Wqk_b, Wv_b);

    dim3 g2(BHEADS, 2);
    chunk_state_kernel<<<g2, 256, CS_SMEM_BYTES>>>();

    chunk_out_f16_kernel<<<BHEADS*NCHUNK, 256, CO_SMEM_BYTES>>>();

    dim3 g5(DMODEL/128, NTOK/128);
    out_f16_gemm<<<g5, 256, GEMM_SMEM_BYTES>>>(Wo_b, out);
}